// round 1
// baseline (speedup 1.0000x reference)
#include <cuda_runtime.h>
#include <cuda_bf16.h>
#include <math.h>

// ---------------- Problem constants ----------------
#define S    2048
#define D    1024
#define NH   16
#define HD   64
#define HFF  2816
#define NV   32000
#define NL   4

// ---------------- Device scratch (no allocations allowed) ----------------
__device__ float g_h[S * D];
__device__ float g_x[S * D];
__device__ float g_q[S * D];
__device__ float g_k[S * D];
__device__ float g_v[S * D];
__device__ float g_o[S * D];
__device__ float g_g[S * HFF];
__device__ float g_u[S * HFF];
__device__ float g_cos[S * (HD / 2)];
__device__ float g_sin[S * (HD / 2)];
__device__ float g_xf[D];

// ---------------- RoPE table ----------------
__global__ void rope_table_kernel(float* ct, float* st) {
    int idx = blockIdx.x * 256 + threadIdx.x;       // S * 32
    if (idx >= S * 32) return;
    int pos = idx >> 5;
    int i = idx & 31;
    float inv = powf(10000.0f, -((float)(2 * i) / (float)HD));
    float ang = (float)pos * inv;
    float s, c;
    sincosf(ang, &s, &c);
    ct[idx] = c;
    st[idx] = s;
}

// ---------------- Embedding gather ----------------
__global__ void embed_kernel(const int* __restrict__ tokens,
                             const float* __restrict__ emb,
                             float* __restrict__ h) {
    int idx = blockIdx.x * 256 + threadIdx.x;       // S * D
    int s = idx >> 10;
    int d = idx & 1023;
    h[idx] = emb[(size_t)tokens[s] * D + d];
}

// ---------------- RMSNorm (one block per row, D=1024) ----------------
__global__ void rmsnorm_kernel(const float* __restrict__ in,
                               const float* __restrict__ w,
                               float* __restrict__ out) {
    const float* r = in + (size_t)blockIdx.x * D;
    float* o = out + (size_t)blockIdx.x * D;
    int t = threadIdx.x;
    float v[4];
    float ss = 0.f;
#pragma unroll
    for (int i = 0; i < 4; i++) { v[i] = r[t + i * 256]; ss += v[i] * v[i]; }
#pragma unroll
    for (int off = 16; off; off >>= 1) ss += __shfl_xor_sync(0xffffffffu, ss, off);
    __shared__ float red[8];
    if ((t & 31) == 0) red[t >> 5] = ss;
    __syncthreads();
    if (t < 8) {
        float x = red[t];
#pragma unroll
        for (int off = 4; off; off >>= 1) x += __shfl_xor_sync(0xffu, x, off);
        if (t == 0) red[0] = x;
    }
    __syncthreads();
    float scale = rsqrtf(red[0] * (1.0f / (float)D) + 1e-6f);
#pragma unroll
    for (int i = 0; i < 4; i++) o[t + i * 256] = v[i] * scale * w[t + i * 256];
}

// ---------------- RoPE apply (in place on q or k) ----------------
__global__ void rope_kernel(float* __restrict__ x,
                            const float* __restrict__ ct,
                            const float* __restrict__ st) {
    int idx = blockIdx.x * 256 + threadIdx.x;       // S * NH * 32
    if (idx >= S * NH * 32) return;
    int pos = idx >> 9;             // / (NH*32)
    int rem = idx & 511;
    int h = rem >> 5;
    int i = rem & 31;
    int base = pos * D + h * HD + 2 * i;
    float c = ct[pos * 32 + i];
    float s = st[pos * 32 + i];
    float x0 = x[base], x1 = x[base + 1];
    x[base]     = x0 * c - x1 * s;
    x[base + 1] = x0 * s + x1 * c;
}

// ---------------- SGEMM: C[M,N] = A[M,K] @ B[K,N] (+ RES) ----------------
// BM=128, BN=64, BK=16, 256 threads, 8x4 per thread.
#define BM 128
#define BN 64
#define BK 16
__global__ __launch_bounds__(256) void sgemm_kernel(
    const float* __restrict__ A, const float* __restrict__ B,
    const float* __restrict__ RES, float* __restrict__ C,
    int M, int N, int K) {
    __shared__ float As[BK][BM + 4];
    __shared__ float Bs[BK][BN];
    const int tid = threadIdx.x;
    const int bm = blockIdx.y * BM;
    const int bn = blockIdx.x * BN;
    const int tx = tid & 15;         // 0..15  -> cols tx*4
    const int ty = tid >> 4;         // 0..15  -> rows ty*8
    const int arow = tid >> 2;       // 0..63
    const int ac4 = (tid & 3) * 4;   // 0,4,8,12
    const int brow = tid >> 4;       // 0..15
    const int bc4 = (tid & 15) * 4;  // 0..60

    float acc[8][4];
#pragma unroll
    for (int i = 0; i < 8; i++)
#pragma unroll
        for (int j = 0; j < 4; j++) acc[i][j] = 0.f;

    for (int k0 = 0; k0 < K; k0 += BK) {
#pragma unroll
        for (int p = 0; p < 2; p++) {
            int r = arow + p * 64;
            float4 v = *(const float4*)(A + (size_t)(bm + r) * K + k0 + ac4);
            As[ac4 + 0][r] = v.x;
            As[ac4 + 1][r] = v.y;
            As[ac4 + 2][r] = v.z;
            As[ac4 + 3][r] = v.w;
        }
        *(float4*)(&Bs[brow][bc4]) =
            *(const float4*)(B + (size_t)(k0 + brow) * N + bn + bc4);
        __syncthreads();
#pragma unroll
        for (int k = 0; k < BK; k++) {
            float4 a0 = *(const float4*)(&As[k][ty * 8]);
            float4 a1 = *(const float4*)(&As[k][ty * 8 + 4]);
            float4 b  = *(const float4*)(&Bs[k][tx * 4]);
            float a[8] = {a0.x, a0.y, a0.z, a0.w, a1.x, a1.y, a1.z, a1.w};
            float bb[4] = {b.x, b.y, b.z, b.w};
#pragma unroll
            for (int i = 0; i < 8; i++)
#pragma unroll
                for (int j = 0; j < 4; j++) acc[i][j] += a[i] * bb[j];
        }
        __syncthreads();
    }
#pragma unroll
    for (int i = 0; i < 8; i++) {
        int row = bm + ty * 8 + i;
        float4 r = make_float4(acc[i][0], acc[i][1], acc[i][2], acc[i][3]);
        if (RES) {
            float4 rv = *(const float4*)(RES + (size_t)row * N + bn + tx * 4);
            r.x += rv.x; r.y += rv.y; r.z += rv.z; r.w += rv.w;
        }
        *(float4*)(C + (size_t)row * N + bn + tx * 4) = r;
    }
}

// ---------------- Flash attention (fp32), 64q x 64k tiles ----------------
// grid (S/64, NH), 128 threads: 2 threads per query row (32-dim halves).
__global__ void attn_kernel(const float* __restrict__ Q,
                            const float* __restrict__ K,
                            const float* __restrict__ V,
                            float* __restrict__ O) {
    const int qt = blockIdx.x;
    const int head = blockIdx.y;
    const int tid = threadIdx.x;
    const int r = tid >> 1;
    const int half = tid & 1;
    const int lane = tid & 31;
    const int qRow = qt * 64 + r;

    __shared__ float4 Ks[64][17];
    __shared__ float4 Vs[64][17];

    float4 q[16];
    const float4* qp = (const float4*)(Q + (size_t)qRow * D + head * HD);
#pragma unroll
    for (int i = 0; i < 16; i++) q[i] = qp[i];

    float4 o[8];
#pragma unroll
    for (int i = 0; i < 8; i++) o[i] = make_float4(0.f, 0.f, 0.f, 0.f);
    float m = -1e30f, l = 0.f;
    const float scale = 0.125f;   // 1/sqrt(64)

    for (int kt = 0; kt <= qt; kt++) {
        {
            const int j = tid >> 1;
            const float4* kp = (const float4*)(K + (size_t)(kt * 64 + j) * D + head * HD) + half * 8;
            const float4* vp = (const float4*)(V + (size_t)(kt * 64 + j) * D + head * HD) + half * 8;
#pragma unroll
            for (int c = 0; c < 8; c++) {
                Ks[j][half * 8 + c] = kp[c];
                Vs[j][half * 8 + c] = vp[c];
            }
        }
        __syncthreads();

        float s[32];
        const bool diag = (kt == qt);
#pragma unroll
        for (int jj = 0; jj < 32; jj++) {
            int j = half * 32 + jj;
            float acc = 0.f;
#pragma unroll
            for (int d = 0; d < 16; d++) {
                float4 kv = Ks[j][d];
                acc += q[d].x * kv.x + q[d].y * kv.y + q[d].z * kv.z + q[d].w * kv.w;
            }
            acc *= scale;
            if (diag && (kt * 64 + j) > qRow) acc = -1e30f;
            s[jj] = acc;
        }
        float tm = s[0];
#pragma unroll
        for (int jj = 1; jj < 32; jj++) tm = fmaxf(tm, s[jj]);
        tm = fmaxf(tm, __shfl_xor_sync(0xffffffffu, tm, 1));
        float mnew = fmaxf(m, tm);
        float corr = __expf(m - mnew);
        float ls = 0.f;
#pragma unroll
        for (int jj = 0; jj < 32; jj++) {
            s[jj] = __expf(s[jj] - mnew);
            ls += s[jj];
        }
        ls += __shfl_xor_sync(0xffffffffu, ls, 1);
        l = l * corr + ls;
        m = mnew;
#pragma unroll
        for (int i = 0; i < 8; i++) {
            o[i].x *= corr; o[i].y *= corr; o[i].z *= corr; o[i].w *= corr;
        }
#pragma unroll
        for (int k = 0; k < 64; k++) {
            float pk = __shfl_sync(0xffffffffu, s[k & 31], (lane & ~1) | (k >> 5));
#pragma unroll
            for (int d = 0; d < 8; d++) {
                float4 vv = Vs[k][half * 8 + d];
                o[d].x += pk * vv.x; o[d].y += pk * vv.y;
                o[d].z += pk * vv.z; o[d].w += pk * vv.w;
            }
        }
        __syncthreads();
    }
    float inv = 1.f / l;
    float4* op = (float4*)(O + (size_t)qRow * D + head * HD) + half * 8;
#pragma unroll
    for (int d = 0; d < 8; d++) {
        o[d].x *= inv; o[d].y *= inv; o[d].z *= inv; o[d].w *= inv;
        op[d] = o[d];
    }
}

// ---------------- SwiGLU elementwise: g = silu(g) * u ----------------
__global__ void swiglu_kernel(float* __restrict__ g, const float* __restrict__ u, int n) {
    int idx = blockIdx.x * 256 + threadIdx.x;
    if (idx >= n) return;
    float z = g[idx];
    float sig = 1.0f / (1.0f + __expf(-z));
    g[idx] = z * sig * u[idx];
}

// ---------------- Logits: out[v] = dot(xf, Wout[:,v]) ----------------
__global__ void logits_kernel(const float* __restrict__ xf,
                              const float* __restrict__ Wout,
                              float* __restrict__ out) {
    __shared__ float xs[D];
    for (int i = threadIdx.x; i < D; i += 256) xs[i] = xf[i];
    __syncthreads();
    int v = blockIdx.x * 256 + threadIdx.x;
    float acc = 0.f;
#pragma unroll 8
    for (int d = 0; d < D; d++) acc += xs[d] * Wout[(size_t)d * NV + v];
    out[v] = acc;
}

// ---------------- Host launch ----------------
extern "C" void kernel_launch(void* const* d_in, const int* in_sizes, int n_in,
                              void* d_out, int out_size) {
    // Input order: tokens, [num_heads], tok_emb, Wq, Wk, Wv, Wo, W1, W2, W3,
    //              attn_norm_w, ffn_norm_w, final_norm_w, Wout
    int bi = 1;
    if (n_in >= 2 && in_sizes[1] == 1) bi = 2;   // scalar num_heads present
    const int*   tokens  = (const int*)d_in[0];
    const float* tok_emb = (const float*)d_in[bi + 0];
    const float* Wq      = (const float*)d_in[bi + 1];
    const float* Wk      = (const float*)d_in[bi + 2];
    const float* Wv      = (const float*)d_in[bi + 3];
    const float* Wo      = (const float*)d_in[bi + 4];
    const float* W1      = (const float*)d_in[bi + 5];
    const float* W2      = (const float*)d_in[bi + 6];
    const float* W3      = (const float*)d_in[bi + 7];
    const float* anw     = (const float*)d_in[bi + 8];
    const float* fnw     = (const float*)d_in[bi + 9];
    const float* finw    = (const float*)d_in[bi + 10];
    const float* Wout    = (const float*)d_in[bi + 11];
    float* out = (float*)d_out;

    float *h_, *x_, *q_, *k_, *v_, *o_, *gg_, *uu_, *cos_, *sin_, *xf_;
    cudaGetSymbolAddress((void**)&h_,  g_h);
    cudaGetSymbolAddress((void**)&x_,  g_x);
    cudaGetSymbolAddress((void**)&q_,  g_q);
    cudaGetSymbolAddress((void**)&k_,  g_k);
    cudaGetSymbolAddress((void**)&v_,  g_v);
    cudaGetSymbolAddress((void**)&o_,  g_o);
    cudaGetSymbolAddress((void**)&gg_, g_g);
    cudaGetSymbolAddress((void**)&uu_, g_u);
    cudaGetSymbolAddress((void**)&cos_, g_cos);
    cudaGetSymbolAddress((void**)&sin_, g_sin);
    cudaGetSymbolAddress((void**)&xf_, g_xf);

    rope_table_kernel<<<(S * 32 + 255) / 256, 256>>>(cos_, sin_);
    embed_kernel<<<(S * D) / 256, 256>>>(tokens, tok_emb, h_);

    const dim3 gDD(D / BN, S / BM);       // (16, 16)  for N=1024 GEMMs
    const dim3 gDF(HFF / BN, S / BM);     // (44, 16)  for N=2816 GEMMs

    for (int l = 0; l < NL; l++) {
        const float* wq = Wq + (size_t)l * D * D;
        const float* wk = Wk + (size_t)l * D * D;
        const float* wv = Wv + (size_t)l * D * D;
        const float* wo = Wo + (size_t)l * D * D;
        const float* w1 = W1 + (size_t)l * D * HFF;
        const float* w2 = W2 + (size_t)l * HFF * D;
        const float* w3 = W3 + (size_t)l * D * HFF;

        rmsnorm_kernel<<<S, 256>>>(h_, anw + (size_t)l * D, x_);

        sgemm_kernel<<<gDD, 256>>>(x_, wq, nullptr, q_, S, D, D);
        sgemm_kernel<<<gDD, 256>>>(x_, wk, nullptr, k_, S, D, D);
        sgemm_kernel<<<gDD, 256>>>(x_, wv, nullptr, v_, S, D, D);

        rope_kernel<<<(S * NH * 32 + 255) / 256, 256>>>(q_, cos_, sin_);
        rope_kernel<<<(S * NH * 32 + 255) / 256, 256>>>(k_, cos_, sin_);

        attn_kernel<<<dim3(S / 64, NH), 128>>>(q_, k_, v_, o_);

        sgemm_kernel<<<gDD, 256>>>(o_, wo, h_, h_, S, D, D);   // residual add

        rmsnorm_kernel<<<S, 256>>>(h_, fnw + (size_t)l * D, x_);

        sgemm_kernel<<<gDF, 256>>>(x_, w1, nullptr, gg_, S, HFF, D);
        sgemm_kernel<<<gDF, 256>>>(x_, w3, nullptr, uu_, S, HFF, D);
        swiglu_kernel<<<(S * HFF + 255) / 256, 256>>>(gg_, uu_, S * HFF);
        sgemm_kernel<<<gDD, 256>>>(gg_, w2, h_, h_, S, D, HFF); // residual add
    }

    rmsnorm_kernel<<<1, 256>>>(h_ + (size_t)(S - 1) * D, finw, xf_);
    logits_kernel<<<NV / 256, 256>>>(xf_, Wout, out);
}

// round 2
// speedup vs baseline: 1.4932x; 1.4932x over previous
#include <cuda_runtime.h>
#include <cuda_bf16.h>
#include <math.h>
#include <stdint.h>

// ---------------- Problem constants ----------------
#define S    2048
#define D    1024
#define NH   16
#define HD   64
#define HFF  2816
#define NV   32000
#define NL   4

typedef __nv_bfloat16 bf16;

// ---------------- Device scratch ----------------
__device__ float g_h[S * D];
__device__ float g_q[S * D];
__device__ float g_k[S * D];
__device__ float g_v[S * D];
__device__ float g_gg[S * HFF];
__device__ float g_uu[S * HFF];
__device__ float g_cos[S * 32];
__device__ float g_sin[S * 32];
__device__ float g_xf[D];

// split (hi/lo) bf16 buffers
__device__ __align__(16) bf16 g_xh[S * D],  g_xl[S * D];
__device__ __align__(16) bf16 g_oh[S * D],  g_ol[S * D];
__device__ __align__(16) bf16 g_gh[S * HFF], g_gl[S * HFF];

__device__ __align__(16) bf16 g_wqh[NL * D * D], g_wql[NL * D * D];
__device__ __align__(16) bf16 g_wkh[NL * D * D], g_wkl[NL * D * D];
__device__ __align__(16) bf16 g_wvh[NL * D * D], g_wvl[NL * D * D];
__device__ __align__(16) bf16 g_woh[NL * D * D], g_wol[NL * D * D];
__device__ __align__(16) bf16 g_w1h[NL * D * HFF], g_w1l[NL * D * HFF];
__device__ __align__(16) bf16 g_w3h[NL * D * HFF], g_w3l[NL * D * HFF];
__device__ __align__(16) bf16 g_w2h[NL * HFF * D], g_w2l[NL * HFF * D];

// ---------------- small helpers ----------------
__device__ __forceinline__ void split1(float v, bf16& h, bf16& l) {
    h = __float2bfloat16(v);
    l = __float2bfloat16(v - __bfloat162float(h));
}

// ---------------- split conversion (weights) ----------------
__global__ void split_kernel(const float* __restrict__ in,
                             bf16* __restrict__ hi, bf16* __restrict__ lo, int n4) {
    int i = blockIdx.x * 256 + threadIdx.x;
    if (i >= n4) return;
    float4 v = ((const float4*)in)[i];
    bf16 h0, l0, h1, l1, h2, l2, h3, l3;
    split1(v.x, h0, l0); split1(v.y, h1, l1);
    split1(v.z, h2, l2); split1(v.w, h3, l3);
    ushort4 hp, lp;
    hp.x = *(unsigned short*)&h0; hp.y = *(unsigned short*)&h1;
    hp.z = *(unsigned short*)&h2; hp.w = *(unsigned short*)&h3;
    lp.x = *(unsigned short*)&l0; lp.y = *(unsigned short*)&l1;
    lp.z = *(unsigned short*)&l2; lp.w = *(unsigned short*)&l3;
    ((ushort4*)hi)[i] = hp;
    ((ushort4*)lo)[i] = lp;
}

// ---------------- RoPE table ----------------
__global__ void rope_table_kernel(float* ct, float* st) {
    int idx = blockIdx.x * 256 + threadIdx.x;
    if (idx >= S * 32) return;
    int pos = idx >> 5;
    int i = idx & 31;
    float inv = powf(10000.0f, -((float)(2 * i) / (float)HD));
    float ang = (float)pos * inv;
    float s, c;
    sincosf(ang, &s, &c);
    ct[idx] = c;
    st[idx] = s;
}

// ---------------- Embedding gather ----------------
__global__ void embed_kernel(const int* __restrict__ tokens,
                             const float* __restrict__ emb,
                             float* __restrict__ h) {
    int idx = blockIdx.x * 256 + threadIdx.x;
    int s = idx >> 10;
    int d = idx & 1023;
    h[idx] = emb[(size_t)tokens[s] * D + d];
}

// ---------------- RMSNorm -> split bf16 hi/lo ----------------
__global__ void rmsnorm_split_kernel(const float* __restrict__ in,
                                     const float* __restrict__ w,
                                     bf16* __restrict__ oh, bf16* __restrict__ ol) {
    const float* r = in + (size_t)blockIdx.x * D;
    bf16* ph = oh + (size_t)blockIdx.x * D;
    bf16* pl = ol + (size_t)blockIdx.x * D;
    int t = threadIdx.x;
    float v[4];
    float ss = 0.f;
#pragma unroll
    for (int i = 0; i < 4; i++) { v[i] = r[t + i * 256]; ss += v[i] * v[i]; }
#pragma unroll
    for (int off = 16; off; off >>= 1) ss += __shfl_xor_sync(0xffffffffu, ss, off);
    __shared__ float red[8];
    if ((t & 31) == 0) red[t >> 5] = ss;
    __syncthreads();
    if (t < 8) {
        float x = red[t];
#pragma unroll
        for (int off = 4; off; off >>= 1) x += __shfl_xor_sync(0xffu, x, off);
        if (t == 0) red[0] = x;
    }
    __syncthreads();
    float scale = rsqrtf(red[0] * (1.0f / (float)D) + 1e-6f);
#pragma unroll
    for (int i = 0; i < 4; i++) {
        float rv = v[i] * scale * w[t + i * 256];
        bf16 h, l; split1(rv, h, l);
        ph[t + i * 256] = h;
        pl[t + i * 256] = l;
    }
}

// ---------------- plain fp32 RMSNorm (final row) ----------------
__global__ void rmsnorm_kernel(const float* __restrict__ in,
                               const float* __restrict__ w,
                               float* __restrict__ out) {
    const float* r = in;
    int t = threadIdx.x;
    float v[4];
    float ss = 0.f;
#pragma unroll
    for (int i = 0; i < 4; i++) { v[i] = r[t + i * 256]; ss += v[i] * v[i]; }
#pragma unroll
    for (int off = 16; off; off >>= 1) ss += __shfl_xor_sync(0xffffffffu, ss, off);
    __shared__ float red[8];
    if ((t & 31) == 0) red[t >> 5] = ss;
    __syncthreads();
    if (t < 8) {
        float x = red[t];
#pragma unroll
        for (int off = 4; off; off >>= 1) x += __shfl_xor_sync(0xffu, x, off);
        if (t == 0) red[0] = x;
    }
    __syncthreads();
    float scale = rsqrtf(red[0] * (1.0f / (float)D) + 1e-6f);
#pragma unroll
    for (int i = 0; i < 4; i++) out[t + i * 256] = v[i] * scale * w[t + i * 256];
}

// ---------------- RoPE apply ----------------
__global__ void rope_kernel(float* __restrict__ x,
                            const float* __restrict__ ct,
                            const float* __restrict__ st) {
    int idx = blockIdx.x * 256 + threadIdx.x;
    if (idx >= S * NH * 32) return;
    int pos = idx >> 9;
    int rem = idx & 511;
    int h = rem >> 5;
    int i = rem & 31;
    int base = pos * D + h * HD + 2 * i;
    float c = ct[pos * 32 + i];
    float s = st[pos * 32 + i];
    float x0 = x[base], x1 = x[base + 1];
    x[base]     = x0 * c - x1 * s;
    x[base + 1] = x0 * s + x1 * c;
}

// ---------------- bf16x3 tensor-core GEMM ----------------
// C[M,N] = (Ah+Al)(Bh+Bl) approx, fp32 accum, optional residual add.
// Block tile 128x64, BK=32, 8 warps (4x2), warp tile 32x32, mma.m16n8k16.
#define GBM 128
#define GBN 64
#define GBK 32

#define LDSM4(r0, r1, r2, r3, addr)                                          \
    asm volatile("ldmatrix.sync.aligned.m8n8.x4.shared.b16 {%0,%1,%2,%3},[%4];" \
                 : "=r"(r0), "=r"(r1), "=r"(r2), "=r"(r3) : "r"(addr))
#define LDSM4T(r0, r1, r2, r3, addr)                                         \
    asm volatile("ldmatrix.sync.aligned.m8n8.x4.trans.shared.b16 {%0,%1,%2,%3},[%4];" \
                 : "=r"(r0), "=r"(r1), "=r"(r2), "=r"(r3) : "r"(addr))

__device__ __forceinline__ void mma16816(float* c, const unsigned* a, const unsigned* b) {
    asm volatile(
        "mma.sync.aligned.m16n8k16.row.col.f32.bf16.bf16.f32 "
        "{%0,%1,%2,%3},{%4,%5,%6,%7},{%8,%9},{%0,%1,%2,%3};"
        : "+f"(c[0]), "+f"(c[1]), "+f"(c[2]), "+f"(c[3])
        : "r"(a[0]), "r"(a[1]), "r"(a[2]), "r"(a[3]), "r"(b[0]), "r"(b[1]));
}

__global__ __launch_bounds__(256, 2) void gemm_bf16x3_kernel(
    const bf16* __restrict__ Ah, const bf16* __restrict__ Al,
    const bf16* __restrict__ Bh, const bf16* __restrict__ Bl,
    const float* __restrict__ RES, float* __restrict__ C,
    int M, int N, int K) {
    // A tiles: [buf][m 0..127][k 0..31], rows padded to 40 halfs (80B) -> conflict-free ldmatrix
    __shared__ __align__(16) bf16 As[2][GBM][40];
    // B tiles: [buf][k 0..31][n 0..63], rows padded to 72 halfs (144B)
    __shared__ __align__(16) bf16 Bs[2][GBK][72];

    const int tid  = threadIdx.x;
    const int bm   = blockIdx.y * GBM;
    const int bn   = blockIdx.x * GBN;
    const int warp = tid >> 5;
    const int lane = tid & 31;
    const int wm   = (warp >> 1) * 32;   // warp m offset
    const int wn   = (warp & 1) * 32;    // warp n offset
    const int grp  = lane >> 3;
    const int rin  = lane & 7;

    uint32_t sA = (uint32_t)__cvta_generic_to_shared(&As[0][0][0]);
    uint32_t sB = (uint32_t)__cvta_generic_to_shared(&Bs[0][0][0]);

    // ldmatrix per-lane base addresses (bytes)
    // A x4: grp0:(m0..7,k0..7) grp1:(m8..15,k0..7) grp2:(m0..7,k8..15) grp3:(m8..15,k8..15)
    uint32_t aBase = sA + ((uint32_t)((wm + ((grp & 1) << 3) + rin) * 40 + ((grp >> 1) << 3)) << 1);
    // B x4.trans: grp0:(k0..7,n0..7) grp1:(k8..15,n0..7) grp2:(k0..7,n8..15) grp3:(k8..15,n8..15)
    uint32_t bBase = sB + ((uint32_t)((((grp & 1) << 3) + rin) * 72 + wn + ((grp >> 1) << 3)) << 1);

    float acc[2][4][4];
#pragma unroll
    for (int mi = 0; mi < 2; mi++)
#pragma unroll
        for (int ni = 0; ni < 4; ni++)
#pragma unroll
            for (int j = 0; j < 4; j++) acc[mi][ni][j] = 0.f;

    const bf16* Abuf[2] = {Ah, Al};
    const bf16* Bbuf[2] = {Bh, Bl};

    for (int k0 = 0; k0 < K; k0 += GBK) {
        // ---- load A (both bufs): 1024 uint4 total, 4 per thread ----
#pragma unroll
        for (int i = 0; i < 4; i++) {
            int j = tid + 256 * i;
            int buf = j >> 9, jj = j & 511;
            int m = jj >> 2, kq = jj & 3;
            uint4 v = *(const uint4*)(Abuf[buf] + (size_t)(bm + m) * K + k0 + kq * 8);
            *(uint4*)&As[buf][m][kq * 8] = v;
        }
        // ---- load B (both bufs): 512 uint4 total, 2 per thread ----
#pragma unroll
        for (int i = 0; i < 2; i++) {
            int j = tid + 256 * i;
            int buf = j >> 8, jj = j & 255;
            int kk = jj >> 3, nq = jj & 7;
            uint4 v = *(const uint4*)(Bbuf[buf] + (size_t)(k0 + kk) * N + bn + nq * 8);
            *(uint4*)&Bs[buf][kk][nq * 8] = v;
        }
        __syncthreads();

#pragma unroll
        for (int ks = 0; ks < 2; ks++) {
            unsigned a[2][2][4];   // [buf][mi][reg]
            unsigned b[2][4][2];   // [buf][ni][reg]
#pragma unroll
            for (int buf = 0; buf < 2; buf++) {
#pragma unroll
                for (int mi = 0; mi < 2; mi++) {
                    uint32_t addr = aBase + buf * 10240 + mi * 1280 + ks * 32;
                    LDSM4(a[buf][mi][0], a[buf][mi][1], a[buf][mi][2], a[buf][mi][3], addr);
                }
#pragma unroll
                for (int nj = 0; nj < 2; nj++) {
                    uint32_t addr = bBase + buf * 4608 + nj * 32 + ks * 2304;
                    LDSM4T(b[buf][2 * nj][0], b[buf][2 * nj][1],
                           b[buf][2 * nj + 1][0], b[buf][2 * nj + 1][1], addr);
                }
            }
#pragma unroll
            for (int mi = 0; mi < 2; mi++)
#pragma unroll
                for (int ni = 0; ni < 4; ni++) {
                    mma16816(acc[mi][ni], a[0][mi], b[0][ni]);   // hi*hi
                    mma16816(acc[mi][ni], a[0][mi], b[1][ni]);   // hi*lo
                    mma16816(acc[mi][ni], a[1][mi], b[0][ni]);   // lo*hi
                }
        }
        __syncthreads();
    }

    // ---- epilogue ----
    int r0 = bm + wm + (lane >> 2);
    int c0 = bn + wn + (lane & 3) * 2;
#pragma unroll
    for (int mi = 0; mi < 2; mi++)
#pragma unroll
        for (int ni = 0; ni < 4; ni++) {
            int row = r0 + mi * 16;
            int col = c0 + ni * 8;
            float2 v0 = make_float2(acc[mi][ni][0], acc[mi][ni][1]);
            float2 v1 = make_float2(acc[mi][ni][2], acc[mi][ni][3]);
            if (RES) {
                float2 a0 = *(const float2*)(RES + (size_t)row * N + col);
                float2 a1 = *(const float2*)(RES + (size_t)(row + 8) * N + col);
                v0.x += a0.x; v0.y += a0.y;
                v1.x += a1.x; v1.y += a1.y;
            }
            *(float2*)(C + (size_t)row * N + col) = v0;
            *(float2*)(C + (size_t)(row + 8) * N + col) = v1;
        }
}

// ---------------- Flash attention (fp32), writes split hi/lo ----------------
__global__ void attn_kernel(const float* __restrict__ Q,
                            const float* __restrict__ K,
                            const float* __restrict__ V,
                            bf16* __restrict__ Oh, bf16* __restrict__ Ol) {
    const int qt = blockIdx.x;
    const int head = blockIdx.y;
    const int tid = threadIdx.x;
    const int r = tid >> 1;
    const int half = tid & 1;
    const int lane = tid & 31;
    const int qRow = qt * 64 + r;

    __shared__ float4 Ks[64][17];
    __shared__ float4 Vs[64][17];

    float4 q[16];
    const float4* qp = (const float4*)(Q + (size_t)qRow * D + head * HD);
#pragma unroll
    for (int i = 0; i < 16; i++) q[i] = qp[i];

    float4 o[8];
#pragma unroll
    for (int i = 0; i < 8; i++) o[i] = make_float4(0.f, 0.f, 0.f, 0.f);
    float m = -1e30f, l = 0.f;
    const float scale = 0.125f;

    for (int kt = 0; kt <= qt; kt++) {
        {
            const int j = tid >> 1;
            const float4* kp = (const float4*)(K + (size_t)(kt * 64 + j) * D + head * HD) + half * 8;
            const float4* vp = (const float4*)(V + (size_t)(kt * 64 + j) * D + head * HD) + half * 8;
#pragma unroll
            for (int c = 0; c < 8; c++) {
                Ks[j][half * 8 + c] = kp[c];
                Vs[j][half * 8 + c] = vp[c];
            }
        }
        __syncthreads();

        float s[32];
        const bool diag = (kt == qt);
#pragma unroll
        for (int jj = 0; jj < 32; jj++) {
            int j = half * 32 + jj;
            float acc = 0.f;
#pragma unroll
            for (int d = 0; d < 16; d++) {
                float4 kv = Ks[j][d];
                acc += q[d].x * kv.x + q[d].y * kv.y + q[d].z * kv.z + q[d].w * kv.w;
            }
            acc *= scale;
            if (diag && (kt * 64 + j) > qRow) acc = -1e30f;
            s[jj] = acc;
        }
        float tm = s[0];
#pragma unroll
        for (int jj = 1; jj < 32; jj++) tm = fmaxf(tm, s[jj]);
        tm = fmaxf(tm, __shfl_xor_sync(0xffffffffu, tm, 1));
        float mnew = fmaxf(m, tm);
        float corr = __expf(m - mnew);
        float ls = 0.f;
#pragma unroll
        for (int jj = 0; jj < 32; jj++) {
            s[jj] = __expf(s[jj] - mnew);
            ls += s[jj];
        }
        ls += __shfl_xor_sync(0xffffffffu, ls, 1);
        l = l * corr + ls;
        m = mnew;
#pragma unroll
        for (int i = 0; i < 8; i++) {
            o[i].x *= corr; o[i].y *= corr; o[i].z *= corr; o[i].w *= corr;
        }
#pragma unroll
        for (int k = 0; k < 64; k++) {
            float pk = __shfl_sync(0xffffffffu, s[k & 31], (lane & ~1) | (k >> 5));
#pragma unroll
            for (int d = 0; d < 8; d++) {
                float4 vv = Vs[k][half * 8 + d];
                o[d].x += pk * vv.x; o[d].y += pk * vv.y;
                o[d].z += pk * vv.z; o[d].w += pk * vv.w;
            }
        }
        __syncthreads();
    }
    float inv = 1.f / l;
    size_t base = (size_t)qRow * D + head * HD + half * 32;
#pragma unroll
    for (int d = 0; d < 8; d++) {
        float4 v = o[d];
        v.x *= inv; v.y *= inv; v.z *= inv; v.w *= inv;
        bf16 h0, l0, h1, l1, h2, l2, h3, l3;
        split1(v.x, h0, l0); split1(v.y, h1, l1);
        split1(v.z, h2, l2); split1(v.w, h3, l3);
        ushort4 hp, lp;
        hp.x = *(unsigned short*)&h0; hp.y = *(unsigned short*)&h1;
        hp.z = *(unsigned short*)&h2; hp.w = *(unsigned short*)&h3;
        lp.x = *(unsigned short*)&l0; lp.y = *(unsigned short*)&l1;
        lp.z = *(unsigned short*)&l2; lp.w = *(unsigned short*)&l3;
        *(ushort4*)(Oh + base + d * 4) = hp;
        *(ushort4*)(Ol + base + d * 4) = lp;
    }
}

// ---------------- SwiGLU -> split hi/lo ----------------
__global__ void swiglu_split_kernel(const float* __restrict__ g,
                                    const float* __restrict__ u,
                                    bf16* __restrict__ oh, bf16* __restrict__ ol, int n) {
    int idx = blockIdx.x * 256 + threadIdx.x;
    if (idx >= n) return;
    float z = g[idx];
    float sig = 1.0f / (1.0f + __expf(-z));
    float r = z * sig * u[idx];
    bf16 h, l; split1(r, h, l);
    oh[idx] = h;
    ol[idx] = l;
}

// ---------------- Logits ----------------
__global__ void logits_kernel(const float* __restrict__ xf,
                              const float* __restrict__ Wout,
                              float* __restrict__ out) {
    __shared__ float xs[D];
    for (int i = threadIdx.x; i < D; i += 256) xs[i] = xf[i];
    __syncthreads();
    int v = blockIdx.x * 256 + threadIdx.x;
    float acc = 0.f;
#pragma unroll 8
    for (int d = 0; d < D; d++) acc += xs[d] * Wout[(size_t)d * NV + v];
    out[v] = acc;
}

// ---------------- Host launch ----------------
extern "C" void kernel_launch(void* const* d_in, const int* in_sizes, int n_in,
                              void* d_out, int out_size) {
    int bi = 1;
    if (n_in >= 2 && in_sizes[1] == 1) bi = 2;
    const int*   tokens  = (const int*)d_in[0];
    const float* tok_emb = (const float*)d_in[bi + 0];
    const float* Wq      = (const float*)d_in[bi + 1];
    const float* Wk      = (const float*)d_in[bi + 2];
    const float* Wv      = (const float*)d_in[bi + 3];
    const float* Wo      = (const float*)d_in[bi + 4];
    const float* W1      = (const float*)d_in[bi + 5];
    const float* W2      = (const float*)d_in[bi + 6];
    const float* W3      = (const float*)d_in[bi + 7];
    const float* anw     = (const float*)d_in[bi + 8];
    const float* fnw     = (const float*)d_in[bi + 9];
    const float* finw    = (const float*)d_in[bi + 10];
    const float* Wout    = (const float*)d_in[bi + 11];
    float* out = (float*)d_out;

    float *h_, *q_, *k_, *v_, *gg_, *uu_, *cos_, *sin_, *xf_;
    bf16 *xh_, *xl_, *oh_, *ol_, *gh_, *gl_;
    bf16 *wqh_, *wql_, *wkh_, *wkl_, *wvh_, *wvl_, *woh_, *wol_;
    bf16 *w1h_, *w1l_, *w3h_, *w3l_, *w2h_, *w2l_;

    cudaGetSymbolAddress((void**)&h_,  g_h);
    cudaGetSymbolAddress((void**)&q_,  g_q);
    cudaGetSymbolAddress((void**)&k_,  g_k);
    cudaGetSymbolAddress((void**)&v_,  g_v);
    cudaGetSymbolAddress((void**)&gg_, g_gg);
    cudaGetSymbolAddress((void**)&uu_, g_uu);
    cudaGetSymbolAddress((void**)&cos_, g_cos);
    cudaGetSymbolAddress((void**)&sin_, g_sin);
    cudaGetSymbolAddress((void**)&xf_, g_xf);
    cudaGetSymbolAddress((void**)&xh_, g_xh);
    cudaGetSymbolAddress((void**)&xl_, g_xl);
    cudaGetSymbolAddress((void**)&oh_, g_oh);
    cudaGetSymbolAddress((void**)&ol_, g_ol);
    cudaGetSymbolAddress((void**)&gh_, g_gh);
    cudaGetSymbolAddress((void**)&gl_, g_gl);
    cudaGetSymbolAddress((void**)&wqh_, g_wqh); cudaGetSymbolAddress((void**)&wql_, g_wql);
    cudaGetSymbolAddress((void**)&wkh_, g_wkh); cudaGetSymbolAddress((void**)&wkl_, g_wkl);
    cudaGetSymbolAddress((void**)&wvh_, g_wvh); cudaGetSymbolAddress((void**)&wvl_, g_wvl);
    cudaGetSymbolAddress((void**)&woh_, g_woh); cudaGetSymbolAddress((void**)&wol_, g_wol);
    cudaGetSymbolAddress((void**)&w1h_, g_w1h); cudaGetSymbolAddress((void**)&w1l_, g_w1l);
    cudaGetSymbolAddress((void**)&w3h_, g_w3h); cudaGetSymbolAddress((void**)&w3l_, g_w3l);
    cudaGetSymbolAddress((void**)&w2h_, g_w2h); cudaGetSymbolAddress((void**)&w2l_, g_w2l);

    // weight splits (runs each replay; pure-bandwidth, ~60us)
    const int nDD = NL * D * D / 4, nDF = NL * D * HFF / 4;
    split_kernel<<<(nDD + 255) / 256, 256>>>(Wq, wqh_, wql_, nDD);
    split_kernel<<<(nDD + 255) / 256, 256>>>(Wk, wkh_, wkl_, nDD);
    split_kernel<<<(nDD + 255) / 256, 256>>>(Wv, wvh_, wvl_, nDD);
    split_kernel<<<(nDD + 255) / 256, 256>>>(Wo, woh_, wol_, nDD);
    split_kernel<<<(nDF + 255) / 256, 256>>>(W1, w1h_, w1l_, nDF);
    split_kernel<<<(nDF + 255) / 256, 256>>>(W3, w3h_, w3l_, nDF);
    split_kernel<<<(nDF + 255) / 256, 256>>>(W2, w2h_, w2l_, nDF);

    rope_table_kernel<<<(S * 32 + 255) / 256, 256>>>(cos_, sin_);
    embed_kernel<<<(S * D) / 256, 256>>>(tokens, tok_emb, h_);

    const dim3 gDD(D / GBN, S / GBM);     // (16, 16)
    const dim3 gDF(HFF / GBN, S / GBM);   // (44, 16)

    for (int l = 0; l < NL; l++) {
        size_t offDD = (size_t)l * D * D;
        size_t offDF = (size_t)l * D * HFF;

        rmsnorm_split_kernel<<<S, 256>>>(h_, anw + (size_t)l * D, xh_, xl_);

        gemm_bf16x3_kernel<<<gDD, 256>>>(xh_, xl_, wqh_ + offDD, wql_ + offDD, nullptr, q_, S, D, D);
        gemm_bf16x3_kernel<<<gDD, 256>>>(xh_, xl_, wkh_ + offDD, wkl_ + offDD, nullptr, k_, S, D, D);
        gemm_bf16x3_kernel<<<gDD, 256>>>(xh_, xl_, wvh_ + offDD, wvl_ + offDD, nullptr, v_, S, D, D);

        rope_kernel<<<(S * NH * 32 + 255) / 256, 256>>>(q_, cos_, sin_);
        rope_kernel<<<(S * NH * 32 + 255) / 256, 256>>>(k_, cos_, sin_);

        attn_kernel<<<dim3(S / 64, NH), 128>>>(q_, k_, v_, oh_, ol_);

        gemm_bf16x3_kernel<<<gDD, 256>>>(oh_, ol_, woh_ + offDD, wol_ + offDD, h_, h_, S, D, D);

        rmsnorm_split_kernel<<<S, 256>>>(h_, fnw + (size_t)l * D, xh_, xl_);

        gemm_bf16x3_kernel<<<gDF, 256>>>(xh_, xl_, w1h_ + offDF, w1l_ + offDF, nullptr, gg_, S, HFF, D);
        gemm_bf16x3_kernel<<<gDF, 256>>>(xh_, xl_, w3h_ + offDF, w3l_ + offDF, nullptr, uu_, S, HFF, D);
        swiglu_split_kernel<<<(S * HFF + 255) / 256, 256>>>(gg_, uu_, gh_, gl_, S * HFF);
        gemm_bf16x3_kernel<<<gDD, 256>>>(gh_, gl_, w2h_ + offDF, w2l_ + offDF, h_, h_, S, D, HFF);
    }

    rmsnorm_kernel<<<1, 256>>>(h_ + (size_t)(S - 1) * D, finw, xf_);
    logits_kernel<<<NV / 256, 256>>>(xf_, Wout, out);
}

// round 3
// speedup vs baseline: 1.4981x; 1.0033x over previous
#include <cuda_runtime.h>
#include <cuda_bf16.h>
#include <math.h>
#include <stdint.h>

// ---------------- Problem constants ----------------
#define S    2048
#define D    1024
#define NH   16
#define HD   64
#define HFF  2816
#define NV   32000
#define NL   4

typedef __nv_bfloat16 bf16;

// ---------------- Device scratch ----------------
__device__ float g_h[S * D];
__device__ float g_q[S * D];
__device__ float g_k[S * D];
__device__ float g_v[S * D];
__device__ float g_gg[S * HFF];
__device__ float g_uu[S * HFF];
__device__ float g_cos[S * 32];
__device__ float g_sin[S * 32];
__device__ float g_xf[D];

// split (hi/lo) bf16 buffers
__device__ __align__(16) bf16 g_xh[S * D],  g_xl[S * D];
__device__ __align__(16) bf16 g_oh[S * D],  g_ol[S * D];
__device__ __align__(16) bf16 g_gh[S * HFF], g_gl[S * HFF];

__device__ __align__(16) bf16 g_wqh[NL * D * D], g_wql[NL * D * D];
__device__ __align__(16) bf16 g_wkh[NL * D * D], g_wkl[NL * D * D];
__device__ __align__(16) bf16 g_wvh[NL * D * D], g_wvl[NL * D * D];
__device__ __align__(16) bf16 g_woh[NL * D * D], g_wol[NL * D * D];
__device__ __align__(16) bf16 g_w1h[NL * D * HFF], g_w1l[NL * D * HFF];
__device__ __align__(16) bf16 g_w3h[NL * D * HFF], g_w3l[NL * D * HFF];
__device__ __align__(16) bf16 g_w2h[NL * HFF * D], g_w2l[NL * HFF * D];

// ---------------- small helpers ----------------
__device__ __forceinline__ void split1(float v, bf16& h, bf16& l) {
    h = __float2bfloat16(v);
    l = __float2bfloat16(v - __bfloat162float(h));
}

// ---------------- split conversion (weights) ----------------
__global__ void split_kernel(const float* __restrict__ in,
                             bf16* __restrict__ hi, bf16* __restrict__ lo, int n4) {
    int i = blockIdx.x * 256 + threadIdx.x;
    if (i >= n4) return;
    float4 v = ((const float4*)in)[i];
    bf16 h0, l0, h1, l1, h2, l2, h3, l3;
    split1(v.x, h0, l0); split1(v.y, h1, l1);
    split1(v.z, h2, l2); split1(v.w, h3, l3);
    ushort4 hp, lp;
    hp.x = *(unsigned short*)&h0; hp.y = *(unsigned short*)&h1;
    hp.z = *(unsigned short*)&h2; hp.w = *(unsigned short*)&h3;
    lp.x = *(unsigned short*)&l0; lp.y = *(unsigned short*)&l1;
    lp.z = *(unsigned short*)&l2; lp.w = *(unsigned short*)&l3;
    ((ushort4*)hi)[i] = hp;
    ((ushort4*)lo)[i] = lp;
}

// ---------------- RoPE table ----------------
__global__ void rope_table_kernel(float* ct, float* st) {
    int idx = blockIdx.x * 256 + threadIdx.x;
    if (idx >= S * 32) return;
    int pos = idx >> 5;
    int i = idx & 31;
    float inv = powf(10000.0f, -((float)(2 * i) / (float)HD));
    float ang = (float)pos * inv;
    float s, c;
    sincosf(ang, &s, &c);
    ct[idx] = c;
    st[idx] = s;
}

// ---------------- Embedding gather ----------------
__global__ void embed_kernel(const int* __restrict__ tokens,
                             const float* __restrict__ emb,
                             float* __restrict__ h) {
    int idx = blockIdx.x * 256 + threadIdx.x;
    int s = idx >> 10;
    int d = idx & 1023;
    h[idx] = emb[(size_t)tokens[s] * D + d];
}

// ---------------- RMSNorm -> split bf16 hi/lo ----------------
__global__ void rmsnorm_split_kernel(const float* __restrict__ in,
                                     const float* __restrict__ w,
                                     bf16* __restrict__ oh, bf16* __restrict__ ol) {
    const float* r = in + (size_t)blockIdx.x * D;
    bf16* ph = oh + (size_t)blockIdx.x * D;
    bf16* pl = ol + (size_t)blockIdx.x * D;
    int t = threadIdx.x;
    float v[4];
    float ss = 0.f;
#pragma unroll
    for (int i = 0; i < 4; i++) { v[i] = r[t + i * 256]; ss += v[i] * v[i]; }
#pragma unroll
    for (int off = 16; off; off >>= 1) ss += __shfl_xor_sync(0xffffffffu, ss, off);
    __shared__ float red[8];
    if ((t & 31) == 0) red[t >> 5] = ss;
    __syncthreads();
    if (t < 8) {
        float x = red[t];
#pragma unroll
        for (int off = 4; off; off >>= 1) x += __shfl_xor_sync(0xffu, x, off);
        if (t == 0) red[0] = x;
    }
    __syncthreads();
    float scale = rsqrtf(red[0] * (1.0f / (float)D) + 1e-6f);
#pragma unroll
    for (int i = 0; i < 4; i++) {
        float rv = v[i] * scale * w[t + i * 256];
        bf16 h, l; split1(rv, h, l);
        ph[t + i * 256] = h;
        pl[t + i * 256] = l;
    }
}

// ---------------- plain fp32 RMSNorm (final row) ----------------
__global__ void rmsnorm_kernel(const float* __restrict__ in,
                               const float* __restrict__ w,
                               float* __restrict__ out) {
    const float* r = in;
    int t = threadIdx.x;
    float v[4];
    float ss = 0.f;
#pragma unroll
    for (int i = 0; i < 4; i++) { v[i] = r[t + i * 256]; ss += v[i] * v[i]; }
#pragma unroll
    for (int off = 16; off; off >>= 1) ss += __shfl_xor_sync(0xffffffffu, ss, off);
    __shared__ float red[8];
    if ((t & 31) == 0) red[t >> 5] = ss;
    __syncthreads();
    if (t < 8) {
        float x = red[t];
#pragma unroll
        for (int off = 4; off; off >>= 1) x += __shfl_xor_sync(0xffu, x, off);
        if (t == 0) red[0] = x;
    }
    __syncthreads();
    float scale = rsqrtf(red[0] * (1.0f / (float)D) + 1e-6f);
#pragma unroll
    for (int i = 0; i < 4; i++) out[t + i * 256] = v[i] * scale * w[t + i * 256];
}

// ---------------- RoPE apply ----------------
__global__ void rope_kernel(float* __restrict__ x,
                            const float* __restrict__ ct,
                            const float* __restrict__ st) {
    int idx = blockIdx.x * 256 + threadIdx.x;
    if (idx >= S * NH * 32) return;
    int pos = idx >> 9;
    int rem = idx & 511;
    int h = rem >> 5;
    int i = rem & 31;
    int base = pos * D + h * HD + 2 * i;
    float c = ct[pos * 32 + i];
    float s = st[pos * 32 + i];
    float x0 = x[base], x1 = x[base + 1];
    x[base]     = x0 * c - x1 * s;
    x[base + 1] = x0 * s + x1 * c;
}

// ---------------- bf16x3 tensor-core GEMM, cp.async 3-stage pipeline ----------------
// C[M,N] = (Ah+Al)(Bh+Bl) approx (hh + hl + lh), fp32 accum, optional residual.
// Block 128x128x32, 256 threads (8 warps, 2x4), warp tile 64x32.
#define GBM 128
#define GBN 128
#define GBK 32
#define NSTAGE 3
// byte layout per stage: A: 2 bufs x 128 rows x 40 halfs (80B rows) = 20480
//                        B: 2 bufs x 32 rows x 136 halfs (272B rows) = 17408
#define A_BUF_BYTES 10240
#define B_BUF_BYTES 8704
#define A_STAGE_BYTES 20480
#define STAGE_BYTES 37888
#define SMEM_BYTES (NSTAGE * STAGE_BYTES)

#define LDSM4(r0, r1, r2, r3, addr)                                          \
    asm volatile("ldmatrix.sync.aligned.m8n8.x4.shared.b16 {%0,%1,%2,%3},[%4];" \
                 : "=r"(r0), "=r"(r1), "=r"(r2), "=r"(r3) : "r"(addr))
#define LDSM4T(r0, r1, r2, r3, addr)                                         \
    asm volatile("ldmatrix.sync.aligned.m8n8.x4.trans.shared.b16 {%0,%1,%2,%3},[%4];" \
                 : "=r"(r0), "=r"(r1), "=r"(r2), "=r"(r3) : "r"(addr))
#define CP_ASYNC16(saddr, gaddr)                                             \
    asm volatile("cp.async.cg.shared.global [%0],[%1],16;" :: "r"(saddr), "l"(gaddr))
#define CP_COMMIT() asm volatile("cp.async.commit_group;" ::: "memory")
#define CP_WAIT1()  asm volatile("cp.async.wait_group 1;" ::: "memory")

__device__ __forceinline__ void mma16816(float* c, const unsigned* a, const unsigned* b) {
    asm volatile(
        "mma.sync.aligned.m16n8k16.row.col.f32.bf16.bf16.f32 "
        "{%0,%1,%2,%3},{%4,%5,%6,%7},{%8,%9},{%0,%1,%2,%3};"
        : "+f"(c[0]), "+f"(c[1]), "+f"(c[2]), "+f"(c[3])
        : "r"(a[0]), "r"(a[1]), "r"(a[2]), "r"(a[3]), "r"(b[0]), "r"(b[1]));
}

extern __shared__ char gsmem[];

__global__ __launch_bounds__(256) void gemm_bf16x3_kernel(
    const bf16* __restrict__ Ah, const bf16* __restrict__ Al,
    const bf16* __restrict__ Bh, const bf16* __restrict__ Bl,
    const float* __restrict__ RES, float* __restrict__ C,
    int M, int N, int K) {
    const int tid  = threadIdx.x;
    const int bm   = blockIdx.y * GBM;
    const int bn   = blockIdx.x * GBN;
    const int warp = tid >> 5;
    const int lane = tid & 31;
    const int wm   = (warp >> 2) * 64;   // 2 warp-rows
    const int wn   = (warp & 3) * 32;    // 4 warp-cols
    const int grp  = lane >> 3;
    const int rin  = lane & 7;

    const uint32_t sBase = (uint32_t)__cvta_generic_to_shared(gsmem);

    // per-lane ldmatrix offsets
    const uint32_t laneA = (uint32_t)((((grp & 1) << 3) + rin) * 80 + ((grp >> 1) << 4));
    const uint32_t laneB = (uint32_t)((((grp & 1) << 3) + rin) * 272 + (((grp >> 1) << 3) + wn) * 2);

    float acc[4][4][4];
#pragma unroll
    for (int mi = 0; mi < 4; mi++)
#pragma unroll
        for (int ni = 0; ni < 4; ni++)
#pragma unroll
            for (int j = 0; j < 4; j++) acc[mi][ni][j] = 0.f;

    const int KT = K / GBK;

    // cp.async stage loader: A 1024 chunks (4/thr), B 1024 chunks (4/thr)
    auto issue = [&](int kt, int stage) {
        const uint32_t stOff = sBase + stage * STAGE_BYTES;
        const int kOff = kt * GBK;
#pragma unroll
        for (int i = 0; i < 4; i++) {
            int c = tid + 256 * i;
            int buf = c >> 9, rem = c & 511;
            int m = rem >> 2, kq = rem & 3;
            const bf16* g = (buf ? Al : Ah) + (size_t)(bm + m) * K + kOff + kq * 8;
            uint32_t sa = stOff + buf * A_BUF_BYTES + m * 80 + kq * 16;
            CP_ASYNC16(sa, g);
        }
#pragma unroll
        for (int i = 0; i < 4; i++) {
            int c = tid + 256 * i;
            int buf = c >> 9, rem = c & 511;
            int kk = rem >> 4, nq = rem & 15;
            const bf16* g = (buf ? Bl : Bh) + (size_t)(kOff + kk) * N + bn + nq * 8;
            uint32_t sa = stOff + A_STAGE_BYTES + buf * B_BUF_BYTES + kk * 272 + nq * 16;
            CP_ASYNC16(sa, g);
        }
    };

    issue(0, 0); CP_COMMIT();
    issue(1, 1); CP_COMMIT();

    for (int kt = 0; kt < KT; kt++) {
        CP_WAIT1();
        __syncthreads();
        if (kt + 2 < KT) issue(kt + 2, (kt + 2) % NSTAGE);
        CP_COMMIT();

        const uint32_t stOff = sBase + (kt % NSTAGE) * STAGE_BYTES;
#pragma unroll
        for (int ks = 0; ks < 2; ks++) {
            unsigned a[2][4][4];
            unsigned b[2][4][2];
#pragma unroll
            for (int buf = 0; buf < 2; buf++) {
                uint32_t aS = stOff + buf * A_BUF_BYTES + laneA + ks * 32;
#pragma unroll
                for (int mt = 0; mt < 4; mt++) {
                    uint32_t addr = aS + (wm + mt * 16) * 80;
                    LDSM4(a[buf][mt][0], a[buf][mt][1], a[buf][mt][2], a[buf][mt][3], addr);
                }
                uint32_t bS = stOff + A_STAGE_BYTES + buf * B_BUF_BYTES + laneB + ks * 4352;
#pragma unroll
                for (int nj = 0; nj < 2; nj++) {
                    uint32_t addr = bS + nj * 32;
                    LDSM4T(b[buf][2 * nj][0], b[buf][2 * nj][1],
                           b[buf][2 * nj + 1][0], b[buf][2 * nj + 1][1], addr);
                }
            }
#pragma unroll
            for (int mt = 0; mt < 4; mt++)
#pragma unroll
                for (int nt = 0; nt < 4; nt++) {
                    mma16816(acc[mt][nt], a[0][mt], b[0][nt]);   // hi*hi
                    mma16816(acc[mt][nt], a[0][mt], b[1][nt]);   // hi*lo
                    mma16816(acc[mt][nt], a[1][mt], b[0][nt]);   // lo*hi
                }
        }
        __syncthreads();
    }

    // ---- epilogue ----
    int r0 = bm + wm + (lane >> 2);
    int c0 = bn + wn + (lane & 3) * 2;
#pragma unroll
    for (int mt = 0; mt < 4; mt++)
#pragma unroll
        for (int nt = 0; nt < 4; nt++) {
            int row = r0 + mt * 16;
            int col = c0 + nt * 8;
            float2 v0 = make_float2(acc[mt][nt][0], acc[mt][nt][1]);
            float2 v1 = make_float2(acc[mt][nt][2], acc[mt][nt][3]);
            if (RES) {
                float2 a0 = *(const float2*)(RES + (size_t)row * N + col);
                float2 a1 = *(const float2*)(RES + (size_t)(row + 8) * N + col);
                v0.x += a0.x; v0.y += a0.y;
                v1.x += a1.x; v1.y += a1.y;
            }
            *(float2*)(C + (size_t)row * N + col) = v0;
            *(float2*)(C + (size_t)(row + 8) * N + col) = v1;
        }
}

// ---------------- Flash attention (fp32), writes split hi/lo ----------------
__global__ void attn_kernel(const float* __restrict__ Q,
                            const float* __restrict__ K,
                            const float* __restrict__ V,
                            bf16* __restrict__ Oh, bf16* __restrict__ Ol) {
    const int qt = blockIdx.x;
    const int head = blockIdx.y;
    const int tid = threadIdx.x;
    const int r = tid >> 1;
    const int half = tid & 1;
    const int lane = tid & 31;
    const int qRow = qt * 64 + r;

    __shared__ float4 Ks[64][17];
    __shared__ float4 Vs[64][17];

    float4 q[16];
    const float4* qp = (const float4*)(Q + (size_t)qRow * D + head * HD);
#pragma unroll
    for (int i = 0; i < 16; i++) q[i] = qp[i];

    float4 o[8];
#pragma unroll
    for (int i = 0; i < 8; i++) o[i] = make_float4(0.f, 0.f, 0.f, 0.f);
    float m = -1e30f, l = 0.f;
    const float scale = 0.125f;

    for (int kt = 0; kt <= qt; kt++) {
        {
            const int j = tid >> 1;
            const float4* kp = (const float4*)(K + (size_t)(kt * 64 + j) * D + head * HD) + half * 8;
            const float4* vp = (const float4*)(V + (size_t)(kt * 64 + j) * D + head * HD) + half * 8;
#pragma unroll
            for (int c = 0; c < 8; c++) {
                Ks[j][half * 8 + c] = kp[c];
                Vs[j][half * 8 + c] = vp[c];
            }
        }
        __syncthreads();

        float s[32];
        const bool diag = (kt == qt);
#pragma unroll
        for (int jj = 0; jj < 32; jj++) {
            int j = half * 32 + jj;
            float acc = 0.f;
#pragma unroll
            for (int d = 0; d < 16; d++) {
                float4 kv = Ks[j][d];
                acc += q[d].x * kv.x + q[d].y * kv.y + q[d].z * kv.z + q[d].w * kv.w;
            }
            acc *= scale;
            if (diag && (kt * 64 + j) > qRow) acc = -1e30f;
            s[jj] = acc;
        }
        float tm = s[0];
#pragma unroll
        for (int jj = 1; jj < 32; jj++) tm = fmaxf(tm, s[jj]);
        tm = fmaxf(tm, __shfl_xor_sync(0xffffffffu, tm, 1));
        float mnew = fmaxf(m, tm);
        float corr = __expf(m - mnew);
        float ls = 0.f;
#pragma unroll
        for (int jj = 0; jj < 32; jj++) {
            s[jj] = __expf(s[jj] - mnew);
            ls += s[jj];
        }
        ls += __shfl_xor_sync(0xffffffffu, ls, 1);
        l = l * corr + ls;
        m = mnew;
#pragma unroll
        for (int i = 0; i < 8; i++) {
            o[i].x *= corr; o[i].y *= corr; o[i].z *= corr; o[i].w *= corr;
        }
#pragma unroll
        for (int k = 0; k < 64; k++) {
            float pk = __shfl_sync(0xffffffffu, s[k & 31], (lane & ~1) | (k >> 5));
#pragma unroll
            for (int d = 0; d < 8; d++) {
                float4 vv = Vs[k][half * 8 + d];
                o[d].x += pk * vv.x; o[d].y += pk * vv.y;
                o[d].z += pk * vv.z; o[d].w += pk * vv.w;
            }
        }
        __syncthreads();
    }
    float inv = 1.f / l;
    size_t base = (size_t)qRow * D + head * HD + half * 32;
#pragma unroll
    for (int d = 0; d < 8; d++) {
        float4 v = o[d];
        v.x *= inv; v.y *= inv; v.z *= inv; v.w *= inv;
        bf16 h0, l0, h1, l1, h2, l2, h3, l3;
        split1(v.x, h0, l0); split1(v.y, h1, l1);
        split1(v.z, h2, l2); split1(v.w, h3, l3);
        ushort4 hp, lp;
        hp.x = *(unsigned short*)&h0; hp.y = *(unsigned short*)&h1;
        hp.z = *(unsigned short*)&h2; hp.w = *(unsigned short*)&h3;
        lp.x = *(unsigned short*)&l0; lp.y = *(unsigned short*)&l1;
        lp.z = *(unsigned short*)&l2; lp.w = *(unsigned short*)&l3;
        *(ushort4*)(Oh + base + d * 4) = hp;
        *(ushort4*)(Ol + base + d * 4) = lp;
    }
}

// ---------------- SwiGLU -> split hi/lo ----------------
__global__ void swiglu_split_kernel(const float* __restrict__ g,
                                    const float* __restrict__ u,
                                    bf16* __restrict__ oh, bf16* __restrict__ ol, int n) {
    int idx = blockIdx.x * 256 + threadIdx.x;
    if (idx >= n) return;
    float z = g[idx];
    float sig = 1.0f / (1.0f + __expf(-z));
    float r = z * sig * u[idx];
    bf16 h, l; split1(r, h, l);
    oh[idx] = h;
    ol[idx] = l;
}

// ---------------- Logits ----------------
__global__ void logits_kernel(const float* __restrict__ xf,
                              const float* __restrict__ Wout,
                              float* __restrict__ out) {
    __shared__ float xs[D];
    for (int i = threadIdx.x; i < D; i += 256) xs[i] = xf[i];
    __syncthreads();
    int v = blockIdx.x * 256 + threadIdx.x;
    float acc = 0.f;
#pragma unroll 8
    for (int d = 0; d < D; d++) acc += xs[d] * Wout[(size_t)d * NV + v];
    out[v] = acc;
}

// ---------------- Host launch ----------------
extern "C" void kernel_launch(void* const* d_in, const int* in_sizes, int n_in,
                              void* d_out, int out_size) {
    int bi = 1;
    if (n_in >= 2 && in_sizes[1] == 1) bi = 2;
    const int*   tokens  = (const int*)d_in[0];
    const float* tok_emb = (const float*)d_in[bi + 0];
    const float* Wq      = (const float*)d_in[bi + 1];
    const float* Wk      = (const float*)d_in[bi + 2];
    const float* Wv      = (const float*)d_in[bi + 3];
    const float* Wo      = (const float*)d_in[bi + 4];
    const float* W1      = (const float*)d_in[bi + 5];
    const float* W2      = (const float*)d_in[bi + 6];
    const float* W3      = (const float*)d_in[bi + 7];
    const float* anw     = (const float*)d_in[bi + 8];
    const float* fnw     = (const float*)d_in[bi + 9];
    const float* finw    = (const float*)d_in[bi + 10];
    const float* Wout    = (const float*)d_in[bi + 11];
    float* out = (float*)d_out;

    float *h_, *q_, *k_, *v_, *gg_, *uu_, *cos_, *sin_, *xf_;
    bf16 *xh_, *xl_, *oh_, *ol_, *gh_, *gl_;
    bf16 *wqh_, *wql_, *wkh_, *wkl_, *wvh_, *wvl_, *woh_, *wol_;
    bf16 *w1h_, *w1l_, *w3h_, *w3l_, *w2h_, *w2l_;

    cudaGetSymbolAddress((void**)&h_,  g_h);
    cudaGetSymbolAddress((void**)&q_,  g_q);
    cudaGetSymbolAddress((void**)&k_,  g_k);
    cudaGetSymbolAddress((void**)&v_,  g_v);
    cudaGetSymbolAddress((void**)&gg_, g_gg);
    cudaGetSymbolAddress((void**)&uu_, g_uu);
    cudaGetSymbolAddress((void**)&cos_, g_cos);
    cudaGetSymbolAddress((void**)&sin_, g_sin);
    cudaGetSymbolAddress((void**)&xf_, g_xf);
    cudaGetSymbolAddress((void**)&xh_, g_xh);
    cudaGetSymbolAddress((void**)&xl_, g_xl);
    cudaGetSymbolAddress((void**)&oh_, g_oh);
    cudaGetSymbolAddress((void**)&ol_, g_ol);
    cudaGetSymbolAddress((void**)&gh_, g_gh);
    cudaGetSymbolAddress((void**)&gl_, g_gl);
    cudaGetSymbolAddress((void**)&wqh_, g_wqh); cudaGetSymbolAddress((void**)&wql_, g_wql);
    cudaGetSymbolAddress((void**)&wkh_, g_wkh); cudaGetSymbolAddress((void**)&wkl_, g_wkl);
    cudaGetSymbolAddress((void**)&wvh_, g_wvh); cudaGetSymbolAddress((void**)&wvl_, g_wvl);
    cudaGetSymbolAddress((void**)&woh_, g_woh); cudaGetSymbolAddress((void**)&wol_, g_wol);
    cudaGetSymbolAddress((void**)&w1h_, g_w1h); cudaGetSymbolAddress((void**)&w1l_, g_w1l);
    cudaGetSymbolAddress((void**)&w3h_, g_w3h); cudaGetSymbolAddress((void**)&w3l_, g_w3l);
    cudaGetSymbolAddress((void**)&w2h_, g_w2h); cudaGetSymbolAddress((void**)&w2l_, g_w2l);

    static int smem_set = 0;
    if (!smem_set) {
        cudaFuncSetAttribute(gemm_bf16x3_kernel,
                             cudaFuncAttributeMaxDynamicSharedMemorySize, SMEM_BYTES);
        smem_set = 1;
    }

    const int nDD = NL * D * D / 4, nDF = NL * D * HFF / 4;
    split_kernel<<<(nDD + 255) / 256, 256>>>(Wq, wqh_, wql_, nDD);
    split_kernel<<<(nDD + 255) / 256, 256>>>(Wk, wkh_, wkl_, nDD);
    split_kernel<<<(nDD + 255) / 256, 256>>>(Wv, wvh_, wvl_, nDD);
    split_kernel<<<(nDD + 255) / 256, 256>>>(Wo, woh_, wol_, nDD);
    split_kernel<<<(nDF + 255) / 256, 256>>>(W1, w1h_, w1l_, nDF);
    split_kernel<<<(nDF + 255) / 256, 256>>>(W3, w3h_, w3l_, nDF);
    split_kernel<<<(nDF + 255) / 256, 256>>>(W2, w2h_, w2l_, nDF);

    rope_table_kernel<<<(S * 32 + 255) / 256, 256>>>(cos_, sin_);
    embed_kernel<<<(S * D) / 256, 256>>>(tokens, tok_emb, h_);

    const dim3 gDD(D / GBN, S / GBM);     // (8, 16)
    const dim3 gDF(HFF / GBN, S / GBM);   // (22, 16)

    for (int l = 0; l < NL; l++) {
        size_t offDD = (size_t)l * D * D;
        size_t offDF = (size_t)l * D * HFF;

        rmsnorm_split_kernel<<<S, 256>>>(h_, anw + (size_t)l * D, xh_, xl_);

        gemm_bf16x3_kernel<<<gDD, 256, SMEM_BYTES>>>(xh_, xl_, wqh_ + offDD, wql_ + offDD, nullptr, q_, S, D, D);
        gemm_bf16x3_kernel<<<gDD, 256, SMEM_BYTES>>>(xh_, xl_, wkh_ + offDD, wkl_ + offDD, nullptr, k_, S, D, D);
        gemm_bf16x3_kernel<<<gDD, 256, SMEM_BYTES>>>(xh_, xl_, wvh_ + offDD, wvl_ + offDD, nullptr, v_, S, D, D);

        rope_kernel<<<(S * NH * 32 + 255) / 256, 256>>>(q_, cos_, sin_);
        rope_kernel<<<(S * NH * 32 + 255) / 256, 256>>>(k_, cos_, sin_);

        attn_kernel<<<dim3(S / 64, NH), 128>>>(q_, k_, v_, oh_, ol_);

        gemm_bf16x3_kernel<<<gDD, 256, SMEM_BYTES>>>(oh_, ol_, woh_ + offDD, wol_ + offDD, h_, h_, S, D, D);

        rmsnorm_split_kernel<<<S, 256>>>(h_, fnw + (size_t)l * D, xh_, xl_);

        gemm_bf16x3_kernel<<<gDF, 256, SMEM_BYTES>>>(xh_, xl_, w1h_ + offDF, w1l_ + offDF, nullptr, gg_, S, HFF, D);
        gemm_bf16x3_kernel<<<gDF, 256, SMEM_BYTES>>>(xh_, xl_, w3h_ + offDF, w3l_ + offDF, nullptr, uu_, S, HFF, D);
        swiglu_split_kernel<<<(S * HFF + 255) / 256, 256>>>(gg_, uu_, gh_, gl_, S * HFF);
        gemm_bf16x3_kernel<<<gDD, 256, SMEM_BYTES>>>(gh_, gl_, w2h_ + offDF, w2l_ + offDF, h_, h_, S, D, HFF);
    }

    rmsnorm_kernel<<<1, 256>>>(h_ + (size_t)(S - 1) * D, finw, xf_);
    logits_kernel<<<NV / 256, 256>>>(xf_, Wout, out);
}

// round 4
// speedup vs baseline: 2.9732x; 1.9846x over previous
#include <cuda_runtime.h>
#include <cuda_bf16.h>
#include <math.h>
#include <stdint.h>

// ---------------- Problem constants ----------------
#define S    2048
#define D    1024
#define NH   16
#define HD   64
#define HFF  2816
#define NV   32000
#define NL   4

typedef __nv_bfloat16 bf16;

// ---------------- Device scratch ----------------
__device__ float g_h[S * D];
__device__ float g_q[S * D];
__device__ float g_k[S * D];
__device__ float g_v[S * D];
__device__ float g_gg[S * HFF];
__device__ float g_uu[S * HFF];
__device__ float g_cos[S * 32];
__device__ float g_sin[S * 32];
__device__ float g_xf[D];

// split (hi/lo) bf16 buffers
__device__ __align__(16) bf16 g_xh[S * D],  g_xl[S * D];
__device__ __align__(16) bf16 g_oh[S * D],  g_ol[S * D];
__device__ __align__(16) bf16 g_gh[S * HFF], g_gl[S * HFF];
__device__ __align__(16) bf16 g_qh[S * D], g_ql[S * D];
__device__ __align__(16) bf16 g_kh[S * D], g_kl[S * D];
__device__ __align__(16) bf16 g_vh[S * D], g_vl[S * D];

__device__ __align__(16) bf16 g_wqh[NL * D * D], g_wql[NL * D * D];
__device__ __align__(16) bf16 g_wkh[NL * D * D], g_wkl[NL * D * D];
__device__ __align__(16) bf16 g_wvh[NL * D * D], g_wvl[NL * D * D];
__device__ __align__(16) bf16 g_woh[NL * D * D], g_wol[NL * D * D];
__device__ __align__(16) bf16 g_w1h[NL * D * HFF], g_w1l[NL * D * HFF];
__device__ __align__(16) bf16 g_w3h[NL * D * HFF], g_w3l[NL * D * HFF];
__device__ __align__(16) bf16 g_w2h[NL * HFF * D], g_w2l[NL * HFF * D];

// ---------------- small helpers ----------------
__device__ __forceinline__ void split1(float v, bf16& h, bf16& l) {
    h = __float2bfloat16(v);
    l = __float2bfloat16(v - __bfloat162float(h));
}

__device__ __forceinline__ void split2pack(float x, float y, unsigned& hp, unsigned& lp) {
    bf16 hx = __float2bfloat16(x), hy = __float2bfloat16(y);
    float lx = x - __bfloat162float(hx), ly = y - __bfloat162float(hy);
    bf16 lxb = __float2bfloat16(lx), lyb = __float2bfloat16(ly);
    hp = (unsigned)(*(unsigned short*)&hx) | ((unsigned)(*(unsigned short*)&hy) << 16);
    lp = (unsigned)(*(unsigned short*)&lxb) | ((unsigned)(*(unsigned short*)&lyb) << 16);
}

// ---------------- split conversion (weights) ----------------
__global__ void split_kernel(const float* __restrict__ in,
                             bf16* __restrict__ hi, bf16* __restrict__ lo, int n4) {
    int i = blockIdx.x * 256 + threadIdx.x;
    if (i >= n4) return;
    float4 v = ((const float4*)in)[i];
    unsigned h0, l0, h1, l1;
    split2pack(v.x, v.y, h0, l0);
    split2pack(v.z, v.w, h1, l1);
    ((uint2*)hi)[i] = make_uint2(h0, h1);
    ((uint2*)lo)[i] = make_uint2(l0, l1);
}

// ---------------- RoPE table ----------------
__global__ void rope_table_kernel(float* ct, float* st) {
    int idx = blockIdx.x * 256 + threadIdx.x;
    if (idx >= S * 32) return;
    int pos = idx >> 5;
    int i = idx & 31;
    float inv = powf(10000.0f, -((float)(2 * i) / (float)HD));
    float ang = (float)pos * inv;
    float s, c;
    sincosf(ang, &s, &c);
    ct[idx] = c;
    st[idx] = s;
}

// ---------------- Embedding gather ----------------
__global__ void embed_kernel(const int* __restrict__ tokens,
                             const float* __restrict__ emb,
                             float* __restrict__ h) {
    int idx = blockIdx.x * 256 + threadIdx.x;
    int s = idx >> 10;
    int d = idx & 1023;
    h[idx] = emb[(size_t)tokens[s] * D + d];
}

// ---------------- RMSNorm -> split bf16 hi/lo ----------------
__global__ void rmsnorm_split_kernel(const float* __restrict__ in,
                                     const float* __restrict__ w,
                                     bf16* __restrict__ oh, bf16* __restrict__ ol) {
    const float* r = in + (size_t)blockIdx.x * D;
    bf16* ph = oh + (size_t)blockIdx.x * D;
    bf16* pl = ol + (size_t)blockIdx.x * D;
    int t = threadIdx.x;
    float v[4];
    float ss = 0.f;
#pragma unroll
    for (int i = 0; i < 4; i++) { v[i] = r[t + i * 256]; ss += v[i] * v[i]; }
#pragma unroll
    for (int off = 16; off; off >>= 1) ss += __shfl_xor_sync(0xffffffffu, ss, off);
    __shared__ float red[8];
    if ((t & 31) == 0) red[t >> 5] = ss;
    __syncthreads();
    if (t < 8) {
        float x = red[t];
#pragma unroll
        for (int off = 4; off; off >>= 1) x += __shfl_xor_sync(0xffu, x, off);
        if (t == 0) red[0] = x;
    }
    __syncthreads();
    float scale = rsqrtf(red[0] * (1.0f / (float)D) + 1e-6f);
#pragma unroll
    for (int i = 0; i < 4; i++) {
        float rv = v[i] * scale * w[t + i * 256];
        bf16 h, l; split1(rv, h, l);
        ph[t + i * 256] = h;
        pl[t + i * 256] = l;
    }
}

// ---------------- plain fp32 RMSNorm (final row) ----------------
__global__ void rmsnorm_kernel(const float* __restrict__ in,
                               const float* __restrict__ w,
                               float* __restrict__ out) {
    const float* r = in;
    int t = threadIdx.x;
    float v[4];
    float ss = 0.f;
#pragma unroll
    for (int i = 0; i < 4; i++) { v[i] = r[t + i * 256]; ss += v[i] * v[i]; }
#pragma unroll
    for (int off = 16; off; off >>= 1) ss += __shfl_xor_sync(0xffffffffu, ss, off);
    __shared__ float red[8];
    if ((t & 31) == 0) red[t >> 5] = ss;
    __syncthreads();
    if (t < 8) {
        float x = red[t];
#pragma unroll
        for (int off = 4; off; off >>= 1) x += __shfl_xor_sync(0xffu, x, off);
        if (t == 0) red[0] = x;
    }
    __syncthreads();
    float scale = rsqrtf(red[0] * (1.0f / (float)D) + 1e-6f);
#pragma unroll
    for (int i = 0; i < 4; i++) out[t + i * 256] = v[i] * scale * w[t + i * 256];
}

// ---------------- fused RoPE + split for q,k,v ----------------
__global__ void qkv_rope_split_kernel(
    const float* __restrict__ q, const float* __restrict__ k, const float* __restrict__ v,
    const float* __restrict__ ct, const float* __restrict__ st,
    bf16* __restrict__ qh, bf16* __restrict__ ql,
    bf16* __restrict__ kh, bf16* __restrict__ kl,
    bf16* __restrict__ vh, bf16* __restrict__ vl) {
    int idx = blockIdx.x * 256 + threadIdx.x;          // S*D/2 pairs
    if (idx >= S * D / 2) return;
    int pos = idx >> 9;
    int rem = idx & 511;
    int i = rem & 31;
    int base = pos * D + (rem >> 5) * HD + 2 * i;
    float c = ct[pos * 32 + i];
    float s_ = st[pos * 32 + i];
    float q0 = q[base], q1 = q[base + 1];
    float k0 = k[base], k1 = k[base + 1];
    float v0 = v[base], v1 = v[base + 1];
    float qa = q0 * c - q1 * s_, qb = q0 * s_ + q1 * c;
    float ka = k0 * c - k1 * s_, kb = k0 * s_ + k1 * c;
    unsigned hp, lp;
    split2pack(qa, qb, hp, lp);
    *(unsigned*)(qh + base) = hp; *(unsigned*)(ql + base) = lp;
    split2pack(ka, kb, hp, lp);
    *(unsigned*)(kh + base) = hp; *(unsigned*)(kl + base) = lp;
    split2pack(v0, v1, hp, lp);
    *(unsigned*)(vh + base) = hp; *(unsigned*)(vl + base) = lp;
}

// ---------------- MMA helpers ----------------
#define LDSM4(r0, r1, r2, r3, addr)                                          \
    asm volatile("ldmatrix.sync.aligned.m8n8.x4.shared.b16 {%0,%1,%2,%3},[%4];" \
                 : "=r"(r0), "=r"(r1), "=r"(r2), "=r"(r3) : "r"(addr))
#define LDSM4T(r0, r1, r2, r3, addr)                                         \
    asm volatile("ldmatrix.sync.aligned.m8n8.x4.trans.shared.b16 {%0,%1,%2,%3},[%4];" \
                 : "=r"(r0), "=r"(r1), "=r"(r2), "=r"(r3) : "r"(addr))
#define CP_ASYNC16(saddr, gaddr)                                             \
    asm volatile("cp.async.cg.shared.global [%0],[%1],16;" :: "r"(saddr), "l"(gaddr))
#define CP_COMMIT() asm volatile("cp.async.commit_group;" ::: "memory")
#define CP_WAIT1()  asm volatile("cp.async.wait_group 1;" ::: "memory")

__device__ __forceinline__ void mma16816(float* c, const unsigned* a, const unsigned* b) {
    asm volatile(
        "mma.sync.aligned.m16n8k16.row.col.f32.bf16.bf16.f32 "
        "{%0,%1,%2,%3},{%4,%5,%6,%7},{%8,%9},{%0,%1,%2,%3};"
        : "+f"(c[0]), "+f"(c[1]), "+f"(c[2]), "+f"(c[3])
        : "r"(a[0]), "r"(a[1]), "r"(a[2]), "r"(a[3]), "r"(b[0]), "r"(b[1]));
}

// ---------------- Tensor-core flash attention (bf16 split) ----------------
// grid (S/64, NH), 128 threads (4 warps x 16 q-rows each).
#define AP 72   // smem row pitch in halfs (144B)

__global__ __launch_bounds__(128) void attn_mma_kernel(
    const bf16* __restrict__ Qh, const bf16* __restrict__ Ql,
    const bf16* __restrict__ Kh, const bf16* __restrict__ Kl,
    const bf16* __restrict__ Vh, const bf16* __restrict__ Vl,
    bf16* __restrict__ Oh, bf16* __restrict__ Ol) {
    __shared__ __align__(16) bf16 sK[2][64 * AP];
    __shared__ __align__(16) bf16 sV[2][64 * AP];

    const int qt   = blockIdx.x;
    const int head = blockIdx.y;
    const int tid  = threadIdx.x;
    const int warp = tid >> 5;
    const int lane = tid & 31;
    const int grp  = lane >> 3;
    const int rin  = lane & 7;
    const int wq   = warp * 16;

    // ---- stage Q tile into sK, load fragments ----
    {
        const bf16* qsrc[2] = {Qh, Ql};
#pragma unroll
        for (int c = tid; c < 1024; c += 128) {
            int buf = c >> 9, rem = c & 511;
            int row = rem >> 3, col8 = rem & 7;
            *(uint4*)&sK[buf][row * AP + col8 * 8] =
                *(const uint4*)(qsrc[buf] + (size_t)(qt * 64 + row) * D + head * HD + col8 * 8);
        }
    }
    __syncthreads();

    unsigned aQ[2][4][4];
    {
        uint32_t b0 = (uint32_t)__cvta_generic_to_shared(&sK[0][0]);
        uint32_t b1 = (uint32_t)__cvta_generic_to_shared(&sK[1][0]);
        uint32_t laneOff = (uint32_t)(((wq + ((grp & 1) << 3) + rin) * AP + ((grp >> 1) << 3)) << 1);
#pragma unroll
        for (int kc = 0; kc < 4; kc++) {
            LDSM4(aQ[0][kc][0], aQ[0][kc][1], aQ[0][kc][2], aQ[0][kc][3], b0 + laneOff + kc * 32);
            LDSM4(aQ[1][kc][0], aQ[1][kc][1], aQ[1][kc][2], aQ[1][kc][3], b1 + laneOff + kc * 32);
        }
    }

    float o[8][4];
#pragma unroll
    for (int nt = 0; nt < 8; nt++)
#pragma unroll
        for (int j = 0; j < 4; j++) o[nt][j] = 0.f;
    float m0 = -1e30f, m1 = -1e30f, l0 = 0.f, l1 = 0.f;
    const float scale = 0.125f;

    const uint32_t sK0 = (uint32_t)__cvta_generic_to_shared(&sK[0][0]);
    const uint32_t sK1 = (uint32_t)__cvta_generic_to_shared(&sK[1][0]);
    const uint32_t sV0 = (uint32_t)__cvta_generic_to_shared(&sV[0][0]);
    const uint32_t sV1 = (uint32_t)__cvta_generic_to_shared(&sV[1][0]);

    const int r0g = qt * 64 + wq + (lane >> 2);
    const int r1g = r0g + 8;

    for (int kt = 0; kt <= qt; kt++) {
        __syncthreads();
        {
            const bf16* src[4] = {Kh, Kl, Vh, Vl};
            bf16* dst[4] = {sK[0], sK[1], sV[0], sV[1]};
#pragma unroll
            for (int c = tid; c < 2048; c += 128) {
                int which = c >> 9, rem = c & 511;
                int row = rem >> 3, col8 = rem & 7;
                *(uint4*)&dst[which][row * AP + col8 * 8] =
                    *(const uint4*)(src[which] + (size_t)(kt * 64 + row) * D + head * HD + col8 * 8);
            }
        }
        __syncthreads();

        // ---- scores S = Q K^T (3 bf16 passes) ----
        float s[8][4];
#pragma unroll
        for (int nt = 0; nt < 8; nt++)
#pragma unroll
            for (int j = 0; j < 4; j++) s[nt][j] = 0.f;

#pragma unroll
        for (int kc = 0; kc < 4; kc++) {
            unsigned bh[8][2], bl[8][2];
#pragma unroll
            for (int np = 0; np < 4; np++) {
                uint32_t off = (uint32_t)(((np * 16 + ((grp >> 1) << 3) + rin) * AP
                                           + kc * 16 + ((grp & 1) << 3)) << 1);
                LDSM4(bh[2 * np][0], bh[2 * np][1], bh[2 * np + 1][0], bh[2 * np + 1][1], sK0 + off);
                LDSM4(bl[2 * np][0], bl[2 * np][1], bl[2 * np + 1][0], bl[2 * np + 1][1], sK1 + off);
            }
#pragma unroll
            for (int nt = 0; nt < 8; nt++) {
                mma16816(s[nt], aQ[0][kc], bh[nt]);
                mma16816(s[nt], aQ[0][kc], bl[nt]);
                mma16816(s[nt], aQ[1][kc], bh[nt]);
            }
        }

        // ---- scale + causal mask ----
        const bool diag = (kt == qt);
#pragma unroll
        for (int nt = 0; nt < 8; nt++) {
            int c0g = kt * 64 + nt * 8 + (lane & 3) * 2;
            s[nt][0] *= scale; s[nt][1] *= scale;
            s[nt][2] *= scale; s[nt][3] *= scale;
            if (diag) {
                if (c0g     > r0g) s[nt][0] = -1e30f;
                if (c0g + 1 > r0g) s[nt][1] = -1e30f;
                if (c0g     > r1g) s[nt][2] = -1e30f;
                if (c0g + 1 > r1g) s[nt][3] = -1e30f;
            }
        }

        // ---- online softmax ----
        float mx0 = -1e30f, mx1 = -1e30f;
#pragma unroll
        for (int nt = 0; nt < 8; nt++) {
            mx0 = fmaxf(mx0, fmaxf(s[nt][0], s[nt][1]));
            mx1 = fmaxf(mx1, fmaxf(s[nt][2], s[nt][3]));
        }
        mx0 = fmaxf(mx0, __shfl_xor_sync(0xffffffffu, mx0, 1));
        mx0 = fmaxf(mx0, __shfl_xor_sync(0xffffffffu, mx0, 2));
        mx1 = fmaxf(mx1, __shfl_xor_sync(0xffffffffu, mx1, 1));
        mx1 = fmaxf(mx1, __shfl_xor_sync(0xffffffffu, mx1, 2));
        float mn0 = fmaxf(m0, mx0), mn1 = fmaxf(m1, mx1);
        float cr0 = __expf(m0 - mn0), cr1 = __expf(m1 - mn1);
        m0 = mn0; m1 = mn1;
        float rs0 = 0.f, rs1 = 0.f;
#pragma unroll
        for (int nt = 0; nt < 8; nt++) {
            s[nt][0] = __expf(s[nt][0] - mn0); rs0 += s[nt][0];
            s[nt][1] = __expf(s[nt][1] - mn0); rs0 += s[nt][1];
            s[nt][2] = __expf(s[nt][2] - mn1); rs1 += s[nt][2];
            s[nt][3] = __expf(s[nt][3] - mn1); rs1 += s[nt][3];
        }
        l0 = l0 * cr0 + rs0;
        l1 = l1 * cr1 + rs1;
#pragma unroll
        for (int nt = 0; nt < 8; nt++) {
            o[nt][0] *= cr0; o[nt][1] *= cr0;
            o[nt][2] *= cr1; o[nt][3] *= cr1;
        }

        // ---- O += P V (3 bf16 passes) ----
#pragma unroll
        for (int kc = 0; kc < 4; kc++) {
            int t0 = 2 * kc, t1 = 2 * kc + 1;
            unsigned ah[4], al[4];
            split2pack(s[t0][0], s[t0][1], ah[0], al[0]);
            split2pack(s[t0][2], s[t0][3], ah[1], al[1]);
            split2pack(s[t1][0], s[t1][1], ah[2], al[2]);
            split2pack(s[t1][2], s[t1][3], ah[3], al[3]);

            unsigned bvh[8][2], bvl[8][2];
#pragma unroll
            for (int np = 0; np < 4; np++) {
                uint32_t off = (uint32_t)(((kc * 16 + ((grp & 1) << 3) + rin) * AP
                                           + np * 16 + ((grp >> 1) << 3)) << 1);
                LDSM4T(bvh[2 * np][0], bvh[2 * np][1], bvh[2 * np + 1][0], bvh[2 * np + 1][1], sV0 + off);
                LDSM4T(bvl[2 * np][0], bvl[2 * np][1], bvl[2 * np + 1][0], bvl[2 * np + 1][1], sV1 + off);
            }
#pragma unroll
            for (int nt = 0; nt < 8; nt++) {
                mma16816(o[nt], ah, bvh[nt]);
                mma16816(o[nt], ah, bvl[nt]);
                mma16816(o[nt], al, bvh[nt]);
            }
        }
    }

    // ---- epilogue ----
    l0 += __shfl_xor_sync(0xffffffffu, l0, 1);
    l0 += __shfl_xor_sync(0xffffffffu, l0, 2);
    l1 += __shfl_xor_sync(0xffffffffu, l1, 1);
    l1 += __shfl_xor_sync(0xffffffffu, l1, 2);
    float inv0 = 1.f / l0, inv1 = 1.f / l1;
#pragma unroll
    for (int nt = 0; nt < 8; nt++) {
        int col = head * HD + nt * 8 + (lane & 3) * 2;
        unsigned hp, lp;
        split2pack(o[nt][0] * inv0, o[nt][1] * inv0, hp, lp);
        *(unsigned*)(Oh + (size_t)r0g * D + col) = hp;
        *(unsigned*)(Ol + (size_t)r0g * D + col) = lp;
        split2pack(o[nt][2] * inv1, o[nt][3] * inv1, hp, lp);
        *(unsigned*)(Oh + (size_t)r1g * D + col) = hp;
        *(unsigned*)(Ol + (size_t)r1g * D + col) = lp;
    }
}

// ---------------- bf16x3 tensor-core GEMM, cp.async 3-stage pipeline ----------------
#define GBM 128
#define GBN 128
#define GBK 32
#define NSTAGE 3
#define A_BUF_BYTES 10240
#define B_BUF_BYTES 8704
#define A_STAGE_BYTES 20480
#define STAGE_BYTES 37888
#define SMEM_BYTES (NSTAGE * STAGE_BYTES)

extern __shared__ char gsmem[];

__global__ __launch_bounds__(256) void gemm_bf16x3_kernel(
    const bf16* __restrict__ Ah, const bf16* __restrict__ Al,
    const bf16* __restrict__ Bh, const bf16* __restrict__ Bl,
    const float* __restrict__ RES, float* __restrict__ C,
    int M, int N, int K) {
    const int tid  = threadIdx.x;
    const int bm   = blockIdx.y * GBM;
    const int bn   = blockIdx.x * GBN;
    const int warp = tid >> 5;
    const int lane = tid & 31;
    const int wm   = (warp >> 2) * 64;
    const int wn   = (warp & 3) * 32;
    const int grp  = lane >> 3;
    const int rin  = lane & 7;

    const uint32_t sBase = (uint32_t)__cvta_generic_to_shared(gsmem);
    const uint32_t laneA = (uint32_t)((((grp & 1) << 3) + rin) * 80 + ((grp >> 1) << 4));
    const uint32_t laneB = (uint32_t)((((grp & 1) << 3) + rin) * 272 + (((grp >> 1) << 3) + wn) * 2);

    float acc[4][4][4];
#pragma unroll
    for (int mi = 0; mi < 4; mi++)
#pragma unroll
        for (int ni = 0; ni < 4; ni++)
#pragma unroll
            for (int j = 0; j < 4; j++) acc[mi][ni][j] = 0.f;

    const int KT = K / GBK;

    auto issue = [&](int kt, int stage) {
        const uint32_t stOff = sBase + stage * STAGE_BYTES;
        const int kOff = kt * GBK;
#pragma unroll
        for (int i = 0; i < 4; i++) {
            int c = tid + 256 * i;
            int buf = c >> 9, rem = c & 511;
            int m = rem >> 2, kq = rem & 3;
            const bf16* g = (buf ? Al : Ah) + (size_t)(bm + m) * K + kOff + kq * 8;
            uint32_t sa = stOff + buf * A_BUF_BYTES + m * 80 + kq * 16;
            CP_ASYNC16(sa, g);
        }
#pragma unroll
        for (int i = 0; i < 4; i++) {
            int c = tid + 256 * i;
            int buf = c >> 9, rem = c & 511;
            int kk = rem >> 4, nq = rem & 15;
            const bf16* g = (buf ? Bl : Bh) + (size_t)(kOff + kk) * N + bn + nq * 8;
            uint32_t sa = stOff + A_STAGE_BYTES + buf * B_BUF_BYTES + kk * 272 + nq * 16;
            CP_ASYNC16(sa, g);
        }
    };

    issue(0, 0); CP_COMMIT();
    issue(1, 1); CP_COMMIT();

    for (int kt = 0; kt < KT; kt++) {
        CP_WAIT1();
        __syncthreads();
        if (kt + 2 < KT) issue(kt + 2, (kt + 2) % NSTAGE);
        CP_COMMIT();

        const uint32_t stOff = sBase + (kt % NSTAGE) * STAGE_BYTES;
#pragma unroll
        for (int ks = 0; ks < 2; ks++) {
            unsigned a[2][4][4];
            unsigned b[2][4][2];
#pragma unroll
            for (int buf = 0; buf < 2; buf++) {
                uint32_t aS = stOff + buf * A_BUF_BYTES + laneA + ks * 32;
#pragma unroll
                for (int mt = 0; mt < 4; mt++) {
                    uint32_t addr = aS + (wm + mt * 16) * 80;
                    LDSM4(a[buf][mt][0], a[buf][mt][1], a[buf][mt][2], a[buf][mt][3], addr);
                }
                uint32_t bS = stOff + A_STAGE_BYTES + buf * B_BUF_BYTES + laneB + ks * 4352;
#pragma unroll
                for (int nj = 0; nj < 2; nj++) {
                    uint32_t addr = bS + nj * 32;
                    LDSM4T(b[buf][2 * nj][0], b[buf][2 * nj][1],
                           b[buf][2 * nj + 1][0], b[buf][2 * nj + 1][1], addr);
                }
            }
#pragma unroll
            for (int mt = 0; mt < 4; mt++)
#pragma unroll
                for (int nt = 0; nt < 4; nt++) {
                    mma16816(acc[mt][nt], a[0][mt], b[0][nt]);
                    mma16816(acc[mt][nt], a[0][mt], b[1][nt]);
                    mma16816(acc[mt][nt], a[1][mt], b[0][nt]);
                }
        }
        __syncthreads();
    }

    int r0 = bm + wm + (lane >> 2);
    int c0 = bn + wn + (lane & 3) * 2;
#pragma unroll
    for (int mt = 0; mt < 4; mt++)
#pragma unroll
        for (int nt = 0; nt < 4; nt++) {
            int row = r0 + mt * 16;
            int col = c0 + nt * 8;
            float2 v0 = make_float2(acc[mt][nt][0], acc[mt][nt][1]);
            float2 v1 = make_float2(acc[mt][nt][2], acc[mt][nt][3]);
            if (RES) {
                float2 a0 = *(const float2*)(RES + (size_t)row * N + col);
                float2 a1 = *(const float2*)(RES + (size_t)(row + 8) * N + col);
                v0.x += a0.x; v0.y += a0.y;
                v1.x += a1.x; v1.y += a1.y;
            }
            *(float2*)(C + (size_t)row * N + col) = v0;
            *(float2*)(C + (size_t)(row + 8) * N + col) = v1;
        }
}

// ---------------- SwiGLU -> split hi/lo ----------------
__global__ void swiglu_split_kernel(const float* __restrict__ g,
                                    const float* __restrict__ u,
                                    bf16* __restrict__ oh, bf16* __restrict__ ol, int n) {
    int idx = blockIdx.x * 256 + threadIdx.x;
    if (idx >= n) return;
    float z = g[idx];
    float sig = 1.0f / (1.0f + __expf(-z));
    float r = z * sig * u[idx];
    bf16 h, l; split1(r, h, l);
    oh[idx] = h;
    ol[idx] = l;
}

// ---------------- Logits ----------------
__global__ void logits_kernel(const float* __restrict__ xf,
                              const float* __restrict__ Wout,
                              float* __restrict__ out) {
    __shared__ float xs[D];
    for (int i = threadIdx.x; i < D; i += 256) xs[i] = xf[i];
    __syncthreads();
    int v = blockIdx.x * 256 + threadIdx.x;
    float acc = 0.f;
#pragma unroll 8
    for (int d = 0; d < D; d++) acc += xs[d] * Wout[(size_t)d * NV + v];
    out[v] = acc;
}

// ---------------- Host launch ----------------
extern "C" void kernel_launch(void* const* d_in, const int* in_sizes, int n_in,
                              void* d_out, int out_size) {
    int bi = 1;
    if (n_in >= 2 && in_sizes[1] == 1) bi = 2;
    const int*   tokens  = (const int*)d_in[0];
    const float* tok_emb = (const float*)d_in[bi + 0];
    const float* Wq      = (const float*)d_in[bi + 1];
    const float* Wk      = (const float*)d_in[bi + 2];
    const float* Wv      = (const float*)d_in[bi + 3];
    const float* Wo      = (const float*)d_in[bi + 4];
    const float* W1      = (const float*)d_in[bi + 5];
    const float* W2      = (const float*)d_in[bi + 6];
    const float* W3      = (const float*)d_in[bi + 7];
    const float* anw     = (const float*)d_in[bi + 8];
    const float* fnw     = (const float*)d_in[bi + 9];
    const float* finw    = (const float*)d_in[bi + 10];
    const float* Wout    = (const float*)d_in[bi + 11];
    float* out = (float*)d_out;

    float *h_, *q_, *k_, *v_, *gg_, *uu_, *cos_, *sin_, *xf_;
    bf16 *xh_, *xl_, *oh_, *ol_, *gh_, *gl_;
    bf16 *qh_, *ql_, *kh_, *kl_, *vh_, *vl_;
    bf16 *wqh_, *wql_, *wkh_, *wkl_, *wvh_, *wvl_, *woh_, *wol_;
    bf16 *w1h_, *w1l_, *w3h_, *w3l_, *w2h_, *w2l_;

    cudaGetSymbolAddress((void**)&h_,  g_h);
    cudaGetSymbolAddress((void**)&q_,  g_q);
    cudaGetSymbolAddress((void**)&k_,  g_k);
    cudaGetSymbolAddress((void**)&v_,  g_v);
    cudaGetSymbolAddress((void**)&gg_, g_gg);
    cudaGetSymbolAddress((void**)&uu_, g_uu);
    cudaGetSymbolAddress((void**)&cos_, g_cos);
    cudaGetSymbolAddress((void**)&sin_, g_sin);
    cudaGetSymbolAddress((void**)&xf_, g_xf);
    cudaGetSymbolAddress((void**)&xh_, g_xh);
    cudaGetSymbolAddress((void**)&xl_, g_xl);
    cudaGetSymbolAddress((void**)&oh_, g_oh);
    cudaGetSymbolAddress((void**)&ol_, g_ol);
    cudaGetSymbolAddress((void**)&gh_, g_gh);
    cudaGetSymbolAddress((void**)&gl_, g_gl);
    cudaGetSymbolAddress((void**)&qh_, g_qh); cudaGetSymbolAddress((void**)&ql_, g_ql);
    cudaGetSymbolAddress((void**)&kh_, g_kh); cudaGetSymbolAddress((void**)&kl_, g_kl);
    cudaGetSymbolAddress((void**)&vh_, g_vh); cudaGetSymbolAddress((void**)&vl_, g_vl);
    cudaGetSymbolAddress((void**)&wqh_, g_wqh); cudaGetSymbolAddress((void**)&wql_, g_wql);
    cudaGetSymbolAddress((void**)&wkh_, g_wkh); cudaGetSymbolAddress((void**)&wkl_, g_wkl);
    cudaGetSymbolAddress((void**)&wvh_, g_wvh); cudaGetSymbolAddress((void**)&wvl_, g_wvl);
    cudaGetSymbolAddress((void**)&woh_, g_woh); cudaGetSymbolAddress((void**)&wol_, g_wol);
    cudaGetSymbolAddress((void**)&w1h_, g_w1h); cudaGetSymbolAddress((void**)&w1l_, g_w1l);
    cudaGetSymbolAddress((void**)&w3h_, g_w3h); cudaGetSymbolAddress((void**)&w3l_, g_w3l);
    cudaGetSymbolAddress((void**)&w2h_, g_w2h); cudaGetSymbolAddress((void**)&w2l_, g_w2l);

    static int smem_set = 0;
    if (!smem_set) {
        cudaFuncSetAttribute(gemm_bf16x3_kernel,
                             cudaFuncAttributeMaxDynamicSharedMemorySize, SMEM_BYTES);
        smem_set = 1;
    }

    const int nDD = NL * D * D / 4, nDF = NL * D * HFF / 4;
    split_kernel<<<(nDD + 255) / 256, 256>>>(Wq, wqh_, wql_, nDD);
    split_kernel<<<(nDD + 255) / 256, 256>>>(Wk, wkh_, wkl_, nDD);
    split_kernel<<<(nDD + 255) / 256, 256>>>(Wv, wvh_, wvl_, nDD);
    split_kernel<<<(nDD + 255) / 256, 256>>>(Wo, woh_, wol_, nDD);
    split_kernel<<<(nDF + 255) / 256, 256>>>(W1, w1h_, w1l_, nDF);
    split_kernel<<<(nDF + 255) / 256, 256>>>(W3, w3h_, w3l_, nDF);
    split_kernel<<<(nDF + 255) / 256, 256>>>(W2, w2h_, w2l_, nDF);

    rope_table_kernel<<<(S * 32 + 255) / 256, 256>>>(cos_, sin_);
    embed_kernel<<<(S * D) / 256, 256>>>(tokens, tok_emb, h_);

    const dim3 gDD(D / GBN, S / GBM);     // (8, 16)
    const dim3 gDF(HFF / GBN, S / GBM);   // (22, 16)

    for (int l = 0; l < NL; l++) {
        size_t offDD = (size_t)l * D * D;
        size_t offDF = (size_t)l * D * HFF;

        rmsnorm_split_kernel<<<S, 256>>>(h_, anw + (size_t)l * D, xh_, xl_);

        gemm_bf16x3_kernel<<<gDD, 256, SMEM_BYTES>>>(xh_, xl_, wqh_ + offDD, wql_ + offDD, nullptr, q_, S, D, D);
        gemm_bf16x3_kernel<<<gDD, 256, SMEM_BYTES>>>(xh_, xl_, wkh_ + offDD, wkl_ + offDD, nullptr, k_, S, D, D);
        gemm_bf16x3_kernel<<<gDD, 256, SMEM_BYTES>>>(xh_, xl_, wvh_ + offDD, wvl_ + offDD, nullptr, v_, S, D, D);

        qkv_rope_split_kernel<<<(S * D / 2 + 255) / 256, 256>>>(
            q_, k_, v_, cos_, sin_, qh_, ql_, kh_, kl_, vh_, vl_);

        attn_mma_kernel<<<dim3(S / 64, NH), 128>>>(qh_, ql_, kh_, kl_, vh_, vl_, oh_, ol_);

        gemm_bf16x3_kernel<<<gDD, 256, SMEM_BYTES>>>(oh_, ol_, woh_ + offDD, wol_ + offDD, h_, h_, S, D, D);

        rmsnorm_split_kernel<<<S, 256>>>(h_, fnw + (size_t)l * D, xh_, xl_);

        gemm_bf16x3_kernel<<<gDF, 256, SMEM_BYTES>>>(xh_, xl_, w1h_ + offDF, w1l_ + offDF, nullptr, gg_, S, HFF, D);
        gemm_bf16x3_kernel<<<gDF, 256, SMEM_BYTES>>>(xh_, xl_, w3h_ + offDF, w3l_ + offDF, nullptr, uu_, S, HFF, D);
        swiglu_split_kernel<<<(S * HFF + 255) / 256, 256>>>(gg_, uu_, gh_, gl_, S * HFF);
        gemm_bf16x3_kernel<<<gDD, 256, SMEM_BYTES>>>(gh_, gl_, w2h_ + offDF, w2l_ + offDF, h_, h_, S, D, HFF);
    }

    rmsnorm_kernel<<<1, 256>>>(h_ + (size_t)(S - 1) * D, finw, xf_);
    logits_kernel<<<NV / 256, 256>>>(xf_, Wout, out);
}

// round 6
// speedup vs baseline: 3.1756x; 1.0681x over previous
#include <cuda_runtime.h>
#include <cuda_bf16.h>
#include <math.h>
#include <stdint.h>

// ---------------- Problem constants ----------------
#define S    2048
#define D    1024
#define NH   16
#define HD   64
#define HFF  2816
#define NV   32000
#define NL   4

typedef __nv_bfloat16 bf16;

// ---------------- Device scratch ----------------
__device__ float g_h[S * D];
__device__ float g_cos[S * 32];
__device__ float g_sin[S * 32];
__device__ float g_xf[D];

// split (hi/lo) bf16 activation buffers
__device__ __align__(16) bf16 g_xh[S * D],  g_xl[S * D];
__device__ __align__(16) bf16 g_oh[S * D],  g_ol[S * D];
__device__ __align__(16) bf16 g_gh[S * HFF], g_gl[S * HFF];
__device__ __align__(16) bf16 g_qh[S * D], g_ql[S * D];
__device__ __align__(16) bf16 g_kh[S * D], g_kl[S * D];
__device__ __align__(16) bf16 g_vh[S * D], g_vl[S * D];

// packed split weights (B stays [K, N] row-major)
__device__ __align__(16) bf16 g_wqkvh[NL * D * 3 * D], g_wqkvl[NL * D * 3 * D];  // [K=1024, N=3072]
__device__ __align__(16) bf16 g_w13h[NL * D * 2 * HFF], g_w13l[NL * D * 2 * HFF]; // [K=1024, N=5632] interleaved
__device__ __align__(16) bf16 g_woh[NL * D * D], g_wol[NL * D * D];               // [K=1024, N=1024]
__device__ __align__(16) bf16 g_w2h[NL * HFF * D], g_w2l[NL * HFF * D];           // [K=2816, N=1024]

// ---------------- small helpers ----------------
__device__ __forceinline__ void split1(float v, bf16& h, bf16& l) {
    h = __float2bfloat16(v);
    l = __float2bfloat16(v - __bfloat162float(h));
}
__device__ __forceinline__ void split2pack(float x, float y, unsigned& hp, unsigned& lp) {
    bf16 hx = __float2bfloat16(x), hy = __float2bfloat16(y);
    float lx = x - __bfloat162float(hx), ly = y - __bfloat162float(hy);
    bf16 lxb = __float2bfloat16(lx), lyb = __float2bfloat16(ly);
    hp = (unsigned)(*(unsigned short*)&hx) | ((unsigned)(*(unsigned short*)&hy) << 16);
    lp = (unsigned)(*(unsigned short*)&lxb) | ((unsigned)(*(unsigned short*)&lyb) << 16);
}

// ---------------- pack + split weights ----------------
// in [K,N] fp32 -> out bf16 hi/lo at column (colMul*n + colOff), row stride outStride.
__global__ void pack_split_kernel(const float* __restrict__ in,
                                  bf16* __restrict__ oh, bf16* __restrict__ ol,
                                  int K, int N, int colMul, int colOff, int outStride,
                                  size_t inLS, size_t outLS) {
    int l = blockIdx.z;
    in += l * inLS; oh += l * outLS; ol += l * outLS;
    int idx = blockIdx.x * 256 + threadIdx.x;     // over K*N/2
    if (idx >= K * (N / 2)) return;
    int k = idx / (N / 2);
    int n = (idx % (N / 2)) * 2;
    float2 v = *(const float2*)(in + (size_t)k * N + n);
    if (colMul == 1) {
        unsigned hp, lp; split2pack(v.x, v.y, hp, lp);
        size_t o = (size_t)k * outStride + colOff + n;
        *(unsigned*)(oh + o) = hp;
        *(unsigned*)(ol + o) = lp;
    } else {
        bf16 h, lo;
        size_t o = (size_t)k * outStride + colOff + 2 * n;
        split1(v.x, h, lo); oh[o] = h; ol[o] = lo;
        split1(v.y, h, lo); oh[o + 2] = h; ol[o + 2] = lo;
    }
}

// ---------------- RoPE table ----------------
__global__ void rope_table_kernel(float* ct, float* st) {
    int idx = blockIdx.x * 256 + threadIdx.x;
    if (idx >= S * 32) return;
    int pos = idx >> 5;
    int i = idx & 31;
    float inv = powf(10000.0f, -((float)(2 * i) / (float)HD));
    float ang = (float)pos * inv;
    float s, c;
    sincosf(ang, &s, &c);
    ct[idx] = c;
    st[idx] = s;
}

// ---------------- Embedding gather ----------------
__global__ void embed_kernel(const int* __restrict__ tokens,
                             const float* __restrict__ emb,
                             float* __restrict__ h) {
    int idx = blockIdx.x * 256 + threadIdx.x;
    int s = idx >> 10;
    int d = idx & 1023;
    h[idx] = emb[(size_t)tokens[s] * D + d];
}

// ---------------- RMSNorm -> split bf16 hi/lo ----------------
__global__ void rmsnorm_split_kernel(const float* __restrict__ in,
                                     const float* __restrict__ w,
                                     bf16* __restrict__ oh, bf16* __restrict__ ol) {
    const float* r = in + (size_t)blockIdx.x * D;
    bf16* ph = oh + (size_t)blockIdx.x * D;
    bf16* pl = ol + (size_t)blockIdx.x * D;
    int t = threadIdx.x;
    float v[4];
    float ss = 0.f;
#pragma unroll
    for (int i = 0; i < 4; i++) { v[i] = r[t + i * 256]; ss += v[i] * v[i]; }
#pragma unroll
    for (int off = 16; off; off >>= 1) ss += __shfl_xor_sync(0xffffffffu, ss, off);
    __shared__ float red[8];
    if ((t & 31) == 0) red[t >> 5] = ss;
    __syncthreads();
    if (t < 8) {
        float x = red[t];
#pragma unroll
        for (int off = 4; off; off >>= 1) x += __shfl_xor_sync(0xffu, x, off);
        if (t == 0) red[0] = x;
    }
    __syncthreads();
    float scale = rsqrtf(red[0] * (1.0f / (float)D) + 1e-6f);
#pragma unroll
    for (int i = 0; i < 4; i++) {
        float rv = v[i] * scale * w[t + i * 256];
        bf16 h, l; split1(rv, h, l);
        ph[t + i * 256] = h;
        pl[t + i * 256] = l;
    }
}

// ---------------- plain fp32 RMSNorm (final row) ----------------
__global__ void rmsnorm_kernel(const float* __restrict__ in,
                               const float* __restrict__ w,
                               float* __restrict__ out) {
    const float* r = in;
    int t = threadIdx.x;
    float v[4];
    float ss = 0.f;
#pragma unroll
    for (int i = 0; i < 4; i++) { v[i] = r[t + i * 256]; ss += v[i] * v[i]; }
#pragma unroll
    for (int off = 16; off; off >>= 1) ss += __shfl_xor_sync(0xffffffffu, ss, off);
    __shared__ float red[8];
    if ((t & 31) == 0) red[t >> 5] = ss;
    __syncthreads();
    if (t < 8) {
        float x = red[t];
#pragma unroll
        for (int off = 4; off; off >>= 1) x += __shfl_xor_sync(0xffu, x, off);
        if (t == 0) red[0] = x;
    }
    __syncthreads();
    float scale = rsqrtf(red[0] * (1.0f / (float)D) + 1e-6f);
#pragma unroll
    for (int i = 0; i < 4; i++) out[t + i * 256] = v[i] * scale * w[t + i * 256];
}

// ---------------- MMA helpers ----------------
#define LDSM4(r0, r1, r2, r3, addr)                                          \
    asm volatile("ldmatrix.sync.aligned.m8n8.x4.shared.b16 {%0,%1,%2,%3},[%4];" \
                 : "=r"(r0), "=r"(r1), "=r"(r2), "=r"(r3) : "r"(addr))
#define LDSM4T(r0, r1, r2, r3, addr)                                         \
    asm volatile("ldmatrix.sync.aligned.m8n8.x4.trans.shared.b16 {%0,%1,%2,%3},[%4];" \
                 : "=r"(r0), "=r"(r1), "=r"(r2), "=r"(r3) : "r"(addr))
#define CP_ASYNC16(saddr, gaddr)                                             \
    asm volatile("cp.async.cg.shared.global [%0],[%1],16;" :: "r"(saddr), "l"(gaddr))
#define CP_COMMIT() asm volatile("cp.async.commit_group;" ::: "memory")
#define CP_WAIT1()  asm volatile("cp.async.wait_group 1;" ::: "memory")

__device__ __forceinline__ void mma16816(float* c, const unsigned* a, const unsigned* b) {
    asm volatile(
        "mma.sync.aligned.m16n8k16.row.col.f32.bf16.bf16.f32 "
        "{%0,%1,%2,%3},{%4,%5,%6,%7},{%8,%9},{%0,%1,%2,%3};"
        : "+f"(c[0]), "+f"(c[1]), "+f"(c[2]), "+f"(c[3])
        : "r"(a[0]), "r"(a[1]), "r"(a[2]), "r"(a[3]), "r"(b[0]), "r"(b[1]));
}

// ---------------- bf16x3 tensor-core GEMM, cp.async 3-stage, fused epilogues ----------------
// MODE 0: C = acc (+RES), fp32.
// MODE 1: QKV fused: rope on segs 0,1; split -> (qh,ql),(kh,kl),(vh,vl). N=3072.
// MODE 2: W13 fused: cols (2j,2j+1)=(g,u); silu(g)*u split -> (gh,gl). N=5632.
#define GBM 128
#define GBN 128
#define GBK 32
#define NSTAGE 3
#define A_BUF_BYTES 10240
#define B_BUF_BYTES 8704
#define A_STAGE_BYTES 20480
#define STAGE_BYTES 37888
#define SMEM_BYTES (NSTAGE * STAGE_BYTES)

extern __shared__ char gsmem[];

template <int MODE>
__global__ __launch_bounds__(256) void gemm_bf16x3_kernel(
    const bf16* __restrict__ Ah, const bf16* __restrict__ Al,
    const bf16* __restrict__ Bh, const bf16* __restrict__ Bl,
    const float* __restrict__ RES, float* __restrict__ C,
    bf16* __restrict__ O1h, bf16* __restrict__ O1l,
    bf16* __restrict__ O2h, bf16* __restrict__ O2l,
    bf16* __restrict__ O3h, bf16* __restrict__ O3l,
    const float* __restrict__ ct, const float* __restrict__ st,
    int M, int N, int K) {
    const int tid  = threadIdx.x;
    const int bm   = blockIdx.y * GBM;
    const int bn   = blockIdx.x * GBN;
    const int warp = tid >> 5;
    const int lane = tid & 31;
    const int wm   = (warp >> 2) * 64;
    const int wn   = (warp & 3) * 32;
    const int grp  = lane >> 3;
    const int rin  = lane & 7;

    const uint32_t sBase = (uint32_t)__cvta_generic_to_shared(gsmem);
    const uint32_t laneA = (uint32_t)((((grp & 1) << 3) + rin) * 80 + ((grp >> 1) << 4));
    const uint32_t laneB = (uint32_t)((((grp & 1) << 3) + rin) * 272 + (((grp >> 1) << 3) + wn) * 2);

    float acc[4][4][4];
#pragma unroll
    for (int mi = 0; mi < 4; mi++)
#pragma unroll
        for (int ni = 0; ni < 4; ni++)
#pragma unroll
            for (int j = 0; j < 4; j++) acc[mi][ni][j] = 0.f;

    const int KT = K / GBK;

    auto issue = [&](int kt, int stage) {
        const uint32_t stOff = sBase + stage * STAGE_BYTES;
        const int kOff = kt * GBK;
#pragma unroll
        for (int i = 0; i < 4; i++) {
            int c = tid + 256 * i;
            int buf = c >> 9, rem = c & 511;
            int m = rem >> 2, kq = rem & 3;
            const bf16* g = (buf ? Al : Ah) + (size_t)(bm + m) * K + kOff + kq * 8;
            uint32_t sa = stOff + buf * A_BUF_BYTES + m * 80 + kq * 16;
            CP_ASYNC16(sa, g);
        }
#pragma unroll
        for (int i = 0; i < 4; i++) {
            int c = tid + 256 * i;
            int buf = c >> 9, rem = c & 511;
            int kk = rem >> 4, nq = rem & 15;
            const bf16* g = (buf ? Bl : Bh) + (size_t)(kOff + kk) * N + bn + nq * 8;
            uint32_t sa = stOff + A_STAGE_BYTES + buf * B_BUF_BYTES + kk * 272 + nq * 16;
            CP_ASYNC16(sa, g);
        }
    };

    issue(0, 0); CP_COMMIT();
    issue(1, 1); CP_COMMIT();

    for (int kt = 0; kt < KT; kt++) {
        CP_WAIT1();
        __syncthreads();
        if (kt + 2 < KT) issue(kt + 2, (kt + 2) % NSTAGE);
        CP_COMMIT();

        const uint32_t stOff = sBase + (kt % NSTAGE) * STAGE_BYTES;
#pragma unroll
        for (int ks = 0; ks < 2; ks++) {
            unsigned a[2][4][4];
            unsigned b[2][4][2];
#pragma unroll
            for (int buf = 0; buf < 2; buf++) {
                uint32_t aS = stOff + buf * A_BUF_BYTES + laneA + ks * 32;
#pragma unroll
                for (int mt = 0; mt < 4; mt++) {
                    uint32_t addr = aS + (wm + mt * 16) * 80;
                    LDSM4(a[buf][mt][0], a[buf][mt][1], a[buf][mt][2], a[buf][mt][3], addr);
                }
                uint32_t bS = stOff + A_STAGE_BYTES + buf * B_BUF_BYTES + laneB + ks * 4352;
#pragma unroll
                for (int nj = 0; nj < 2; nj++) {
                    uint32_t addr = bS + nj * 32;
                    LDSM4T(b[buf][2 * nj][0], b[buf][2 * nj][1],
                           b[buf][2 * nj + 1][0], b[buf][2 * nj + 1][1], addr);
                }
            }
#pragma unroll
            for (int mt = 0; mt < 4; mt++)
#pragma unroll
                for (int nt = 0; nt < 4; nt++) {
                    mma16816(acc[mt][nt], a[0][mt], b[0][nt]);
                    mma16816(acc[mt][nt], a[0][mt], b[1][nt]);
                    mma16816(acc[mt][nt], a[1][mt], b[0][nt]);
                }
        }
        __syncthreads();
    }

    // ---- fused epilogue ----
    const int r0 = bm + wm + (lane >> 2);
    const int c0 = bn + wn + (lane & 3) * 2;
#pragma unroll
    for (int mt = 0; mt < 4; mt++)
#pragma unroll
        for (int nt = 0; nt < 4; nt++) {
            const int col = c0 + nt * 8;
#pragma unroll
            for (int rp = 0; rp < 2; rp++) {
                const int row = r0 + mt * 16 + rp * 8;
                float2 v = make_float2(acc[mt][nt][2 * rp], acc[mt][nt][2 * rp + 1]);
                if (MODE == 0) {
                    if (RES) {
                        float2 a0 = *(const float2*)(RES + (size_t)row * N + col);
                        v.x += a0.x; v.y += a0.y;
                    }
                    *(float2*)(C + (size_t)row * N + col) = v;
                } else if (MODE == 1) {
                    const int seg = col >> 10;          // 0:q 1:k 2:v
                    const int d = col & 1023;
                    if (seg < 2) {
                        const int i = (d & 63) >> 1;
                        float c = ct[row * 32 + i];
                        float s = st[row * 32 + i];
                        float a0 = v.x * c - v.y * s;
                        float b0 = v.x * s + v.y * c;
                        v.x = a0; v.y = b0;
                    }
                    unsigned hp, lp;
                    split2pack(v.x, v.y, hp, lp);
                    bf16* oh = (seg == 0) ? O1h : (seg == 1) ? O2h : O3h;
                    bf16* ol = (seg == 0) ? O1l : (seg == 1) ? O2l : O3l;
                    *(unsigned*)(oh + (size_t)row * D + d) = hp;
                    *(unsigned*)(ol + (size_t)row * D + d) = lp;
                } else {   // MODE 2: (g,u) pair -> silu(g)*u
                    const int j = col >> 1;
                    float z = v.x;
                    float sig = 1.0f / (1.0f + __expf(-z));
                    float r = z * sig * v.y;
                    bf16 h, l; split1(r, h, l);
                    O1h[(size_t)row * HFF + j] = h;
                    O1l[(size_t)row * HFF + j] = l;
                }
            }
        }
}

// ---------------- Tensor-core flash attention (bf16 split) ----------------
#define AP 72   // smem row pitch in halfs (144B)

__global__ __launch_bounds__(128) void attn_mma_kernel(
    const bf16* __restrict__ Qh, const bf16* __restrict__ Ql,
    const bf16* __restrict__ Kh, const bf16* __restrict__ Kl,
    const bf16* __restrict__ Vh, const bf16* __restrict__ Vl,
    bf16* __restrict__ Oh, bf16* __restrict__ Ol) {
    __shared__ __align__(16) bf16 sK[2][64 * AP];
    __shared__ __align__(16) bf16 sV[2][64 * AP];

    const int qt   = blockIdx.x;
    const int head = blockIdx.y;
    const int tid  = threadIdx.x;
    const int warp = tid >> 5;
    const int lane = tid & 31;
    const int grp  = lane >> 3;
    const int rin  = lane & 7;
    const int wq   = warp * 16;

    {
        const bf16* qsrc[2] = {Qh, Ql};
#pragma unroll
        for (int c = tid; c < 1024; c += 128) {
            int buf = c >> 9, rem = c & 511;
            int row = rem >> 3, col8 = rem & 7;
            *(uint4*)&sK[buf][row * AP + col8 * 8] =
                *(const uint4*)(qsrc[buf] + (size_t)(qt * 64 + row) * D + head * HD + col8 * 8);
        }
    }
    __syncthreads();

    unsigned aQ[2][4][4];
    {
        uint32_t b0 = (uint32_t)__cvta_generic_to_shared(&sK[0][0]);
        uint32_t b1 = (uint32_t)__cvta_generic_to_shared(&sK[1][0]);
        uint32_t laneOff = (uint32_t)(((wq + ((grp & 1) << 3) + rin) * AP + ((grp >> 1) << 3)) << 1);
#pragma unroll
        for (int kc = 0; kc < 4; kc++) {
            LDSM4(aQ[0][kc][0], aQ[0][kc][1], aQ[0][kc][2], aQ[0][kc][3], b0 + laneOff + kc * 32);
            LDSM4(aQ[1][kc][0], aQ[1][kc][1], aQ[1][kc][2], aQ[1][kc][3], b1 + laneOff + kc * 32);
        }
    }

    float o[8][4];
#pragma unroll
    for (int nt = 0; nt < 8; nt++)
#pragma unroll
        for (int j = 0; j < 4; j++) o[nt][j] = 0.f;
    float m0 = -1e30f, m1 = -1e30f, l0 = 0.f, l1 = 0.f;
    const float scale = 0.125f;

    const uint32_t sK0 = (uint32_t)__cvta_generic_to_shared(&sK[0][0]);
    const uint32_t sK1 = (uint32_t)__cvta_generic_to_shared(&sK[1][0]);
    const uint32_t sV0 = (uint32_t)__cvta_generic_to_shared(&sV[0][0]);
    const uint32_t sV1 = (uint32_t)__cvta_generic_to_shared(&sV[1][0]);

    const int r0g = qt * 64 + wq + (lane >> 2);
    const int r1g = r0g + 8;

    for (int kt = 0; kt <= qt; kt++) {
        __syncthreads();
        {
            const bf16* src[4] = {Kh, Kl, Vh, Vl};
            bf16* dst[4] = {sK[0], sK[1], sV[0], sV[1]};
#pragma unroll
            for (int c = tid; c < 2048; c += 128) {
                int which = c >> 9, rem = c & 511;
                int row = rem >> 3, col8 = rem & 7;
                *(uint4*)&dst[which][row * AP + col8 * 8] =
                    *(const uint4*)(src[which] + (size_t)(kt * 64 + row) * D + head * HD + col8 * 8);
            }
        }
        __syncthreads();

        float s[8][4];
#pragma unroll
        for (int nt = 0; nt < 8; nt++)
#pragma unroll
            for (int j = 0; j < 4; j++) s[nt][j] = 0.f;

#pragma unroll
        for (int kc = 0; kc < 4; kc++) {
            unsigned bh[8][2], bl[8][2];
#pragma unroll
            for (int np = 0; np < 4; np++) {
                uint32_t off = (uint32_t)(((np * 16 + ((grp >> 1) << 3) + rin) * AP
                                           + kc * 16 + ((grp & 1) << 3)) << 1);
                LDSM4(bh[2 * np][0], bh[2 * np][1], bh[2 * np + 1][0], bh[2 * np + 1][1], sK0 + off);
                LDSM4(bl[2 * np][0], bl[2 * np][1], bl[2 * np + 1][0], bl[2 * np + 1][1], sK1 + off);
            }
#pragma unroll
            for (int nt = 0; nt < 8; nt++) {
                mma16816(s[nt], aQ[0][kc], bh[nt]);
                mma16816(s[nt], aQ[0][kc], bl[nt]);
                mma16816(s[nt], aQ[1][kc], bh[nt]);
            }
        }

        const bool diag = (kt == qt);
#pragma unroll
        for (int nt = 0; nt < 8; nt++) {
            int c0g = kt * 64 + nt * 8 + (lane & 3) * 2;
            s[nt][0] *= scale; s[nt][1] *= scale;
            s[nt][2] *= scale; s[nt][3] *= scale;
            if (diag) {
                if (c0g     > r0g) s[nt][0] = -1e30f;
                if (c0g + 1 > r0g) s[nt][1] = -1e30f;
                if (c0g     > r1g) s[nt][2] = -1e30f;
                if (c0g + 1 > r1g) s[nt][3] = -1e30f;
            }
        }

        float mx0 = -1e30f, mx1 = -1e30f;
#pragma unroll
        for (int nt = 0; nt < 8; nt++) {
            mx0 = fmaxf(mx0, fmaxf(s[nt][0], s[nt][1]));
            mx1 = fmaxf(mx1, fmaxf(s[nt][2], s[nt][3]));
        }
        mx0 = fmaxf(mx0, __shfl_xor_sync(0xffffffffu, mx0, 1));
        mx0 = fmaxf(mx0, __shfl_xor_sync(0xffffffffu, mx0, 2));
        mx1 = fmaxf(mx1, __shfl_xor_sync(0xffffffffu, mx1, 1));
        mx1 = fmaxf(mx1, __shfl_xor_sync(0xffffffffu, mx1, 2));
        float mn0 = fmaxf(m0, mx0), mn1 = fmaxf(m1, mx1);
        float cr0 = __expf(m0 - mn0), cr1 = __expf(m1 - mn1);
        m0 = mn0; m1 = mn1;
        float rs0 = 0.f, rs1 = 0.f;
#pragma unroll
        for (int nt = 0; nt < 8; nt++) {
            s[nt][0] = __expf(s[nt][0] - mn0); rs0 += s[nt][0];
            s[nt][1] = __expf(s[nt][1] - mn0); rs0 += s[nt][1];
            s[nt][2] = __expf(s[nt][2] - mn1); rs1 += s[nt][2];
            s[nt][3] = __expf(s[nt][3] - mn1); rs1 += s[nt][3];
        }
        l0 = l0 * cr0 + rs0;
        l1 = l1 * cr1 + rs1;
#pragma unroll
        for (int nt = 0; nt < 8; nt++) {
            o[nt][0] *= cr0; o[nt][1] *= cr0;
            o[nt][2] *= cr1; o[nt][3] *= cr1;
        }

#pragma unroll
        for (int kc = 0; kc < 4; kc++) {
            int t0 = 2 * kc, t1 = 2 * kc + 1;
            unsigned ah[4], al[4];
            split2pack(s[t0][0], s[t0][1], ah[0], al[0]);
            split2pack(s[t0][2], s[t0][3], ah[1], al[1]);
            split2pack(s[t1][0], s[t1][1], ah[2], al[2]);
            split2pack(s[t1][2], s[t1][3], ah[3], al[3]);

            unsigned bvh[8][2], bvl[8][2];
#pragma unroll
            for (int np = 0; np < 4; np++) {
                uint32_t off = (uint32_t)(((kc * 16 + ((grp & 1) << 3) + rin) * AP
                                           + np * 16 + ((grp >> 1) << 3)) << 1);
                LDSM4T(bvh[2 * np][0], bvh[2 * np][1], bvh[2 * np + 1][0], bvh[2 * np + 1][1], sV0 + off);
                LDSM4T(bvl[2 * np][0], bvl[2 * np][1], bvl[2 * np + 1][0], bvl[2 * np + 1][1], sV1 + off);
            }
#pragma unroll
            for (int nt = 0; nt < 8; nt++) {
                mma16816(o[nt], ah, bvh[nt]);
                mma16816(o[nt], ah, bvl[nt]);
                mma16816(o[nt], al, bvh[nt]);
            }
        }
    }

    l0 += __shfl_xor_sync(0xffffffffu, l0, 1);
    l0 += __shfl_xor_sync(0xffffffffu, l0, 2);
    l1 += __shfl_xor_sync(0xffffffffu, l1, 1);
    l1 += __shfl_xor_sync(0xffffffffu, l1, 2);
    float inv0 = 1.f / l0, inv1 = 1.f / l1;
#pragma unroll
    for (int nt = 0; nt < 8; nt++) {
        int col = head * HD + nt * 8 + (lane & 3) * 2;
        unsigned hp, lp;
        split2pack(o[nt][0] * inv0, o[nt][1] * inv0, hp, lp);
        *(unsigned*)(Oh + (size_t)r0g * D + col) = hp;
        *(unsigned*)(Ol + (size_t)r0g * D + col) = lp;
        split2pack(o[nt][2] * inv1, o[nt][3] * inv1, hp, lp);
        *(unsigned*)(Oh + (size_t)r1g * D + col) = hp;
        *(unsigned*)(Ol + (size_t)r1g * D + col) = lp;
    }
}

// ---------------- Logits ----------------
__global__ void logits_kernel(const float* __restrict__ xf,
                              const float* __restrict__ Wout,
                              float* __restrict__ out) {
    __shared__ float xs[D];
    for (int i = threadIdx.x; i < D; i += 256) xs[i] = xf[i];
    __syncthreads();
    int v = blockIdx.x * 256 + threadIdx.x;
    float acc = 0.f;
#pragma unroll 8
    for (int d = 0; d < D; d++) acc += xs[d] * Wout[(size_t)d * NV + v];
    out[v] = acc;
}

// ---------------- Host launch ----------------
extern "C" void kernel_launch(void* const* d_in, const int* in_sizes, int n_in,
                              void* d_out, int out_size) {
    int bi = 1;
    if (n_in >= 2 && in_sizes[1] == 1) bi = 2;
    const int*   tokens  = (const int*)d_in[0];
    const float* tok_emb = (const float*)d_in[bi + 0];
    const float* Wq      = (const float*)d_in[bi + 1];
    const float* Wk      = (const float*)d_in[bi + 2];
    const float* Wv      = (const float*)d_in[bi + 3];
    const float* Wo      = (const float*)d_in[bi + 4];
    const float* W1      = (const float*)d_in[bi + 5];
    const float* W2      = (const float*)d_in[bi + 6];
    const float* W3      = (const float*)d_in[bi + 7];
    const float* anw     = (const float*)d_in[bi + 8];
    const float* fnw     = (const float*)d_in[bi + 9];
    const float* finw    = (const float*)d_in[bi + 10];
    const float* Wout    = (const float*)d_in[bi + 11];
    float* out = (float*)d_out;

    float *h_, *cos_, *sin_, *xf_;
    bf16 *xh_, *xl_, *oh_, *ol_, *gh_, *gl_;
    bf16 *qh_, *ql_, *kh_, *kl_, *vh_, *vl_;
    bf16 *wqkvh_, *wqkvl_, *w13h_, *w13l_, *woh_, *wol_, *w2h_, *w2l_;

    cudaGetSymbolAddress((void**)&h_,  g_h);
    cudaGetSymbolAddress((void**)&cos_, g_cos);
    cudaGetSymbolAddress((void**)&sin_, g_sin);
    cudaGetSymbolAddress((void**)&xf_, g_xf);
    cudaGetSymbolAddress((void**)&xh_, g_xh);
    cudaGetSymbolAddress((void**)&xl_, g_xl);
    cudaGetSymbolAddress((void**)&oh_, g_oh);
    cudaGetSymbolAddress((void**)&ol_, g_ol);
    cudaGetSymbolAddress((void**)&gh_, g_gh);
    cudaGetSymbolAddress((void**)&gl_, g_gl);
    cudaGetSymbolAddress((void**)&qh_, g_qh); cudaGetSymbolAddress((void**)&ql_, g_ql);
    cudaGetSymbolAddress((void**)&kh_, g_kh); cudaGetSymbolAddress((void**)&kl_, g_kl);
    cudaGetSymbolAddress((void**)&vh_, g_vh); cudaGetSymbolAddress((void**)&vl_, g_vl);
    cudaGetSymbolAddress((void**)&wqkvh_, g_wqkvh); cudaGetSymbolAddress((void**)&wqkvl_, g_wqkvl);
    cudaGetSymbolAddress((void**)&w13h_, g_w13h); cudaGetSymbolAddress((void**)&w13l_, g_w13l);
    cudaGetSymbolAddress((void**)&woh_, g_woh); cudaGetSymbolAddress((void**)&wol_, g_wol);
    cudaGetSymbolAddress((void**)&w2h_, g_w2h); cudaGetSymbolAddress((void**)&w2l_, g_w2l);

    static int smem_set = 0;
    if (!smem_set) {
        cudaFuncSetAttribute(gemm_bf16x3_kernel<0>,
                             cudaFuncAttributeMaxDynamicSharedMemorySize, SMEM_BYTES);
        cudaFuncSetAttribute(gemm_bf16x3_kernel<1>,
                             cudaFuncAttributeMaxDynamicSharedMemorySize, SMEM_BYTES);
        cudaFuncSetAttribute(gemm_bf16x3_kernel<2>,
                             cudaFuncAttributeMaxDynamicSharedMemorySize, SMEM_BYTES);
        smem_set = 1;
    }

    // ---- pack + split weights ----
    {
        int nDD = D * D / 2, nDF = D * HFF / 2, nFD = HFF * D / 2;
        dim3 bDD((nDD + 255) / 256, 1, NL);
        dim3 bDF((nDF + 255) / 256, 1, NL);
        dim3 bFD((nFD + 255) / 256, 1, NL);
        pack_split_kernel<<<bDD, 256>>>(Wq, wqkvh_, wqkvl_, D, D, 1, 0,    3 * D, (size_t)D * D, (size_t)3 * D * D);
        pack_split_kernel<<<bDD, 256>>>(Wk, wqkvh_, wqkvl_, D, D, 1, D,    3 * D, (size_t)D * D, (size_t)3 * D * D);
        pack_split_kernel<<<bDD, 256>>>(Wv, wqkvh_, wqkvl_, D, D, 1, 2 * D, 3 * D, (size_t)D * D, (size_t)3 * D * D);
        pack_split_kernel<<<bDF, 256>>>(W1, w13h_, w13l_, D, HFF, 2, 0, 2 * HFF, (size_t)D * HFF, (size_t)2 * D * HFF);
        pack_split_kernel<<<bDF, 256>>>(W3, w13h_, w13l_, D, HFF, 2, 1, 2 * HFF, (size_t)D * HFF, (size_t)2 * D * HFF);
        pack_split_kernel<<<bDD, 256>>>(Wo, woh_, wol_, D, D, 1, 0, D, (size_t)D * D, (size_t)D * D);
        pack_split_kernel<<<bFD, 256>>>(W2, w2h_, w2l_, HFF, D, 1, 0, D, (size_t)HFF * D, (size_t)HFF * D);
    }

    rope_table_kernel<<<(S * 32 + 255) / 256, 256>>>(cos_, sin_);
    embed_kernel<<<(S * D) / 256, 256>>>(tokens, tok_emb, h_);

    const dim3 gQKV(3 * D / GBN, S / GBM);   // (24, 16)
    const dim3 gDD(D / GBN, S / GBM);        // (8, 16)
    const dim3 gW13(2 * HFF / GBN, S / GBM); // (44, 16)

    for (int l = 0; l < NL; l++) {
        size_t offQKV = (size_t)l * 3 * D * D;
        size_t offDD  = (size_t)l * D * D;
        size_t off13  = (size_t)l * 2 * D * HFF;
        size_t offFD  = (size_t)l * HFF * D;

        rmsnorm_split_kernel<<<S, 256>>>(h_, anw + (size_t)l * D, xh_, xl_);

        gemm_bf16x3_kernel<1><<<gQKV, 256, SMEM_BYTES>>>(
            xh_, xl_, wqkvh_ + offQKV, wqkvl_ + offQKV, nullptr, nullptr,
            qh_, ql_, kh_, kl_, vh_, vl_, cos_, sin_, S, 3 * D, D);

        attn_mma_kernel<<<dim3(S / 64, NH), 128>>>(qh_, ql_, kh_, kl_, vh_, vl_, oh_, ol_);

        gemm_bf16x3_kernel<0><<<gDD, 256, SMEM_BYTES>>>(
            oh_, ol_, woh_ + offDD, wol_ + offDD, h_, h_,
            nullptr, nullptr, nullptr, nullptr, nullptr, nullptr, nullptr, nullptr, S, D, D);

        rmsnorm_split_kernel<<<S, 256>>>(h_, fnw + (size_t)l * D, xh_, xl_);

        gemm_bf16x3_kernel<2><<<gW13, 256, SMEM_BYTES>>>(
            xh_, xl_, w13h_ + off13, w13l_ + off13, nullptr, nullptr,
            gh_, gl_, nullptr, nullptr, nullptr, nullptr, nullptr, nullptr, S, 2 * HFF, D);

        gemm_bf16x3_kernel<0><<<gDD, 256, SMEM_BYTES>>>(
            gh_, gl_, w2h_ + offFD, w2l_ + offFD, h_, h_,
            nullptr, nullptr, nullptr, nullptr, nullptr, nullptr, nullptr, nullptr, S, D, HFF);
    }

    rmsnorm_kernel<<<1, 256>>>(h_ + (size_t)(S - 1) * D, finw, xf_);
    logits_kernel<<<NV / 256, 256>>>(xf_, Wout, out);
}

// round 7
// speedup vs baseline: 3.2014x; 1.0081x over previous
#include <cuda_runtime.h>
#include <cuda_bf16.h>
#include <math.h>
#include <stdint.h>

// ---------------- Problem constants ----------------
#define S    2048
#define D    1024
#define NH   16
#define HD   64
#define HFF  2816
#define NV   32000
#define NL   4

typedef __nv_bfloat16 bf16;

// ---------------- Device scratch ----------------
__device__ float g_h[S * D];
__device__ float g_cos[S * 32];
__device__ float g_sin[S * 32];
__device__ float g_xf[D];

// split (hi/lo) bf16 activation buffers
__device__ __align__(16) bf16 g_xh[S * D],  g_xl[S * D];
__device__ __align__(16) bf16 g_oh[S * D],  g_ol[S * D];
__device__ __align__(16) bf16 g_gh[S * HFF], g_gl[S * HFF];
__device__ __align__(16) bf16 g_qh[S * D], g_ql[S * D];
__device__ __align__(16) bf16 g_kh[S * D], g_kl[S * D];
__device__ __align__(16) bf16 g_vh[S * D], g_vl[S * D];

// packed split weights (B stays [K, N] row-major)
__device__ __align__(16) bf16 g_wqkvh[NL * D * 3 * D], g_wqkvl[NL * D * 3 * D];
__device__ __align__(16) bf16 g_w13h[NL * D * 2 * HFF], g_w13l[NL * D * 2 * HFF];
__device__ __align__(16) bf16 g_woh[NL * D * D], g_wol[NL * D * D];
__device__ __align__(16) bf16 g_w2h[NL * HFF * D], g_w2l[NL * HFF * D];

// ---------------- small helpers ----------------
__device__ __forceinline__ void split1(float v, bf16& h, bf16& l) {
    h = __float2bfloat16(v);
    l = __float2bfloat16(v - __bfloat162float(h));
}
__device__ __forceinline__ void split2pack(float x, float y, unsigned& hp, unsigned& lp) {
    bf16 hx = __float2bfloat16(x), hy = __float2bfloat16(y);
    float lx = x - __bfloat162float(hx), ly = y - __bfloat162float(hy);
    bf16 lxb = __float2bfloat16(lx), lyb = __float2bfloat16(ly);
    hp = (unsigned)(*(unsigned short*)&hx) | ((unsigned)(*(unsigned short*)&hy) << 16);
    lp = (unsigned)(*(unsigned short*)&lxb) | ((unsigned)(*(unsigned short*)&lyb) << 16);
}

// ---------------- pack + split weights ----------------
__global__ void pack_split_kernel(const float* __restrict__ in,
                                  bf16* __restrict__ oh, bf16* __restrict__ ol,
                                  int K, int N, int colMul, int colOff, int outStride,
                                  size_t inLS, size_t outLS) {
    int l = blockIdx.z;
    in += l * inLS; oh += l * outLS; ol += l * outLS;
    int idx = blockIdx.x * 256 + threadIdx.x;
    if (idx >= K * (N / 2)) return;
    int k = idx / (N / 2);
    int n = (idx % (N / 2)) * 2;
    float2 v = *(const float2*)(in + (size_t)k * N + n);
    if (colMul == 1) {
        unsigned hp, lp; split2pack(v.x, v.y, hp, lp);
        size_t o = (size_t)k * outStride + colOff + n;
        *(unsigned*)(oh + o) = hp;
        *(unsigned*)(ol + o) = lp;
    } else {
        bf16 h, lo;
        size_t o = (size_t)k * outStride + colOff + 2 * n;
        split1(v.x, h, lo); oh[o] = h; ol[o] = lo;
        split1(v.y, h, lo); oh[o + 2] = h; ol[o + 2] = lo;
    }
}

// ---------------- RoPE table ----------------
__global__ void rope_table_kernel(float* ct, float* st) {
    int idx = blockIdx.x * 256 + threadIdx.x;
    if (idx >= S * 32) return;
    int pos = idx >> 5;
    int i = idx & 31;
    float inv = powf(10000.0f, -((float)(2 * i) / (float)HD));
    float ang = (float)pos * inv;
    float s, c;
    sincosf(ang, &s, &c);
    ct[idx] = c;
    st[idx] = s;
}

// ---------------- Embedding gather ----------------
__global__ void embed_kernel(const int* __restrict__ tokens,
                             const float* __restrict__ emb,
                             float* __restrict__ h) {
    int idx = blockIdx.x * 256 + threadIdx.x;
    int s = idx >> 10;
    int d = idx & 1023;
    h[idx] = emb[(size_t)tokens[s] * D + d];
}

// ---------------- RMSNorm -> split bf16 hi/lo ----------------
__global__ void rmsnorm_split_kernel(const float* __restrict__ in,
                                     const float* __restrict__ w,
                                     bf16* __restrict__ oh, bf16* __restrict__ ol) {
    const float* r = in + (size_t)blockIdx.x * D;
    bf16* ph = oh + (size_t)blockIdx.x * D;
    bf16* pl = ol + (size_t)blockIdx.x * D;
    int t = threadIdx.x;
    float v[4];
    float ss = 0.f;
#pragma unroll
    for (int i = 0; i < 4; i++) { v[i] = r[t + i * 256]; ss += v[i] * v[i]; }
#pragma unroll
    for (int off = 16; off; off >>= 1) ss += __shfl_xor_sync(0xffffffffu, ss, off);
    __shared__ float red[8];
    if ((t & 31) == 0) red[t >> 5] = ss;
    __syncthreads();
    if (t < 8) {
        float x = red[t];
#pragma unroll
        for (int off = 4; off; off >>= 1) x += __shfl_xor_sync(0xffu, x, off);
        if (t == 0) red[0] = x;
    }
    __syncthreads();
    float scale = rsqrtf(red[0] * (1.0f / (float)D) + 1e-6f);
#pragma unroll
    for (int i = 0; i < 4; i++) {
        float rv = v[i] * scale * w[t + i * 256];
        bf16 h, l; split1(rv, h, l);
        ph[t + i * 256] = h;
        pl[t + i * 256] = l;
    }
}

// ---------------- plain fp32 RMSNorm (final row) ----------------
__global__ void rmsnorm_kernel(const float* __restrict__ in,
                               const float* __restrict__ w,
                               float* __restrict__ out) {
    const float* r = in;
    int t = threadIdx.x;
    float v[4];
    float ss = 0.f;
#pragma unroll
    for (int i = 0; i < 4; i++) { v[i] = r[t + i * 256]; ss += v[i] * v[i]; }
#pragma unroll
    for (int off = 16; off; off >>= 1) ss += __shfl_xor_sync(0xffffffffu, ss, off);
    __shared__ float red[8];
    if ((t & 31) == 0) red[t >> 5] = ss;
    __syncthreads();
    if (t < 8) {
        float x = red[t];
#pragma unroll
        for (int off = 4; off; off >>= 1) x += __shfl_xor_sync(0xffu, x, off);
        if (t == 0) red[0] = x;
    }
    __syncthreads();
    float scale = rsqrtf(red[0] * (1.0f / (float)D) + 1e-6f);
#pragma unroll
    for (int i = 0; i < 4; i++) out[t + i * 256] = v[i] * scale * w[t + i * 256];
}

// ---------------- MMA helpers ----------------
#define LDSM4(r0, r1, r2, r3, addr)                                          \
    asm volatile("ldmatrix.sync.aligned.m8n8.x4.shared.b16 {%0,%1,%2,%3},[%4];" \
                 : "=r"(r0), "=r"(r1), "=r"(r2), "=r"(r3) : "r"(addr))
#define LDSM4T(r0, r1, r2, r3, addr)                                         \
    asm volatile("ldmatrix.sync.aligned.m8n8.x4.trans.shared.b16 {%0,%1,%2,%3},[%4];" \
                 : "=r"(r0), "=r"(r1), "=r"(r2), "=r"(r3) : "r"(addr))
#define CP_ASYNC16(saddr, gaddr)                                             \
    asm volatile("cp.async.cg.shared.global [%0],[%1],16;" :: "r"(saddr), "l"(gaddr))
#define CP_COMMIT() asm volatile("cp.async.commit_group;" ::: "memory")
#define CP_WAIT1()  asm volatile("cp.async.wait_group 1;" ::: "memory")

__device__ __forceinline__ void mma16816(float* c, const unsigned* a, const unsigned* b) {
    asm volatile(
        "mma.sync.aligned.m16n8k16.row.col.f32.bf16.bf16.f32 "
        "{%0,%1,%2,%3},{%4,%5,%6,%7},{%8,%9},{%0,%1,%2,%3};"
        : "+f"(c[0]), "+f"(c[1]), "+f"(c[2]), "+f"(c[3])
        : "r"(a[0]), "r"(a[1]), "r"(a[2]), "r"(a[3]), "r"(b[0]), "r"(b[1]));
}

// ---------------- bf16x3 tensor-core GEMM, cp.async 3-stage, fused epilogues ----------------
#define GBM 128
#define GBN 128
#define GBK 32
#define NSTAGE 3
#define A_BUF_BYTES 10240
#define B_BUF_BYTES 8704
#define A_STAGE_BYTES 20480
#define STAGE_BYTES 37888
#define SMEM_BYTES (NSTAGE * STAGE_BYTES)

extern __shared__ char gsmem[];

template <int MODE>
__global__ __launch_bounds__(256) void gemm_bf16x3_kernel(
    const bf16* __restrict__ Ah, const bf16* __restrict__ Al,
    const bf16* __restrict__ Bh, const bf16* __restrict__ Bl,
    const float* __restrict__ RES, float* __restrict__ C,
    bf16* __restrict__ O1h, bf16* __restrict__ O1l,
    bf16* __restrict__ O2h, bf16* __restrict__ O2l,
    bf16* __restrict__ O3h, bf16* __restrict__ O3l,
    const float* __restrict__ ct, const float* __restrict__ st,
    int M, int N, int K) {
    const int tid  = threadIdx.x;
    const int bm   = blockIdx.y * GBM;
    const int bn   = blockIdx.x * GBN;
    const int warp = tid >> 5;
    const int lane = tid & 31;
    const int wm   = (warp >> 2) * 64;
    const int wn   = (warp & 3) * 32;
    const int grp  = lane >> 3;
    const int rin  = lane & 7;

    const uint32_t sBase = (uint32_t)__cvta_generic_to_shared(gsmem);
    const uint32_t laneA = (uint32_t)((((grp & 1) << 3) + rin) * 80 + ((grp >> 1) << 4));
    const uint32_t laneB = (uint32_t)((((grp & 1) << 3) + rin) * 272 + (((grp >> 1) << 3) + wn) * 2);

    float acc[4][4][4];
#pragma unroll
    for (int mi = 0; mi < 4; mi++)
#pragma unroll
        for (int ni = 0; ni < 4; ni++)
#pragma unroll
            for (int j = 0; j < 4; j++) acc[mi][ni][j] = 0.f;

    const int KT = K / GBK;

    auto issue = [&](int kt, int stage) {
        const uint32_t stOff = sBase + stage * STAGE_BYTES;
        const int kOff = kt * GBK;
#pragma unroll
        for (int i = 0; i < 4; i++) {
            int c = tid + 256 * i;
            int buf = c >> 9, rem = c & 511;
            int m = rem >> 2, kq = rem & 3;
            const bf16* g = (buf ? Al : Ah) + (size_t)(bm + m) * K + kOff + kq * 8;
            uint32_t sa = stOff + buf * A_BUF_BYTES + m * 80 + kq * 16;
            CP_ASYNC16(sa, g);
        }
#pragma unroll
        for (int i = 0; i < 4; i++) {
            int c = tid + 256 * i;
            int buf = c >> 9, rem = c & 511;
            int kk = rem >> 4, nq = rem & 15;
            const bf16* g = (buf ? Bl : Bh) + (size_t)(kOff + kk) * N + bn + nq * 8;
            uint32_t sa = stOff + A_STAGE_BYTES + buf * B_BUF_BYTES + kk * 272 + nq * 16;
            CP_ASYNC16(sa, g);
        }
    };

    issue(0, 0); CP_COMMIT();
    issue(1, 1); CP_COMMIT();

    for (int kt = 0; kt < KT; kt++) {
        CP_WAIT1();
        __syncthreads();
        if (kt + 2 < KT) issue(kt + 2, (kt + 2) % NSTAGE);
        CP_COMMIT();

        const uint32_t stOff = sBase + (kt % NSTAGE) * STAGE_BYTES;
#pragma unroll
        for (int ks = 0; ks < 2; ks++) {
            unsigned a[2][4][4];
            unsigned b[2][4][2];
#pragma unroll
            for (int buf = 0; buf < 2; buf++) {
                uint32_t aS = stOff + buf * A_BUF_BYTES + laneA + ks * 32;
#pragma unroll
                for (int mt = 0; mt < 4; mt++) {
                    uint32_t addr = aS + (wm + mt * 16) * 80;
                    LDSM4(a[buf][mt][0], a[buf][mt][1], a[buf][mt][2], a[buf][mt][3], addr);
                }
                uint32_t bS = stOff + A_STAGE_BYTES + buf * B_BUF_BYTES + laneB + ks * 4352;
#pragma unroll
                for (int nj = 0; nj < 2; nj++) {
                    uint32_t addr = bS + nj * 32;
                    LDSM4T(b[buf][2 * nj][0], b[buf][2 * nj][1],
                           b[buf][2 * nj + 1][0], b[buf][2 * nj + 1][1], addr);
                }
            }
            // pass-major MMA order: same-acc dependency distance = 16
#pragma unroll
            for (int mt = 0; mt < 4; mt++)
#pragma unroll
                for (int nt = 0; nt < 4; nt++)
                    mma16816(acc[mt][nt], a[0][mt], b[0][nt]);   // hi*hi
#pragma unroll
            for (int mt = 0; mt < 4; mt++)
#pragma unroll
                for (int nt = 0; nt < 4; nt++)
                    mma16816(acc[mt][nt], a[0][mt], b[1][nt]);   // hi*lo
#pragma unroll
            for (int mt = 0; mt < 4; mt++)
#pragma unroll
                for (int nt = 0; nt < 4; nt++)
                    mma16816(acc[mt][nt], a[1][mt], b[0][nt]);   // lo*hi
        }
        __syncthreads();
    }

    // ---- fused epilogue ----
    const int r0 = bm + wm + (lane >> 2);
    const int c0 = bn + wn + (lane & 3) * 2;
#pragma unroll
    for (int mt = 0; mt < 4; mt++)
#pragma unroll
        for (int nt = 0; nt < 4; nt++) {
            const int col = c0 + nt * 8;
#pragma unroll
            for (int rp = 0; rp < 2; rp++) {
                const int row = r0 + mt * 16 + rp * 8;
                float2 v = make_float2(acc[mt][nt][2 * rp], acc[mt][nt][2 * rp + 1]);
                if (MODE == 0) {
                    if (RES) {
                        float2 a0 = *(const float2*)(RES + (size_t)row * N + col);
                        v.x += a0.x; v.y += a0.y;
                    }
                    *(float2*)(C + (size_t)row * N + col) = v;
                } else if (MODE == 1) {
                    const int seg = col >> 10;          // 0:q 1:k 2:v
                    const int d = col & 1023;
                    if (seg < 2) {
                        const int i = (d & 63) >> 1;
                        float c = ct[row * 32 + i];
                        float s = st[row * 32 + i];
                        float a0 = v.x * c - v.y * s;
                        float b0 = v.x * s + v.y * c;
                        v.x = a0; v.y = b0;
                    }
                    unsigned hp, lp;
                    split2pack(v.x, v.y, hp, lp);
                    bf16* oh = (seg == 0) ? O1h : (seg == 1) ? O2h : O3h;
                    bf16* ol = (seg == 0) ? O1l : (seg == 1) ? O2l : O3l;
                    *(unsigned*)(oh + (size_t)row * D + d) = hp;
                    *(unsigned*)(ol + (size_t)row * D + d) = lp;
                } else {   // MODE 2: (g,u) pair -> silu(g)*u
                    const int j = col >> 1;
                    float z = v.x;
                    float sig = 1.0f / (1.0f + __expf(-z));
                    float r = z * sig * v.y;
                    bf16 h, l; split1(r, h, l);
                    O1h[(size_t)row * HFF + j] = h;
                    O1l[(size_t)row * HFF + j] = l;
                }
            }
        }
}

// ---------------- Tensor-core flash attention (bf16 split) ----------------
#define AP 72   // smem row pitch in halfs (144B)

__global__ __launch_bounds__(128) void attn_mma_kernel(
    const bf16* __restrict__ Qh, const bf16* __restrict__ Ql,
    const bf16* __restrict__ Kh, const bf16* __restrict__ Kl,
    const bf16* __restrict__ Vh, const bf16* __restrict__ Vl,
    bf16* __restrict__ Oh, bf16* __restrict__ Ol) {
    __shared__ __align__(16) bf16 sK[2][64 * AP];
    __shared__ __align__(16) bf16 sV[2][64 * AP];

    const int qt   = gridDim.x - 1 - blockIdx.x;   // longest-first scheduling
    const int head = blockIdx.y;
    const int tid  = threadIdx.x;
    const int warp = tid >> 5;
    const int lane = tid & 31;
    const int grp  = lane >> 3;
    const int rin  = lane & 7;
    const int wq   = warp * 16;

    {
        const bf16* qsrc[2] = {Qh, Ql};
#pragma unroll
        for (int c = tid; c < 1024; c += 128) {
            int buf = c >> 9, rem = c & 511;
            int row = rem >> 3, col8 = rem & 7;
            *(uint4*)&sK[buf][row * AP + col8 * 8] =
                *(const uint4*)(qsrc[buf] + (size_t)(qt * 64 + row) * D + head * HD + col8 * 8);
        }
    }
    __syncthreads();

    unsigned aQ[2][4][4];
    {
        uint32_t b0 = (uint32_t)__cvta_generic_to_shared(&sK[0][0]);
        uint32_t b1 = (uint32_t)__cvta_generic_to_shared(&sK[1][0]);
        uint32_t laneOff = (uint32_t)(((wq + ((grp & 1) << 3) + rin) * AP + ((grp >> 1) << 3)) << 1);
#pragma unroll
        for (int kc = 0; kc < 4; kc++) {
            LDSM4(aQ[0][kc][0], aQ[0][kc][1], aQ[0][kc][2], aQ[0][kc][3], b0 + laneOff + kc * 32);
            LDSM4(aQ[1][kc][0], aQ[1][kc][1], aQ[1][kc][2], aQ[1][kc][3], b1 + laneOff + kc * 32);
        }
    }

    float o[8][4];
#pragma unroll
    for (int nt = 0; nt < 8; nt++)
#pragma unroll
        for (int j = 0; j < 4; j++) o[nt][j] = 0.f;
    float m0 = -1e30f, m1 = -1e30f, l0 = 0.f, l1 = 0.f;
    const float scale = 0.125f;

    const uint32_t sK0 = (uint32_t)__cvta_generic_to_shared(&sK[0][0]);
    const uint32_t sK1 = (uint32_t)__cvta_generic_to_shared(&sK[1][0]);
    const uint32_t sV0 = (uint32_t)__cvta_generic_to_shared(&sV[0][0]);
    const uint32_t sV1 = (uint32_t)__cvta_generic_to_shared(&sV[1][0]);

    const int r0g = qt * 64 + wq + (lane >> 2);
    const int r1g = r0g + 8;

    for (int kt = 0; kt <= qt; kt++) {
        __syncthreads();
        {
            const bf16* src[4] = {Kh, Kl, Vh, Vl};
            bf16* dst[4] = {sK[0], sK[1], sV[0], sV[1]};
#pragma unroll
            for (int c = tid; c < 2048; c += 128) {
                int which = c >> 9, rem = c & 511;
                int row = rem >> 3, col8 = rem & 7;
                *(uint4*)&dst[which][row * AP + col8 * 8] =
                    *(const uint4*)(src[which] + (size_t)(kt * 64 + row) * D + head * HD + col8 * 8);
            }
        }
        __syncthreads();

        float s[8][4];
#pragma unroll
        for (int nt = 0; nt < 8; nt++)
#pragma unroll
            for (int j = 0; j < 4; j++) s[nt][j] = 0.f;

#pragma unroll
        for (int kc = 0; kc < 4; kc++) {
            unsigned bh[8][2], bl[8][2];
#pragma unroll
            for (int np = 0; np < 4; np++) {
                uint32_t off = (uint32_t)(((np * 16 + ((grp >> 1) << 3) + rin) * AP
                                           + kc * 16 + ((grp & 1) << 3)) << 1);
                LDSM4(bh[2 * np][0], bh[2 * np][1], bh[2 * np + 1][0], bh[2 * np + 1][1], sK0 + off);
                LDSM4(bl[2 * np][0], bl[2 * np][1], bl[2 * np + 1][0], bl[2 * np + 1][1], sK1 + off);
            }
            // pass-major: same-acc distance = 8
#pragma unroll
            for (int nt = 0; nt < 8; nt++) mma16816(s[nt], aQ[0][kc], bh[nt]);
#pragma unroll
            for (int nt = 0; nt < 8; nt++) mma16816(s[nt], aQ[0][kc], bl[nt]);
#pragma unroll
            for (int nt = 0; nt < 8; nt++) mma16816(s[nt], aQ[1][kc], bh[nt]);
        }

        const bool diag = (kt == qt);
#pragma unroll
        for (int nt = 0; nt < 8; nt++) {
            int c0g = kt * 64 + nt * 8 + (lane & 3) * 2;
            s[nt][0] *= scale; s[nt][1] *= scale;
            s[nt][2] *= scale; s[nt][3] *= scale;
            if (diag) {
                if (c0g     > r0g) s[nt][0] = -1e30f;
                if (c0g + 1 > r0g) s[nt][1] = -1e30f;
                if (c0g     > r1g) s[nt][2] = -1e30f;
                if (c0g + 1 > r1g) s[nt][3] = -1e30f;
            }
        }

        float mx0 = -1e30f, mx1 = -1e30f;
#pragma unroll
        for (int nt = 0; nt < 8; nt++) {
            mx0 = fmaxf(mx0, fmaxf(s[nt][0], s[nt][1]));
            mx1 = fmaxf(mx1, fmaxf(s[nt][2], s[nt][3]));
        }
        mx0 = fmaxf(mx0, __shfl_xor_sync(0xffffffffu, mx0, 1));
        mx0 = fmaxf(mx0, __shfl_xor_sync(0xffffffffu, mx0, 2));
        mx1 = fmaxf(mx1, __shfl_xor_sync(0xffffffffu, mx1, 1));
        mx1 = fmaxf(mx1, __shfl_xor_sync(0xffffffffu, mx1, 2));
        float mn0 = fmaxf(m0, mx0), mn1 = fmaxf(m1, mx1);
        float cr0 = __expf(m0 - mn0), cr1 = __expf(m1 - mn1);
        m0 = mn0; m1 = mn1;
        float rs0 = 0.f, rs1 = 0.f;
#pragma unroll
        for (int nt = 0; nt < 8; nt++) {
            s[nt][0] = __expf(s[nt][0] - mn0); rs0 += s[nt][0];
            s[nt][1] = __expf(s[nt][1] - mn0); rs0 += s[nt][1];
            s[nt][2] = __expf(s[nt][2] - mn1); rs1 += s[nt][2];
            s[nt][3] = __expf(s[nt][3] - mn1); rs1 += s[nt][3];
        }
        l0 = l0 * cr0 + rs0;
        l1 = l1 * cr1 + rs1;
#pragma unroll
        for (int nt = 0; nt < 8; nt++) {
            o[nt][0] *= cr0; o[nt][1] *= cr0;
            o[nt][2] *= cr1; o[nt][3] *= cr1;
        }

#pragma unroll
        for (int kc = 0; kc < 4; kc++) {
            int t0 = 2 * kc, t1 = 2 * kc + 1;
            unsigned ah[4], al[4];
            split2pack(s[t0][0], s[t0][1], ah[0], al[0]);
            split2pack(s[t0][2], s[t0][3], ah[1], al[1]);
            split2pack(s[t1][0], s[t1][1], ah[2], al[2]);
            split2pack(s[t1][2], s[t1][3], ah[3], al[3]);

            unsigned bvh[8][2], bvl[8][2];
#pragma unroll
            for (int np = 0; np < 4; np++) {
                uint32_t off = (uint32_t)(((kc * 16 + ((grp & 1) << 3) + rin) * AP
                                           + np * 16 + ((grp >> 1) << 3)) << 1);
                LDSM4T(bvh[2 * np][0], bvh[2 * np][1], bvh[2 * np + 1][0], bvh[2 * np + 1][1], sV0 + off);
                LDSM4T(bvl[2 * np][0], bvl[2 * np][1], bvl[2 * np + 1][0], bvl[2 * np + 1][1], sV1 + off);
            }
            // pass-major: same-acc distance = 8
#pragma unroll
            for (int nt = 0; nt < 8; nt++) mma16816(o[nt], ah, bvh[nt]);
#pragma unroll
            for (int nt = 0; nt < 8; nt++) mma16816(o[nt], ah, bvl[nt]);
#pragma unroll
            for (int nt = 0; nt < 8; nt++) mma16816(o[nt], al, bvh[nt]);
        }
    }

    l0 += __shfl_xor_sync(0xffffffffu, l0, 1);
    l0 += __shfl_xor_sync(0xffffffffu, l0, 2);
    l1 += __shfl_xor_sync(0xffffffffu, l1, 1);
    l1 += __shfl_xor_sync(0xffffffffu, l1, 2);
    float inv0 = 1.f / l0, inv1 = 1.f / l1;
#pragma unroll
    for (int nt = 0; nt < 8; nt++) {
        int col = head * HD + nt * 8 + (lane & 3) * 2;
        unsigned hp, lp;
        split2pack(o[nt][0] * inv0, o[nt][1] * inv0, hp, lp);
        *(unsigned*)(Oh + (size_t)r0g * D + col) = hp;
        *(unsigned*)(Ol + (size_t)r0g * D + col) = lp;
        split2pack(o[nt][2] * inv1, o[nt][3] * inv1, hp, lp);
        *(unsigned*)(Oh + (size_t)r1g * D + col) = hp;
        *(unsigned*)(Ol + (size_t)r1g * D + col) = lp;
    }
}

// ---------------- Logits ----------------
__global__ void logits_kernel(const float* __restrict__ xf,
                              const float* __restrict__ Wout,
                              float* __restrict__ out) {
    __shared__ float xs[D];
    for (int i = threadIdx.x; i < D; i += 256) xs[i] = xf[i];
    __syncthreads();
    int v = blockIdx.x * 256 + threadIdx.x;
    float acc = 0.f;
#pragma unroll 8
    for (int d = 0; d < D; d++) acc += xs[d] * Wout[(size_t)d * NV + v];
    out[v] = acc;
}

// ---------------- Host launch ----------------
extern "C" void kernel_launch(void* const* d_in, const int* in_sizes, int n_in,
                              void* d_out, int out_size) {
    int bi = 1;
    if (n_in >= 2 && in_sizes[1] == 1) bi = 2;
    const int*   tokens  = (const int*)d_in[0];
    const float* tok_emb = (const float*)d_in[bi + 0];
    const float* Wq      = (const float*)d_in[bi + 1];
    const float* Wk      = (const float*)d_in[bi + 2];
    const float* Wv      = (const float*)d_in[bi + 3];
    const float* Wo      = (const float*)d_in[bi + 4];
    const float* W1      = (const float*)d_in[bi + 5];
    const float* W2      = (const float*)d_in[bi + 6];
    const float* W3      = (const float*)d_in[bi + 7];
    const float* anw     = (const float*)d_in[bi + 8];
    const float* fnw     = (const float*)d_in[bi + 9];
    const float* finw    = (const float*)d_in[bi + 10];
    const float* Wout    = (const float*)d_in[bi + 11];
    float* out = (float*)d_out;

    float *h_, *cos_, *sin_, *xf_;
    bf16 *xh_, *xl_, *oh_, *ol_, *gh_, *gl_;
    bf16 *qh_, *ql_, *kh_, *kl_, *vh_, *vl_;
    bf16 *wqkvh_, *wqkvl_, *w13h_, *w13l_, *woh_, *wol_, *w2h_, *w2l_;

    cudaGetSymbolAddress((void**)&h_,  g_h);
    cudaGetSymbolAddress((void**)&cos_, g_cos);
    cudaGetSymbolAddress((void**)&sin_, g_sin);
    cudaGetSymbolAddress((void**)&xf_, g_xf);
    cudaGetSymbolAddress((void**)&xh_, g_xh);
    cudaGetSymbolAddress((void**)&xl_, g_xl);
    cudaGetSymbolAddress((void**)&oh_, g_oh);
    cudaGetSymbolAddress((void**)&ol_, g_ol);
    cudaGetSymbolAddress((void**)&gh_, g_gh);
    cudaGetSymbolAddress((void**)&gl_, g_gl);
    cudaGetSymbolAddress((void**)&qh_, g_qh); cudaGetSymbolAddress((void**)&ql_, g_ql);
    cudaGetSymbolAddress((void**)&kh_, g_kh); cudaGetSymbolAddress((void**)&kl_, g_kl);
    cudaGetSymbolAddress((void**)&vh_, g_vh); cudaGetSymbolAddress((void**)&vl_, g_vl);
    cudaGetSymbolAddress((void**)&wqkvh_, g_wqkvh); cudaGetSymbolAddress((void**)&wqkvl_, g_wqkvl);
    cudaGetSymbolAddress((void**)&w13h_, g_w13h); cudaGetSymbolAddress((void**)&w13l_, g_w13l);
    cudaGetSymbolAddress((void**)&woh_, g_woh); cudaGetSymbolAddress((void**)&wol_, g_wol);
    cudaGetSymbolAddress((void**)&w2h_, g_w2h); cudaGetSymbolAddress((void**)&w2l_, g_w2l);

    static int smem_set = 0;
    if (!smem_set) {
        cudaFuncSetAttribute(gemm_bf16x3_kernel<0>,
                             cudaFuncAttributeMaxDynamicSharedMemorySize, SMEM_BYTES);
        cudaFuncSetAttribute(gemm_bf16x3_kernel<1>,
                             cudaFuncAttributeMaxDynamicSharedMemorySize, SMEM_BYTES);
        cudaFuncSetAttribute(gemm_bf16x3_kernel<2>,
                             cudaFuncAttributeMaxDynamicSharedMemorySize, SMEM_BYTES);
        smem_set = 1;
    }

    // ---- pack + split weights ----
    {
        int nDD = D * D / 2, nDF = D * HFF / 2, nFD = HFF * D / 2;
        dim3 bDD((nDD + 255) / 256, 1, NL);
        dim3 bDF((nDF + 255) / 256, 1, NL);
        dim3 bFD((nFD + 255) / 256, 1, NL);
        pack_split_kernel<<<bDD, 256>>>(Wq, wqkvh_, wqkvl_, D, D, 1, 0,    3 * D, (size_t)D * D, (size_t)3 * D * D);
        pack_split_kernel<<<bDD, 256>>>(Wk, wqkvh_, wqkvl_, D, D, 1, D,    3 * D, (size_t)D * D, (size_t)3 * D * D);
        pack_split_kernel<<<bDD, 256>>>(Wv, wqkvh_, wqkvl_, D, D, 1, 2 * D, 3 * D, (size_t)D * D, (size_t)3 * D * D);
        pack_split_kernel<<<bDF, 256>>>(W1, w13h_, w13l_, D, HFF, 2, 0, 2 * HFF, (size_t)D * HFF, (size_t)2 * D * HFF);
        pack_split_kernel<<<bDF, 256>>>(W3, w13h_, w13l_, D, HFF, 2, 1, 2 * HFF, (size_t)D * HFF, (size_t)2 * D * HFF);
        pack_split_kernel<<<bDD, 256>>>(Wo, woh_, wol_, D, D, 1, 0, D, (size_t)D * D, (size_t)D * D);
        pack_split_kernel<<<bFD, 256>>>(W2, w2h_, w2l_, HFF, D, 1, 0, D, (size_t)HFF * D, (size_t)HFF * D);
    }

    rope_table_kernel<<<(S * 32 + 255) / 256, 256>>>(cos_, sin_);
    embed_kernel<<<(S * D) / 256, 256>>>(tokens, tok_emb, h_);

    const dim3 gQKV(3 * D / GBN, S / GBM);   // (24, 16)
    const dim3 gDD(D / GBN, S / GBM);        // (8, 16)
    const dim3 gW13(2 * HFF / GBN, S / GBM); // (44, 16)

    for (int l = 0; l < NL; l++) {
        size_t offQKV = (size_t)l * 3 * D * D;
        size_t offDD  = (size_t)l * D * D;
        size_t off13  = (size_t)l * 2 * D * HFF;
        size_t offFD  = (size_t)l * HFF * D;

        rmsnorm_split_kernel<<<S, 256>>>(h_, anw + (size_t)l * D, xh_, xl_);

        gemm_bf16x3_kernel<1><<<gQKV, 256, SMEM_BYTES>>>(
            xh_, xl_, wqkvh_ + offQKV, wqkvl_ + offQKV, nullptr, nullptr,
            qh_, ql_, kh_, kl_, vh_, vl_, cos_, sin_, S, 3 * D, D);

        attn_mma_kernel<<<dim3(S / 64, NH), 128>>>(qh_, ql_, kh_, kl_, vh_, vl_, oh_, ol_);

        gemm_bf16x3_kernel<0><<<gDD, 256, SMEM_BYTES>>>(
            oh_, ol_, woh_ + offDD, wol_ + offDD, h_, h_,
            nullptr, nullptr, nullptr, nullptr, nullptr, nullptr, nullptr, nullptr, S, D, D);

        rmsnorm_split_kernel<<<S, 256>>>(h_, fnw + (size_t)l * D, xh_, xl_);

        gemm_bf16x3_kernel<2><<<gW13, 256, SMEM_BYTES>>>(
            xh_, xl_, w13h_ + off13, w13l_ + off13, nullptr, nullptr,
            gh_, gl_, nullptr, nullptr, nullptr, nullptr, nullptr, nullptr, S, 2 * HFF, D);

        gemm_bf16x3_kernel<0><<<gDD, 256, SMEM_BYTES>>>(
            gh_, gl_, w2h_ + offFD, w2l_ + offFD, h_, h_,
            nullptr, nullptr, nullptr, nullptr, nullptr, nullptr, nullptr, nullptr, S, D, HFF);
    }

    rmsnorm_kernel<<<1, 256>>>(h_ + (size_t)(S - 1) * D, finw, xf_);
    logits_kernel<<<NV / 256, 256>>>(xf_, Wout, out);
}

// round 8
// speedup vs baseline: 3.8148x; 1.1916x over previous
#include <cuda_runtime.h>
#include <cuda_bf16.h>
#include <math.h>
#include <stdint.h>

// ---------------- Problem constants ----------------
#define S    2048
#define D    1024
#define NH   16
#define HD   64
#define HFF  2816
#define NV   32000
#define NL   4

typedef __nv_bfloat16 bf16;

// ---------------- Device scratch ----------------
__device__ float g_h[S * D];
__device__ float g_cos[S * 32];
__device__ float g_sin[S * 32];
__device__ float g_xf[D];

__device__ __align__(16) bf16 g_xh[S * D],  g_xl[S * D];
__device__ __align__(16) bf16 g_oh[S * D],  g_ol[S * D];
__device__ __align__(16) bf16 g_gh[S * HFF], g_gl[S * HFF];
__device__ __align__(16) bf16 g_qh[S * D], g_ql[S * D];
__device__ __align__(16) bf16 g_kh[S * D], g_kl[S * D];
__device__ __align__(16) bf16 g_vh[S * D], g_vl[S * D];

__device__ __align__(16) bf16 g_wqkvh[NL * D * 3 * D], g_wqkvl[NL * D * 3 * D];
__device__ __align__(16) bf16 g_w13h[NL * D * 2 * HFF], g_w13l[NL * D * 2 * HFF];
__device__ __align__(16) bf16 g_woh[NL * D * D], g_wol[NL * D * D];
__device__ __align__(16) bf16 g_w2h[NL * HFF * D], g_w2l[NL * HFF * D];

// ---------------- small helpers ----------------
__device__ __forceinline__ void split1(float v, bf16& h, bf16& l) {
    h = __float2bfloat16(v);
    l = __float2bfloat16(v - __bfloat162float(h));
}
__device__ __forceinline__ void split2pack(float x, float y, unsigned& hp, unsigned& lp) {
    bf16 hx = __float2bfloat16(x), hy = __float2bfloat16(y);
    float lx = x - __bfloat162float(hx), ly = y - __bfloat162float(hy);
    bf16 lxb = __float2bfloat16(lx), lyb = __float2bfloat16(ly);
    hp = (unsigned)(*(unsigned short*)&hx) | ((unsigned)(*(unsigned short*)&hy) << 16);
    lp = (unsigned)(*(unsigned short*)&lxb) | ((unsigned)(*(unsigned short*)&lyb) << 16);
}

// ---------------- ONE fused pack+split kernel for all weights ----------------
#define PDD (D * D / 2)
#define PDF (D * HFF / 2)
__global__ void pack_all_kernel(
    const float* __restrict__ Wq, const float* __restrict__ Wk, const float* __restrict__ Wv,
    const float* __restrict__ W1, const float* __restrict__ W3,
    const float* __restrict__ Wo, const float* __restrict__ W2,
    bf16* __restrict__ qkvh, bf16* __restrict__ qkvl,
    bf16* __restrict__ w13h, bf16* __restrict__ w13l,
    bf16* __restrict__ woh, bf16* __restrict__ wol,
    bf16* __restrict__ w2h, bf16* __restrict__ w2l) {
    const int l = blockIdx.z;
    long idx = (long)blockIdx.x * 256 + threadIdx.x;

    if (idx < 3L * PDD) {       // Wq/Wk/Wv -> packed QKV [K, 3D]
        int seg = (int)(idx / PDD);
        int r = (int)(idx % PDD);
        const float* src = (seg == 0 ? Wq : seg == 1 ? Wk : Wv) + (size_t)l * D * D;
        int k = r / (D / 2), n = (r % (D / 2)) * 2;
        float2 v = *(const float2*)(src + (size_t)k * D + n);
        unsigned hp, lp; split2pack(v.x, v.y, hp, lp);
        size_t o = (size_t)l * 3 * D * D + (size_t)k * 3 * D + seg * D + n;
        *(unsigned*)(qkvh + o) = hp;
        *(unsigned*)(qkvl + o) = lp;
        return;
    }
    idx -= 3L * PDD;
    if (idx < 2L * PDF) {       // W1/W3 -> interleaved [K, 2*HFF]
        int seg = (int)(idx / PDF);
        int r = (int)(idx % PDF);
        const float* src = (seg == 0 ? W1 : W3) + (size_t)l * D * HFF;
        int k = r / (HFF / 2), n = (r % (HFF / 2)) * 2;
        float2 v = *(const float2*)(src + (size_t)k * HFF + n);
        bf16 h, lo;
        size_t o = (size_t)l * 2 * D * HFF + (size_t)k * 2 * HFF + seg + 2 * n;
        split1(v.x, h, lo); w13h[o] = h; w13l[o] = lo;
        split1(v.y, h, lo); w13h[o + 2] = h; w13l[o + 2] = lo;
        return;
    }
    idx -= 2L * PDF;
    if (idx < PDD) {            // Wo
        const float* src = Wo + (size_t)l * D * D;
        int k = (int)(idx / (D / 2)), n = (int)(idx % (D / 2)) * 2;
        float2 v = *(const float2*)(src + (size_t)k * D + n);
        unsigned hp, lp; split2pack(v.x, v.y, hp, lp);
        size_t o = (size_t)l * D * D + (size_t)k * D + n;
        *(unsigned*)(woh + o) = hp;
        *(unsigned*)(wol + o) = lp;
        return;
    }
    idx -= PDD;                 // W2: HFF*D/2 pairs
    {
        const float* src = W2 + (size_t)l * HFF * D;
        int k = (int)(idx / (D / 2)), n = (int)(idx % (D / 2)) * 2;
        float2 v = *(const float2*)(src + (size_t)k * D + n);
        unsigned hp, lp; split2pack(v.x, v.y, hp, lp);
        size_t o = (size_t)l * HFF * D + (size_t)k * D + n;
        *(unsigned*)(w2h + o) = hp;
        *(unsigned*)(w2l + o) = lp;
    }
}
#define PACK_TOTAL (4L * PDD + 3L * PDF)   // PFD == PDF numerically (HFF*D/2)

// ---------------- RoPE table ----------------
__global__ void rope_table_kernel(float* ct, float* st) {
    int idx = blockIdx.x * 256 + threadIdx.x;
    if (idx >= S * 32) return;
    int pos = idx >> 5;
    int i = idx & 31;
    float inv = powf(10000.0f, -((float)(2 * i) / (float)HD));
    float ang = (float)pos * inv;
    float s, c;
    sincosf(ang, &s, &c);
    ct[idx] = c;
    st[idx] = s;
}

// ---------------- Embedding gather ----------------
__global__ void embed_kernel(const int* __restrict__ tokens,
                             const float* __restrict__ emb,
                             float* __restrict__ h) {
    int idx = blockIdx.x * 256 + threadIdx.x;
    int s = idx >> 10;
    int d = idx & 1023;
    h[idx] = emb[(size_t)tokens[s] * D + d];
}

// ---------------- RMSNorm -> split bf16 hi/lo ----------------
__global__ void rmsnorm_split_kernel(const float* __restrict__ in,
                                     const float* __restrict__ w,
                                     bf16* __restrict__ oh, bf16* __restrict__ ol) {
    const float* r = in + (size_t)blockIdx.x * D;
    bf16* ph = oh + (size_t)blockIdx.x * D;
    bf16* pl = ol + (size_t)blockIdx.x * D;
    int t = threadIdx.x;
    float v[4];
    float ss = 0.f;
#pragma unroll
    for (int i = 0; i < 4; i++) { v[i] = r[t + i * 256]; ss += v[i] * v[i]; }
#pragma unroll
    for (int off = 16; off; off >>= 1) ss += __shfl_xor_sync(0xffffffffu, ss, off);
    __shared__ float red[8];
    if ((t & 31) == 0) red[t >> 5] = ss;
    __syncthreads();
    if (t < 8) {
        float x = red[t];
#pragma unroll
        for (int off = 4; off; off >>= 1) x += __shfl_xor_sync(0xffu, x, off);
        if (t == 0) red[0] = x;
    }
    __syncthreads();
    float scale = rsqrtf(red[0] * (1.0f / (float)D) + 1e-6f);
#pragma unroll
    for (int i = 0; i < 4; i++) {
        float rv = v[i] * scale * w[t + i * 256];
        bf16 h, l; split1(rv, h, l);
        ph[t + i * 256] = h;
        pl[t + i * 256] = l;
    }
}

// ---------------- plain fp32 RMSNorm (final row) ----------------
__global__ void rmsnorm_kernel(const float* __restrict__ in,
                               const float* __restrict__ w,
                               float* __restrict__ out) {
    const float* r = in;
    int t = threadIdx.x;
    float v[4];
    float ss = 0.f;
#pragma unroll
    for (int i = 0; i < 4; i++) { v[i] = r[t + i * 256]; ss += v[i] * v[i]; }
#pragma unroll
    for (int off = 16; off; off >>= 1) ss += __shfl_xor_sync(0xffffffffu, ss, off);
    __shared__ float red[8];
    if ((t & 31) == 0) red[t >> 5] = ss;
    __syncthreads();
    if (t < 8) {
        float x = red[t];
#pragma unroll
        for (int off = 4; off; off >>= 1) x += __shfl_xor_sync(0xffu, x, off);
        if (t == 0) red[0] = x;
    }
    __syncthreads();
    float scale = rsqrtf(red[0] * (1.0f / (float)D) + 1e-6f);
#pragma unroll
    for (int i = 0; i < 4; i++) out[t + i * 256] = v[i] * scale * w[t + i * 256];
}

// ---------------- MMA helpers ----------------
#define LDSM4(r0, r1, r2, r3, addr)                                          \
    asm volatile("ldmatrix.sync.aligned.m8n8.x4.shared.b16 {%0,%1,%2,%3},[%4];" \
                 : "=r"(r0), "=r"(r1), "=r"(r2), "=r"(r3) : "r"(addr))
#define LDSM4T(r0, r1, r2, r3, addr)                                         \
    asm volatile("ldmatrix.sync.aligned.m8n8.x4.trans.shared.b16 {%0,%1,%2,%3},[%4];" \
                 : "=r"(r0), "=r"(r1), "=r"(r2), "=r"(r3) : "r"(addr))
#define CP_ASYNC16(saddr, gaddr)                                             \
    asm volatile("cp.async.cg.shared.global [%0],[%1],16;" :: "r"(saddr), "l"(gaddr))
#define CP_COMMIT() asm volatile("cp.async.commit_group;" ::: "memory")
#define CP_WAIT1()  asm volatile("cp.async.wait_group 1;" ::: "memory")

__device__ __forceinline__ void mma16816(float* c, const unsigned* a, const unsigned* b) {
    asm volatile(
        "mma.sync.aligned.m16n8k16.row.col.f32.bf16.bf16.f32 "
        "{%0,%1,%2,%3},{%4,%5,%6,%7},{%8,%9},{%0,%1,%2,%3};"
        : "+f"(c[0]), "+f"(c[1]), "+f"(c[2]), "+f"(c[3])
        : "r"(a[0]), "r"(a[1]), "r"(a[2]), "r"(a[3]), "r"(b[0]), "r"(b[1]));
}

// ---------------- bf16x3 GEMM: cp.async 3-stage + register-double-buffered frags ----------------
#define GBM 128
#define GBN 128
#define GBK 32
#define NSTAGE 3
#define A_BUF_BYTES 10240
#define B_BUF_BYTES 8704
#define A_STAGE_BYTES 20480
#define STAGE_BYTES 37888
#define SMEM_BYTES (NSTAGE * STAGE_BYTES)

extern __shared__ char gsmem[];

template <int MODE>
__global__ __launch_bounds__(256) void gemm_bf16x3_kernel(
    const bf16* __restrict__ Ah, const bf16* __restrict__ Al,
    const bf16* __restrict__ Bh, const bf16* __restrict__ Bl,
    const float* __restrict__ RES, float* __restrict__ C,
    bf16* __restrict__ O1h, bf16* __restrict__ O1l,
    bf16* __restrict__ O2h, bf16* __restrict__ O2l,
    bf16* __restrict__ O3h, bf16* __restrict__ O3l,
    const float* __restrict__ ct, const float* __restrict__ st,
    int M, int N, int K) {
    const int tid  = threadIdx.x;
    const int bm   = blockIdx.y * GBM;
    const int bn   = blockIdx.x * GBN;
    const int warp = tid >> 5;
    const int lane = tid & 31;
    const int wm   = (warp >> 2) * 64;
    const int wn   = (warp & 3) * 32;
    const int grp  = lane >> 3;
    const int rin  = lane & 7;

    const uint32_t sBase = (uint32_t)__cvta_generic_to_shared(gsmem);
    const uint32_t laneA = (uint32_t)((((grp & 1) << 3) + rin) * 80 + ((grp >> 1) << 4));
    const uint32_t laneB = (uint32_t)((((grp & 1) << 3) + rin) * 272 + (((grp >> 1) << 3) + wn) * 2);

    float acc[4][4][4];
#pragma unroll
    for (int mi = 0; mi < 4; mi++)
#pragma unroll
        for (int ni = 0; ni < 4; ni++)
#pragma unroll
            for (int j = 0; j < 4; j++) acc[mi][ni][j] = 0.f;

    const int KT = K / GBK;

    auto issue = [&](int kt, int stage) {
        const uint32_t stOff = sBase + stage * STAGE_BYTES;
        const int kOff = kt * GBK;
#pragma unroll
        for (int i = 0; i < 4; i++) {
            int c = tid + 256 * i;
            int buf = c >> 9, rem = c & 511;
            int m = rem >> 2, kq = rem & 3;
            const bf16* g = (buf ? Al : Ah) + (size_t)(bm + m) * K + kOff + kq * 8;
            uint32_t sa = stOff + buf * A_BUF_BYTES + m * 80 + kq * 16;
            CP_ASYNC16(sa, g);
        }
#pragma unroll
        for (int i = 0; i < 4; i++) {
            int c = tid + 256 * i;
            int buf = c >> 9, rem = c & 511;
            int kk = rem >> 4, nq = rem & 15;
            const bf16* g = (buf ? Bl : Bh) + (size_t)(kOff + kk) * N + bn + nq * 8;
            uint32_t sa = stOff + A_STAGE_BYTES + buf * B_BUF_BYTES + kk * 272 + nq * 16;
            CP_ASYNC16(sa, g);
        }
    };

    auto load_frags = [&](unsigned (&a)[2][4][4], unsigned (&b)[2][4][2],
                          uint32_t stOff, int ks) {
#pragma unroll
        for (int buf = 0; buf < 2; buf++) {
            uint32_t aS = stOff + buf * A_BUF_BYTES + laneA + ks * 32;
#pragma unroll
            for (int mt = 0; mt < 4; mt++) {
                uint32_t addr = aS + (wm + mt * 16) * 80;
                LDSM4(a[buf][mt][0], a[buf][mt][1], a[buf][mt][2], a[buf][mt][3], addr);
            }
            uint32_t bS = stOff + A_STAGE_BYTES + buf * B_BUF_BYTES + laneB + ks * 4352;
#pragma unroll
            for (int nj = 0; nj < 2; nj++) {
                uint32_t addr = bS + nj * 32;
                LDSM4T(b[buf][2 * nj][0], b[buf][2 * nj][1],
                       b[buf][2 * nj + 1][0], b[buf][2 * nj + 1][1], addr);
            }
        }
    };

    auto do_mma = [&](unsigned (&a)[2][4][4], unsigned (&b)[2][4][2]) {
#pragma unroll
        for (int mt = 0; mt < 4; mt++)
#pragma unroll
            for (int nt = 0; nt < 4; nt++)
                mma16816(acc[mt][nt], a[0][mt], b[0][nt]);   // hi*hi
#pragma unroll
        for (int mt = 0; mt < 4; mt++)
#pragma unroll
            for (int nt = 0; nt < 4; nt++)
                mma16816(acc[mt][nt], a[0][mt], b[1][nt]);   // hi*lo
#pragma unroll
        for (int mt = 0; mt < 4; mt++)
#pragma unroll
            for (int nt = 0; nt < 4; nt++)
                mma16816(acc[mt][nt], a[1][mt], b[0][nt]);   // lo*hi
    };

    unsigned aX[2][4][4], bX[2][4][2];
    unsigned aY[2][4][4], bY[2][4][2];

    issue(0, 0); CP_COMMIT();
    issue(1, 1); CP_COMMIT();
    CP_WAIT1();                 // stage 0 done
    __syncthreads();
    load_frags(aX, bX, sBase, 0);

    for (int kt = 0; kt < KT; kt++) {
        const uint32_t stOff = sBase + (kt % NSTAGE) * STAGE_BYTES;
        load_frags(aY, bY, stOff, 1);        // prefetch ks=1 (independent of MMAs below)
        do_mma(aX, bX);                      // ks=0 compute
        if (kt + 2 < KT) issue(kt + 2, (kt + 2) % NSTAGE);
        CP_COMMIT();
        CP_WAIT1();                          // stage kt+1 complete
        __syncthreads();                     // make it visible; also guards stage reuse
        if (kt + 1 < KT)
            load_frags(aX, bX, sBase + ((kt + 1) % NSTAGE) * STAGE_BYTES, 0); // prefetch next ktile
        do_mma(aY, bY);                      // ks=1 compute
    }

    // ---- fused epilogue ----
    const int r0 = bm + wm + (lane >> 2);
    const int c0 = bn + wn + (lane & 3) * 2;
#pragma unroll
    for (int mt = 0; mt < 4; mt++)
#pragma unroll
        for (int nt = 0; nt < 4; nt++) {
            const int col = c0 + nt * 8;
#pragma unroll
            for (int rp = 0; rp < 2; rp++) {
                const int row = r0 + mt * 16 + rp * 8;
                float2 v = make_float2(acc[mt][nt][2 * rp], acc[mt][nt][2 * rp + 1]);
                if (MODE == 0) {
                    if (RES) {
                        float2 a0 = *(const float2*)(RES + (size_t)row * N + col);
                        v.x += a0.x; v.y += a0.y;
                    }
                    *(float2*)(C + (size_t)row * N + col) = v;
                } else if (MODE == 1) {
                    const int seg = col >> 10;          // 0:q 1:k 2:v
                    const int d = col & 1023;
                    if (seg < 2) {
                        const int i = (d & 63) >> 1;
                        float c = ct[row * 32 + i];
                        float s = st[row * 32 + i];
                        float a0 = v.x * c - v.y * s;
                        float b0 = v.x * s + v.y * c;
                        v.x = a0; v.y = b0;
                    }
                    unsigned hp, lp;
                    split2pack(v.x, v.y, hp, lp);
                    bf16* oh = (seg == 0) ? O1h : (seg == 1) ? O2h : O3h;
                    bf16* ol = (seg == 0) ? O1l : (seg == 1) ? O2l : O3l;
                    *(unsigned*)(oh + (size_t)row * D + d) = hp;
                    *(unsigned*)(ol + (size_t)row * D + d) = lp;
                } else {   // MODE 2: (g,u) pair -> silu(g)*u
                    const int j = col >> 1;
                    float z = v.x;
                    float sig = 1.0f / (1.0f + __expf(-z));
                    float r = z * sig * v.y;
                    bf16 h, l; split1(r, h, l);
                    O1h[(size_t)row * HFF + j] = h;
                    O1l[(size_t)row * HFF + j] = l;
                }
            }
        }
}

// ---------------- Tensor-core flash attention (bf16 split) ----------------
#define AP 72   // smem row pitch in halfs (144B)

__global__ __launch_bounds__(128) void attn_mma_kernel(
    const bf16* __restrict__ Qh, const bf16* __restrict__ Ql,
    const bf16* __restrict__ Kh, const bf16* __restrict__ Kl,
    const bf16* __restrict__ Vh, const bf16* __restrict__ Vl,
    bf16* __restrict__ Oh, bf16* __restrict__ Ol) {
    __shared__ __align__(16) bf16 sK[2][64 * AP];
    __shared__ __align__(16) bf16 sV[2][64 * AP];

    const int qt   = gridDim.x - 1 - blockIdx.x;   // longest-first
    const int head = blockIdx.y;
    const int tid  = threadIdx.x;
    const int warp = tid >> 5;
    const int lane = tid & 31;
    const int grp  = lane >> 3;
    const int rin  = lane & 7;
    const int wq   = warp * 16;

    {
        const bf16* qsrc[2] = {Qh, Ql};
#pragma unroll
        for (int c = tid; c < 1024; c += 128) {
            int buf = c >> 9, rem = c & 511;
            int row = rem >> 3, col8 = rem & 7;
            *(uint4*)&sK[buf][row * AP + col8 * 8] =
                *(const uint4*)(qsrc[buf] + (size_t)(qt * 64 + row) * D + head * HD + col8 * 8);
        }
    }
    __syncthreads();

    unsigned aQ[2][4][4];
    {
        uint32_t b0 = (uint32_t)__cvta_generic_to_shared(&sK[0][0]);
        uint32_t b1 = (uint32_t)__cvta_generic_to_shared(&sK[1][0]);
        uint32_t laneOff = (uint32_t)(((wq + ((grp & 1) << 3) + rin) * AP + ((grp >> 1) << 3)) << 1);
#pragma unroll
        for (int kc = 0; kc < 4; kc++) {
            LDSM4(aQ[0][kc][0], aQ[0][kc][1], aQ[0][kc][2], aQ[0][kc][3], b0 + laneOff + kc * 32);
            LDSM4(aQ[1][kc][0], aQ[1][kc][1], aQ[1][kc][2], aQ[1][kc][3], b1 + laneOff + kc * 32);
        }
    }

    float o[8][4];
#pragma unroll
    for (int nt = 0; nt < 8; nt++)
#pragma unroll
        for (int j = 0; j < 4; j++) o[nt][j] = 0.f;
    float m0 = -1e30f, m1 = -1e30f, l0 = 0.f, l1 = 0.f;
    const float scale = 0.125f;

    const uint32_t sK0 = (uint32_t)__cvta_generic_to_shared(&sK[0][0]);
    const uint32_t sK1 = (uint32_t)__cvta_generic_to_shared(&sK[1][0]);
    const uint32_t sV0 = (uint32_t)__cvta_generic_to_shared(&sV[0][0]);
    const uint32_t sV1 = (uint32_t)__cvta_generic_to_shared(&sV[1][0]);

    const int r0g = qt * 64 + wq + (lane >> 2);
    const int r1g = r0g + 8;

    for (int kt = 0; kt <= qt; kt++) {
        __syncthreads();
        {
            const bf16* src[4] = {Kh, Kl, Vh, Vl};
            bf16* dst[4] = {sK[0], sK[1], sV[0], sV[1]};
#pragma unroll
            for (int c = tid; c < 2048; c += 128) {
                int which = c >> 9, rem = c & 511;
                int row = rem >> 3, col8 = rem & 7;
                *(uint4*)&dst[which][row * AP + col8 * 8] =
                    *(const uint4*)(src[which] + (size_t)(kt * 64 + row) * D + head * HD + col8 * 8);
            }
        }
        __syncthreads();

        float s[8][4];
#pragma unroll
        for (int nt = 0; nt < 8; nt++)
#pragma unroll
            for (int j = 0; j < 4; j++) s[nt][j] = 0.f;

#pragma unroll
        for (int kc = 0; kc < 4; kc++) {
            unsigned bh[8][2], bl[8][2];
#pragma unroll
            for (int np = 0; np < 4; np++) {
                uint32_t off = (uint32_t)(((np * 16 + ((grp >> 1) << 3) + rin) * AP
                                           + kc * 16 + ((grp & 1) << 3)) << 1);
                LDSM4(bh[2 * np][0], bh[2 * np][1], bh[2 * np + 1][0], bh[2 * np + 1][1], sK0 + off);
                LDSM4(bl[2 * np][0], bl[2 * np][1], bl[2 * np + 1][0], bl[2 * np + 1][1], sK1 + off);
            }
#pragma unroll
            for (int nt = 0; nt < 8; nt++) mma16816(s[nt], aQ[0][kc], bh[nt]);
#pragma unroll
            for (int nt = 0; nt < 8; nt++) mma16816(s[nt], aQ[0][kc], bl[nt]);
#pragma unroll
            for (int nt = 0; nt < 8; nt++) mma16816(s[nt], aQ[1][kc], bh[nt]);
        }

        const bool diag = (kt == qt);
#pragma unroll
        for (int nt = 0; nt < 8; nt++) {
            int c0g = kt * 64 + nt * 8 + (lane & 3) * 2;
            s[nt][0] *= scale; s[nt][1] *= scale;
            s[nt][2] *= scale; s[nt][3] *= scale;
            if (diag) {
                if (c0g     > r0g) s[nt][0] = -1e30f;
                if (c0g + 1 > r0g) s[nt][1] = -1e30f;
                if (c0g     > r1g) s[nt][2] = -1e30f;
                if (c0g + 1 > r1g) s[nt][3] = -1e30f;
            }
        }

        float mx0 = -1e30f, mx1 = -1e30f;
#pragma unroll
        for (int nt = 0; nt < 8; nt++) {
            mx0 = fmaxf(mx0, fmaxf(s[nt][0], s[nt][1]));
            mx1 = fmaxf(mx1, fmaxf(s[nt][2], s[nt][3]));
        }
        mx0 = fmaxf(mx0, __shfl_xor_sync(0xffffffffu, mx0, 1));
        mx0 = fmaxf(mx0, __shfl_xor_sync(0xffffffffu, mx0, 2));
        mx1 = fmaxf(mx1, __shfl_xor_sync(0xffffffffu, mx1, 1));
        mx1 = fmaxf(mx1, __shfl_xor_sync(0xffffffffu, mx1, 2));
        float mn0 = fmaxf(m0, mx0), mn1 = fmaxf(m1, mx1);
        float cr0 = __expf(m0 - mn0), cr1 = __expf(m1 - mn1);
        m0 = mn0; m1 = mn1;
        float rs0 = 0.f, rs1 = 0.f;
#pragma unroll
        for (int nt = 0; nt < 8; nt++) {
            s[nt][0] = __expf(s[nt][0] - mn0); rs0 += s[nt][0];
            s[nt][1] = __expf(s[nt][1] - mn0); rs0 += s[nt][1];
            s[nt][2] = __expf(s[nt][2] - mn1); rs1 += s[nt][2];
            s[nt][3] = __expf(s[nt][3] - mn1); rs1 += s[nt][3];
        }
        l0 = l0 * cr0 + rs0;
        l1 = l1 * cr1 + rs1;
#pragma unroll
        for (int nt = 0; nt < 8; nt++) {
            o[nt][0] *= cr0; o[nt][1] *= cr0;
            o[nt][2] *= cr1; o[nt][3] *= cr1;
        }

#pragma unroll
        for (int kc = 0; kc < 4; kc++) {
            int t0 = 2 * kc, t1 = 2 * kc + 1;
            unsigned ah[4], al[4];
            split2pack(s[t0][0], s[t0][1], ah[0], al[0]);
            split2pack(s[t0][2], s[t0][3], ah[1], al[1]);
            split2pack(s[t1][0], s[t1][1], ah[2], al[2]);
            split2pack(s[t1][2], s[t1][3], ah[3], al[3]);

            unsigned bvh[8][2], bvl[8][2];
#pragma unroll
            for (int np = 0; np < 4; np++) {
                uint32_t off = (uint32_t)(((kc * 16 + ((grp & 1) << 3) + rin) * AP
                                           + np * 16 + ((grp >> 1) << 3)) << 1);
                LDSM4T(bvh[2 * np][0], bvh[2 * np][1], bvh[2 * np + 1][0], bvh[2 * np + 1][1], sV0 + off);
                LDSM4T(bvl[2 * np][0], bvl[2 * np][1], bvl[2 * np + 1][0], bvl[2 * np + 1][1], sV1 + off);
            }
#pragma unroll
            for (int nt = 0; nt < 8; nt++) mma16816(o[nt], ah, bvh[nt]);
#pragma unroll
            for (int nt = 0; nt < 8; nt++) mma16816(o[nt], ah, bvl[nt]);
#pragma unroll
            for (int nt = 0; nt < 8; nt++) mma16816(o[nt], al, bvh[nt]);
        }
    }

    l0 += __shfl_xor_sync(0xffffffffu, l0, 1);
    l0 += __shfl_xor_sync(0xffffffffu, l0, 2);
    l1 += __shfl_xor_sync(0xffffffffu, l1, 1);
    l1 += __shfl_xor_sync(0xffffffffu, l1, 2);
    float inv0 = 1.f / l0, inv1 = 1.f / l1;
#pragma unroll
    for (int nt = 0; nt < 8; nt++) {
        int col = head * HD + nt * 8 + (lane & 3) * 2;
        unsigned hp, lp;
        split2pack(o[nt][0] * inv0, o[nt][1] * inv0, hp, lp);
        *(unsigned*)(Oh + (size_t)r0g * D + col) = hp;
        *(unsigned*)(Ol + (size_t)r0g * D + col) = lp;
        split2pack(o[nt][2] * inv1, o[nt][3] * inv1, hp, lp);
        *(unsigned*)(Oh + (size_t)r1g * D + col) = hp;
        *(unsigned*)(Ol + (size_t)r1g * D + col) = lp;
    }
}

// ---------------- Logits ----------------
__global__ void logits_kernel(const float* __restrict__ xf,
                              const float* __restrict__ Wout,
                              float* __restrict__ out) {
    __shared__ float xs[D];
    for (int i = threadIdx.x; i < D; i += 256) xs[i] = xf[i];
    __syncthreads();
    int v = blockIdx.x * 256 + threadIdx.x;
    float acc = 0.f;
#pragma unroll 8
    for (int d = 0; d < D; d++) acc += xs[d] * Wout[(size_t)d * NV + v];
    out[v] = acc;
}

// ---------------- Host launch ----------------
extern "C" void kernel_launch(void* const* d_in, const int* in_sizes, int n_in,
                              void* d_out, int out_size) {
    int bi = 1;
    if (n_in >= 2 && in_sizes[1] == 1) bi = 2;
    const int*   tokens  = (const int*)d_in[0];
    const float* tok_emb = (const float*)d_in[bi + 0];
    const float* Wq      = (const float*)d_in[bi + 1];
    const float* Wk      = (const float*)d_in[bi + 2];
    const float* Wv      = (const float*)d_in[bi + 3];
    const float* Wo      = (const float*)d_in[bi + 4];
    const float* W1      = (const float*)d_in[bi + 5];
    const float* W2      = (const float*)d_in[bi + 6];
    const float* W3      = (const float*)d_in[bi + 7];
    const float* anw     = (const float*)d_in[bi + 8];
    const float* fnw     = (const float*)d_in[bi + 9];
    const float* finw    = (const float*)d_in[bi + 10];
    const float* Wout    = (const float*)d_in[bi + 11];
    float* out = (float*)d_out;

    float *h_, *cos_, *sin_, *xf_;
    bf16 *xh_, *xl_, *oh_, *ol_, *gh_, *gl_;
    bf16 *qh_, *ql_, *kh_, *kl_, *vh_, *vl_;
    bf16 *wqkvh_, *wqkvl_, *w13h_, *w13l_, *woh_, *wol_, *w2h_, *w2l_;

    cudaGetSymbolAddress((void**)&h_,  g_h);
    cudaGetSymbolAddress((void**)&cos_, g_cos);
    cudaGetSymbolAddress((void**)&sin_, g_sin);
    cudaGetSymbolAddress((void**)&xf_, g_xf);
    cudaGetSymbolAddress((void**)&xh_, g_xh);
    cudaGetSymbolAddress((void**)&xl_, g_xl);
    cudaGetSymbolAddress((void**)&oh_, g_oh);
    cudaGetSymbolAddress((void**)&ol_, g_ol);
    cudaGetSymbolAddress((void**)&gh_, g_gh);
    cudaGetSymbolAddress((void**)&gl_, g_gl);
    cudaGetSymbolAddress((void**)&qh_, g_qh); cudaGetSymbolAddress((void**)&ql_, g_ql);
    cudaGetSymbolAddress((void**)&kh_, g_kh); cudaGetSymbolAddress((void**)&kl_, g_kl);
    cudaGetSymbolAddress((void**)&vh_, g_vh); cudaGetSymbolAddress((void**)&vl_, g_vl);
    cudaGetSymbolAddress((void**)&wqkvh_, g_wqkvh); cudaGetSymbolAddress((void**)&wqkvl_, g_wqkvl);
    cudaGetSymbolAddress((void**)&w13h_, g_w13h); cudaGetSymbolAddress((void**)&w13l_, g_w13l);
    cudaGetSymbolAddress((void**)&woh_, g_woh); cudaGetSymbolAddress((void**)&wol_, g_wol);
    cudaGetSymbolAddress((void**)&w2h_, g_w2h); cudaGetSymbolAddress((void**)&w2l_, g_w2l);

    static int smem_set = 0;
    if (!smem_set) {
        cudaFuncSetAttribute(gemm_bf16x3_kernel<0>,
                             cudaFuncAttributeMaxDynamicSharedMemorySize, SMEM_BYTES);
        cudaFuncSetAttribute(gemm_bf16x3_kernel<1>,
                             cudaFuncAttributeMaxDynamicSharedMemorySize, SMEM_BYTES);
        cudaFuncSetAttribute(gemm_bf16x3_kernel<2>,
                             cudaFuncAttributeMaxDynamicSharedMemorySize, SMEM_BYTES);
        smem_set = 1;
    }

    // ---- ONE pack+split launch for all weights ----
    {
        dim3 grid((unsigned)(PACK_TOTAL / 256), 1, NL);
        pack_all_kernel<<<grid, 256>>>(Wq, Wk, Wv, W1, W3, Wo, W2,
                                       wqkvh_, wqkvl_, w13h_, w13l_,
                                       woh_, wol_, w2h_, w2l_);
    }

    rope_table_kernel<<<(S * 32 + 255) / 256, 256>>>(cos_, sin_);
    embed_kernel<<<(S * D) / 256, 256>>>(tokens, tok_emb, h_);

    const dim3 gQKV(3 * D / GBN, S / GBM);   // (24, 16)
    const dim3 gDD(D / GBN, S / GBM);        // (8, 16)
    const dim3 gW13(2 * HFF / GBN, S / GBM); // (44, 16)

    for (int l = 0; l < NL; l++) {
        size_t offQKV = (size_t)l * 3 * D * D;
        size_t offDD  = (size_t)l * D * D;
        size_t off13  = (size_t)l * 2 * D * HFF;
        size_t offFD  = (size_t)l * HFF * D;

        rmsnorm_split_kernel<<<S, 256>>>(h_, anw + (size_t)l * D, xh_, xl_);

        gemm_bf16x3_kernel<1><<<gQKV, 256, SMEM_BYTES>>>(
            xh_, xl_, wqkvh_ + offQKV, wqkvl_ + offQKV, nullptr, nullptr,
            qh_, ql_, kh_, kl_, vh_, vl_, cos_, sin_, S, 3 * D, D);

        attn_mma_kernel<<<dim3(S / 64, NH), 128>>>(qh_, ql_, kh_, kl_, vh_, vl_, oh_, ol_);

        gemm_bf16x3_kernel<0><<<gDD, 256, SMEM_BYTES>>>(
            oh_, ol_, woh_ + offDD, wol_ + offDD, h_, h_,
            nullptr, nullptr, nullptr, nullptr, nullptr, nullptr, nullptr, nullptr, S, D, D);

        rmsnorm_split_kernel<<<S, 256>>>(h_, fnw + (size_t)l * D, xh_, xl_);

        gemm_bf16x3_kernel<2><<<gW13, 256, SMEM_BYTES>>>(
            xh_, xl_, w13h_ + off13, w13l_ + off13, nullptr, nullptr,
            gh_, gl_, nullptr, nullptr, nullptr, nullptr, nullptr, nullptr, S, 2 * HFF, D);

        gemm_bf16x3_kernel<0><<<gDD, 256, SMEM_BYTES>>>(
            gh_, gl_, w2h_ + offFD, w2l_ + offFD, h_, h_,
            nullptr, nullptr, nullptr, nullptr, nullptr, nullptr, nullptr, nullptr, S, D, HFF);
    }

    rmsnorm_kernel<<<1, 256>>>(h_ + (size_t)(S - 1) * D, finw, xf_);
    logits_kernel<<<NV / 256, 256>>>(xf_, Wout, out);
}